// round 1
// baseline (speedup 1.0000x reference)
#include <cuda_runtime.h>
#include <math.h>

// ---------------------------------------------------------------------------
// Problem constants
// ---------------------------------------------------------------------------
#define DD     512
#define SS     1024
#define NBB    16
#define QQ     64
#define NDOC   8

// ---------------------------------------------------------------------------
// Scratch (device globals; no allocation anywhere)
// ---------------------------------------------------------------------------
__device__ float g_X   [16384 * 512];
__device__ float g_Qb  [16384 * 512];
__device__ float g_Kb  [16384 * 512];
__device__ float g_Vb  [16384 * 512];
__device__ float g_S   [16 * 1024 * 1024];
__device__ float g_Kdoc[8192 * 512];
__device__ float g_Vdoc[8192 * 512];
__device__ float g_A1S [8 * 64 * 512];
__device__ float g_SELA[16 * 64 * 512];
__device__ float g_K2  [16384 * 512];
__device__ float g_A2SC[16384 * 64];
__device__ float g_A2  [16384 * 512];
__device__ float g_sin [1024 * 256];
__device__ float g_cos [1024 * 256];

// ---------------------------------------------------------------------------
// Generic tiled fp32 GEMM:
//   C[M,N] = alpha * A[M,K] @ op(B) + bias[N],  op(B)=B[K,N] or B[N,K]^T
//   batch via blockIdx.z with element strides sA/sB/sC. epi: 0=none, 1=gelu.
//   Requires M%64==0, N%64==0, K%16==0 (holds for every call here).
// ---------------------------------------------------------------------------
#define BM 64
#define BN 64
#define BK 16

__global__ void gemm_kernel(const float* __restrict__ A,
                            const float* __restrict__ Bm,
                            const float* __restrict__ bias,
                            float* __restrict__ C,
                            int M, int N, int K,
                            long long sA, long long sB, long long sC,
                            float alpha, int transB, int epi)
{
    const int bz = blockIdx.z;
    A  += (size_t)bz * sA;
    Bm += (size_t)bz * sB;
    C  += (size_t)bz * sC;

    const int m0 = blockIdx.y * BM;
    const int n0 = blockIdx.x * BN;

    __shared__ float As[BK][BM + 4];
    __shared__ float Bs[BK][BN + 4];

    const int t  = threadIdx.x;          // 0..255
    const int tx = t & 15;
    const int ty = t >> 4;

    float acc[4][4] = {};

    const int arow = t >> 2;             // 0..63
    const int akc  = (t & 3) * 4;        // 0,4,8,12
    const int kb   = t >> 4;             // 0..15
    const int nb   = (t & 15) * 4;       // 0..60

    for (int k0 = 0; k0 < K; k0 += BK) {
        // A tile (row-major [M,K]) -> As[k][m]
        float4 av = *(const float4*)&A[(size_t)(m0 + arow) * K + k0 + akc];
        As[akc + 0][arow] = av.x;
        As[akc + 1][arow] = av.y;
        As[akc + 2][arow] = av.z;
        As[akc + 3][arow] = av.w;

        if (!transB) {
            // B row-major [K,N] -> Bs[k][n]
            float4 bv = *(const float4*)&Bm[(size_t)(k0 + kb) * N + n0 + nb];
            *(float4*)&Bs[kb][nb] = bv;
        } else {
            // B row-major [N,K]; Bs[k][n] = B[n0+n][k0+k]
            float4 bv = *(const float4*)&Bm[(size_t)(n0 + arow) * K + k0 + akc];
            Bs[akc + 0][arow] = bv.x;
            Bs[akc + 1][arow] = bv.y;
            Bs[akc + 2][arow] = bv.z;
            Bs[akc + 3][arow] = bv.w;
        }
        __syncthreads();

#pragma unroll
        for (int k = 0; k < BK; k++) {
            float4 a = *(const float4*)&As[k][ty * 4];
            float4 b = *(const float4*)&Bs[k][tx * 4];
            acc[0][0] += a.x * b.x; acc[0][1] += a.x * b.y;
            acc[0][2] += a.x * b.z; acc[0][3] += a.x * b.w;
            acc[1][0] += a.y * b.x; acc[1][1] += a.y * b.y;
            acc[1][2] += a.y * b.z; acc[1][3] += a.y * b.w;
            acc[2][0] += a.z * b.x; acc[2][1] += a.z * b.y;
            acc[2][2] += a.z * b.z; acc[2][3] += a.z * b.w;
            acc[3][0] += a.w * b.x; acc[3][1] += a.w * b.y;
            acc[3][2] += a.w * b.z; acc[3][3] += a.w * b.w;
        }
        __syncthreads();
    }

    const float GC = 0.7978845608028654f;
#pragma unroll
    for (int i = 0; i < 4; i++) {
        const int row = m0 + ty * 4 + i;
        float v[4];
#pragma unroll
        for (int j = 0; j < 4; j++) {
            float x = acc[i][j] * alpha;
            if (bias) x += bias[n0 + tx * 4 + j];
            if (epi == 1) {
                x = 0.5f * x * (1.0f + tanhf(GC * (x + 0.044715f * x * x * x)));
            }
            v[j] = x;
        }
        float4 o = make_float4(v[0], v[1], v[2], v[3]);
        *(float4*)&C[(size_t)row * N + n0 + tx * 4] = o;
    }
}

static void gemm_launch(const float* A, const float* B, const float* bias, float* C,
                        int M, int N, int K, int batch,
                        long long sA, long long sB, long long sC,
                        float alpha, int transB, int epi)
{
    dim3 grid(N / BN, M / BM, batch);
    gemm_kernel<<<grid, 256>>>(A, B, bias, C, M, N, K, sA, sB, sC, alpha, transB, epi);
}

// ---------------------------------------------------------------------------
// RoPE: accurate sin/cos table (double range-safe), then in-place apply
// ---------------------------------------------------------------------------
__global__ void rope_table_kernel()
{
    int s = blockIdx.x;          // 0..1023
    int i = threadIdx.x;         // 0..255
    // match jax f32 rounding of the angle: inv in f32, ang = s*inv in f32
    float invf = 1.0f / powf(10000.0f, (float)i / 256.0f);
    float angf = (float)s * invf;
    double ang = (double)angf;
    g_sin[s * 256 + i] = (float)sin(ang);
    g_cos[s * 256 + i] = (float)cos(ang);
}

__global__ void rope_kernel(float* __restrict__ X)
{
    int row = blockIdx.x;
    int i   = threadIdx.x;       // 0..255
    int s   = row & (SS - 1);
    float sn = g_sin[s * 256 + i];
    float cs = g_cos[s * 256 + i];
    float* xr = X + (size_t)row * DD;
    float x1 = xr[2 * i];
    float x2 = xr[2 * i + 1];
    xr[2 * i]     = x1 * cs - x2 * sn;
    xr[2 * i + 1] = x1 * sn + x2 * cs;
}

// ---------------------------------------------------------------------------
// Softmax over rows (in place), optional per-column positional bias.
// mode: 0 = none, 1 = log(p), 2 = log(p) - log1p(-p)
// pos indexed as pos[(row / rows_per_batch) * cols_pos + c] with cols_pos==cols
// ---------------------------------------------------------------------------
__global__ void softmax_kernel(float* __restrict__ S, const float* __restrict__ pos,
                               int cols, int rows_per_batch, int mode)
{
    int row = blockIdx.x;
    float* sr = S + (size_t)row * cols;
    const float* pb = (mode != 0) ? pos + (size_t)(row / rows_per_batch) * cols : nullptr;
    int t = threadIdx.x;
    __shared__ float red[256];

    float mx = -1e30f;
    for (int c = t; c < cols; c += 256) {
        float v = sr[c];
        if (mode == 1)       v += logf(pb[c]);
        else if (mode == 2) { float p = pb[c]; v += logf(p) - log1pf(-p); }
        sr[c] = v;
        mx = fmaxf(mx, v);
    }
    red[t] = mx; __syncthreads();
    for (int s = 128; s > 0; s >>= 1) { if (t < s) red[t] = fmaxf(red[t], red[t + s]); __syncthreads(); }
    mx = red[0]; __syncthreads();

    float sum = 0.0f;
    for (int c = t; c < cols; c += 256) {
        float e = expf(sr[c] - mx);
        sr[c] = e;
        sum += e;
    }
    red[t] = sum; __syncthreads();
    for (int s = 128; s > 0; s >>= 1) { if (t < s) red[t] += red[t + s]; __syncthreads(); }
    float inv = 1.0f / red[0];

    for (int c = t; c < cols; c += 256) sr[c] *= inv;
}

// ---------------------------------------------------------------------------
// X = LayerNorm(X + R) * g + b   (row length 512, block of 256 threads)
// ---------------------------------------------------------------------------
__global__ void ln_kernel(float* __restrict__ X, const float* __restrict__ R,
                          const float* __restrict__ g, const float* __restrict__ b)
{
    int row = blockIdx.x;
    int t   = threadIdx.x;
    float* xr = X + (size_t)row * DD;
    const float* rr = R + (size_t)row * DD;

    float v0 = xr[t] + rr[t];
    float v1 = xr[t + 256] + rr[t + 256];

    __shared__ float red[256];
    red[t] = v0 + v1; __syncthreads();
    for (int s = 128; s > 0; s >>= 1) { if (t < s) red[t] += red[t + s]; __syncthreads(); }
    float m = red[0] * (1.0f / 512.0f);
    __syncthreads();

    float d0 = v0 - m, d1 = v1 - m;
    red[t] = d0 * d0 + d1 * d1; __syncthreads();
    for (int s = 128; s > 0; s >>= 1) { if (t < s) red[t] += red[t + s]; __syncthreads(); }
    float var = red[0] * (1.0f / 512.0f);
    float inv = rsqrtf(var + 1e-5f);

    xr[t]       = d0 * inv * g[t]       + b[t];
    xr[t + 256] = d1 * inv * g[t + 256] + b[t + 256];
}

// ---------------------------------------------------------------------------
// V = raw * sigmoid(F . W_ig + b_ig)   (per-row dot of length 512)
// ---------------------------------------------------------------------------
__global__ void vgate_kernel(const float* __restrict__ F, const float* __restrict__ raw,
                             const float* __restrict__ Wig, const float* __restrict__ big,
                             float* __restrict__ V)
{
    int row = blockIdx.x;
    int t   = threadIdx.x;
    const float* fr = F + (size_t)row * DD;
    __shared__ float red[256];
    float s = fr[t] * Wig[t] + fr[t + 256] * Wig[t + 256];
    red[t] = s; __syncthreads();
    for (int k = 128; k > 0; k >>= 1) { if (t < k) red[t] += red[t + k]; __syncthreads(); }
    float gte = 1.0f / (1.0f + expf(-(red[0] + big[0])));
    const float* rr = raw + (size_t)row * DD;
    float* vr = V + (size_t)row * DD;
    vr[t]       = rr[t]       * gte;
    vr[t + 256] = rr[t + 256] * gte;
}

// ---------------------------------------------------------------------------
// SELA[b] = A1S[lookup_ids[b]]
// ---------------------------------------------------------------------------
__global__ void gather_kernel(float* __restrict__ dst, const float* __restrict__ src,
                              const int* __restrict__ ids)
{
    int idx = blockIdx.x * 256 + threadIdx.x;   // over 16*64*512
    int b   = idx >> 15;                        // /32768
    int rem = idx & 32767;
    dst[idx] = src[(size_t)ids[b] * 32768 + rem];
}

// ---------------------------------------------------------------------------
// Final: gate = sigmoid(FU.Wu1 + bu1 + A2.Wu2 + bu2 + b1 - 4)
//        out  = pd*(1-gate) + A2*gate ; also emit gate
// ---------------------------------------------------------------------------
__global__ void out_kernel(const float* __restrict__ FU, const float* __restrict__ A2,
                           const float* __restrict__ PD,
                           const float* __restrict__ Wu1, const float* __restrict__ bu1,
                           const float* __restrict__ Wu2, const float* __restrict__ bu2,
                           const float* __restrict__ b1,
                           float* __restrict__ out, float* __restrict__ gate)
{
    int row = blockIdx.x;
    int t   = threadIdx.x;
    const float* fu = FU + (size_t)row * DD;
    const float* a2 = A2 + (size_t)row * DD;
    const float* pd = PD + (size_t)row * DD;

    __shared__ float red[256];
    float s = fu[t] * Wu1[t] + fu[t + 256] * Wu1[t + 256]
            + a2[t] * Wu2[t] + a2[t + 256] * Wu2[t + 256];
    red[t] = s; __syncthreads();
    for (int k = 128; k > 0; k >>= 1) { if (t < k) red[t] += red[t + k]; __syncthreads(); }
    float z = red[0] + bu1[0] + bu2[0] + b1[0] - 4.0f;
    float g = 1.0f / (1.0f + expf(-z));

    float* orow = out + (size_t)row * DD;
    orow[t]       = pd[t]       * (1.0f - g) + a2[t]       * g;
    orow[t + 256] = pd[t + 256] * (1.0f - g) + a2[t + 256] * g;
    if (t == 0) gate[row] = g;
}

// ---------------------------------------------------------------------------
// Host orchestration
// ---------------------------------------------------------------------------
static void run_encoder(float* X, int nb, const float* pos, int posmode,
                        const float* Wqkv, const float* bqkv,
                        const float* Wo, const float* bo,
                        const float* ln, const float* Wff, const float* bff,
                        float* bQ, float* bK, float* bV, float* bS)
{
    const int rows = nb * SS;
    const float sc = 1.0f / sqrtf((float)DD);
    for (int l = 0; l < 2; l++) {
        const float* Wl = Wqkv + (size_t)l * 3 * DD * DD;
        const float* bl = bqkv + (size_t)l * 3 * DD;
        gemm_launch(X, Wl + 0 * 262144, bl + 0,    bQ, rows, DD, DD, 1, 0, 0, 0, 1.0f, 0, 0);
        gemm_launch(X, Wl + 1 * 262144, bl + 512,  bK, rows, DD, DD, 1, 0, 0, 0, 1.0f, 0, 0);
        gemm_launch(X, Wl + 2 * 262144, bl + 1024, bV, rows, DD, DD, 1, 0, 0, 0, 1.0f, 0, 0);
        rope_kernel<<<rows, 256>>>(bQ);
        rope_kernel<<<rows, 256>>>(bK);
        // scores[b] = Q[b] @ K[b]^T * sc
        gemm_launch(bQ, bK, nullptr, bS, SS, SS, DD, nb, 524288, 524288, 1048576, sc, 1, 0);
        softmax_kernel<<<rows, 256>>>(bS, pos, SS, SS, posmode);
        // T = A @ V  -> bQ
        gemm_launch(bS, bV, nullptr, bQ, SS, DD, SS, nb, 1048576, 524288, 524288, 1.0f, 0, 0);
        // O = T @ Wo + bo -> bK
        gemm_launch(bQ, Wo + (size_t)l * 262144, bo + l * 512, bK, rows, DD, DD, 1, 0, 0, 0, 1.0f, 0, 0);
        ln_kernel<<<rows, 256>>>(X, bK, ln + l * 2048, ln + l * 2048 + 512);
        // H = gelu(X @ Wff0 + bff0) -> bQ
        gemm_launch(X, Wff + (size_t)l * 524288, bff + l * 1024, bQ, rows, DD, DD, 1, 0, 0, 0, 1.0f, 0, 1);
        // F = H @ Wff1 + bff1 -> bK
        gemm_launch(bQ, Wff + (size_t)l * 524288 + 262144, bff + l * 1024 + 512, bK,
                    rows, DD, DD, 1, 0, 0, 0, 1.0f, 0, 0);
        ln_kernel<<<rows, 256>>>(X, bK, ln + l * 2048 + 1024, ln + l * 2048 + 1536);
    }
}

extern "C" void kernel_launch(void* const* d_in, const int* in_sizes, int n_in,
                              void* d_out, int out_size)
{
    const float* raw_emb   = (const float*)d_in[0];
    const float* pos_w     = (const float*)d_in[1];
    const float* post_dec  = (const float*)d_in[2];
    const float* pos_r     = (const float*)d_in[3];
    const float* questions = (const float*)d_in[4];
    const float* W_k       = (const float*)d_in[5];
    const float* W_ig      = (const float*)d_in[6];
    const float* b_ig      = (const float*)d_in[7];
    const float* W_u1      = (const float*)d_in[8];
    const float* b_u1      = (const float*)d_in[9];
    const float* W_u2      = (const float*)d_in[10];
    const float* b_u2      = (const float*)d_in[11];
    const float* b1        = (const float*)d_in[12];
    const float* W_ok      = (const float*)d_in[13];
    const float* b_ok      = (const float*)d_in[14];
    const float* encw_Wqkv = (const float*)d_in[15];
    const float* encw_bqkv = (const float*)d_in[16];
    const float* encw_Wo   = (const float*)d_in[17];
    const float* encw_bo   = (const float*)d_in[18];
    const float* encw_ln   = (const float*)d_in[19];
    const float* encw_Wff  = (const float*)d_in[20];
    const float* encw_bff  = (const float*)d_in[21];
    const float* encr_Wqkv = (const float*)d_in[22];
    const float* encr_bqkv = (const float*)d_in[23];
    const float* encr_Wo   = (const float*)d_in[24];
    const float* encr_bo   = (const float*)d_in[25];
    const float* encr_ln   = (const float*)d_in[26];
    const float* encr_Wff  = (const float*)d_in[27];
    const float* encr_bff  = (const float*)d_in[28];
    const int*   lookup    = (const int*)d_in[29];

    float* out  = (float*)d_out;
    float* gate = out + (size_t)NBB * SS * DD;   // 8,388,608

    float *pX, *pQ, *pK, *pV, *pS, *pKd, *pVd, *pA1, *pSel, *pK2, *pA2s, *pA2;
    cudaGetSymbolAddress((void**)&pX,   g_X);
    cudaGetSymbolAddress((void**)&pQ,   g_Qb);
    cudaGetSymbolAddress((void**)&pK,   g_Kb);
    cudaGetSymbolAddress((void**)&pV,   g_Vb);
    cudaGetSymbolAddress((void**)&pS,   g_S);
    cudaGetSymbolAddress((void**)&pKd,  g_Kdoc);
    cudaGetSymbolAddress((void**)&pVd,  g_Vdoc);
    cudaGetSymbolAddress((void**)&pA1,  g_A1S);
    cudaGetSymbolAddress((void**)&pSel, g_SELA);
    cudaGetSymbolAddress((void**)&pK2,  g_K2);
    cudaGetSymbolAddress((void**)&pA2s, g_A2SC);
    cudaGetSymbolAddress((void**)&pA2,  g_A2);

    const float scD = 1.0f / sqrtf((float)DD);

    rope_table_kernel<<<1024, 256>>>();

    // ---- write-side encoder on raw_emb (8 docs) ----
    cudaMemcpyAsync(pX, raw_emb, (size_t)NDOC * SS * DD * sizeof(float),
                    cudaMemcpyDeviceToDevice, 0);
    run_encoder(pX, NDOC, pos_w, /*log*/1,
                encw_Wqkv, encw_bqkv, encw_Wo, encw_bo, encw_ln, encw_Wff, encw_bff,
                pQ, pK, pV, pS);

    // v = raw_emb * sigmoid(for_ignore @ W_ig + b_ig)
    vgate_kernel<<<NDOC * SS, 256>>>(pX, raw_emb, W_ig, b_ig, pVd);
    // k = raw_emb @ W_k
    gemm_launch(raw_emb, W_k, nullptr, pKd, NDOC * SS, DD, DD, 1, 0, 0, 0, 1.0f, 0, 0);
    // S1[n] = questions @ k[n]^T * scD  (+ log bias in softmax)
    gemm_launch(questions, pKd, nullptr, pS, QQ, SS, DD, NDOC, 0, 524288, 65536, scD, 1, 0);
    softmax_kernel<<<NDOC * QQ, 256>>>(pS, pos_w, SS, QQ, 1);
    // A1S[n] = S1[n] @ v[n]
    gemm_launch(pS, pVd, nullptr, pA1, QQ, DD, SS, NDOC, 65536, 524288, 32768, 1.0f, 0, 0);

    // ---- read-side encoder on post_dec (16 batches) ----
    cudaMemcpyAsync(pX, post_dec, (size_t)NBB * SS * DD * sizeof(float),
                    cudaMemcpyDeviceToDevice, 0);
    run_encoder(pX, NBB, pos_r, /*logit*/2,
                encr_Wqkv, encr_bqkv, encr_Wo, encr_bo, encr_ln, encr_Wff, encr_bff,
                pQ, pK, pV, pS);

    // k2 = post_dec @ W_ok + b_ok
    gemm_launch(post_dec, W_ok, b_ok, pK2, NBB * SS, DD, DD, 1, 0, 0, 0, 1.0f, 0, 0);
    // a2 = softmax(k2 @ questions^T / 8)
    gemm_launch(pK2, questions, nullptr, pA2s, NBB * SS, QQ, DD, 1, 0, 0, 0, 0.125f, 1, 0);
    softmax_kernel<<<NBB * SS, 256>>>(pA2s, nullptr, QQ, 1, 0);
    // selA gather + A2 = a2 @ selA
    gather_kernel<<<(NBB * QQ * DD) / 256, 256>>>(pSel, pA1, lookup);
    gemm_launch(pA2s, pSel, nullptr, pA2, SS, DD, QQ, NBB, 65536, 32768, 524288, 1.0f, 0, 0);

    // final gate + output
    out_kernel<<<NBB * SS, 256>>>(pX, pA2, post_dec,
                                  W_u1, b_u1, W_u2, b_u2, b1,
                                  out, gate);

    (void)in_sizes; (void)n_in; (void)out_size;
}

// round 2
// speedup vs baseline: 1.0784x; 1.0784x over previous
#include <cuda_runtime.h>
#include <math.h>

// ---------------------------------------------------------------------------
// Problem constants
// ---------------------------------------------------------------------------
#define DD     512
#define SS     1024
#define NBB    16
#define QQ     64
#define NDOC   8

// ---------------------------------------------------------------------------
// Scratch (device globals; no allocation anywhere)
// ---------------------------------------------------------------------------
__device__ float g_X   [16384 * 512];
__device__ float g_Qb  [16384 * 512];
__device__ float g_Kb  [16384 * 512];
__device__ float g_Vb  [16384 * 512];
__device__ float g_S   [16 * 1024 * 1024];
__device__ float g_Kdoc[8192 * 512];
__device__ float g_Vdoc[8192 * 512];
__device__ float g_A1S [8 * 64 * 512];
__device__ float g_SELA[16 * 64 * 512];
__device__ float g_K2  [16384 * 512];
__device__ float g_A2SC[16384 * 64];
__device__ float g_A2  [16384 * 512];
__device__ float g_sin [1024 * 256];
__device__ float g_cos [1024 * 256];

// ---------------------------------------------------------------------------
// Fast tiled fp32 GEMM (128x128x16 tiles, 8x8 microtile, double-buffered smem)
//   C[M,N] = alpha * A[M,K] @ op(B) + bias[N]; op(B)=B[K,N] or B[N,K]^T
//   batch via blockIdx.z; epi: 0=none, 1=gelu.
//   Requires M%128==0, N%128==0, K%16==0.
// ---------------------------------------------------------------------------
#define TM 128
#define TN 128
#define TK 16

__global__ void __launch_bounds__(256, 2)
gemm128_kernel(const float* __restrict__ A,
               const float* __restrict__ Bm,
               const float* __restrict__ bias,
               float* __restrict__ C,
               int M, int N, int K,
               long long sA, long long sB, long long sC,
               float alpha, int transB, int epi)
{
    const int bz = blockIdx.z;
    A  += (size_t)bz * sA;
    Bm += (size_t)bz * sB;
    C  += (size_t)bz * sC;

    const int m0 = blockIdx.y * TM;
    const int n0 = blockIdx.x * TN;

    __shared__ float As[2][TK][TM + 4];
    __shared__ float Bs[2][TK][TN + 4];

    const int t  = threadIdx.x;          // 0..255
    const int tx = t & 15;               // col group
    const int ty = t >> 4;               // row group

    // global-load mapping (A tile and transposed-B tile): 128 rows x 16 k
    const int grow = t >> 1;             // 0..127
    const int gkc  = (t & 1) * 8;        // 0 or 8
    // B (no-trans) tile: 16 k x 128 n
    const int gkb  = t >> 4;             // 0..15
    const int gnb  = (t & 15) * 8;       // 0..120

    float acc[8][8] = {};
    float4 ra0, ra1, rb0, rb1;

    // ---- prefetch tile 0 straight into smem[0] ----
    {
        ra0 = *(const float4*)&A[(size_t)(m0 + grow) * K + gkc];
        ra1 = *(const float4*)&A[(size_t)(m0 + grow) * K + gkc + 4];
        if (!transB) {
            rb0 = *(const float4*)&Bm[(size_t)gkb * N + n0 + gnb];
            rb1 = *(const float4*)&Bm[(size_t)gkb * N + n0 + gnb + 4];
        } else {
            rb0 = *(const float4*)&Bm[(size_t)(n0 + grow) * K + gkc];
            rb1 = *(const float4*)&Bm[(size_t)(n0 + grow) * K + gkc + 4];
        }
        As[0][gkc + 0][grow] = ra0.x; As[0][gkc + 1][grow] = ra0.y;
        As[0][gkc + 2][grow] = ra0.z; As[0][gkc + 3][grow] = ra0.w;
        As[0][gkc + 4][grow] = ra1.x; As[0][gkc + 5][grow] = ra1.y;
        As[0][gkc + 6][grow] = ra1.z; As[0][gkc + 7][grow] = ra1.w;
        if (!transB) {
            *(float4*)&Bs[0][gkb][gnb]     = rb0;
            *(float4*)&Bs[0][gkb][gnb + 4] = rb1;
        } else {
            Bs[0][gkc + 0][grow] = rb0.x; Bs[0][gkc + 1][grow] = rb0.y;
            Bs[0][gkc + 2][grow] = rb0.z; Bs[0][gkc + 3][grow] = rb0.w;
            Bs[0][gkc + 4][grow] = rb1.x; Bs[0][gkc + 5][grow] = rb1.y;
            Bs[0][gkc + 6][grow] = rb1.z; Bs[0][gkc + 7][grow] = rb1.w;
        }
    }
    __syncthreads();

    int buf = 0;
    for (int k0 = 0; k0 < K; k0 += TK) {
        const bool has_next = (k0 + TK) < K;
        if (has_next) {
            const int kn = k0 + TK;
            ra0 = *(const float4*)&A[(size_t)(m0 + grow) * K + kn + gkc];
            ra1 = *(const float4*)&A[(size_t)(m0 + grow) * K + kn + gkc + 4];
            if (!transB) {
                rb0 = *(const float4*)&Bm[(size_t)(kn + gkb) * N + n0 + gnb];
                rb1 = *(const float4*)&Bm[(size_t)(kn + gkb) * N + n0 + gnb + 4];
            } else {
                rb0 = *(const float4*)&Bm[(size_t)(n0 + grow) * K + kn + gkc];
                rb1 = *(const float4*)&Bm[(size_t)(n0 + grow) * K + kn + gkc + 4];
            }
        }

#pragma unroll
        for (int k = 0; k < TK; k++) {
            float4 a0 = *(const float4*)&As[buf][k][ty * 8];
            float4 a1 = *(const float4*)&As[buf][k][ty * 8 + 4];
            float4 b0 = *(const float4*)&Bs[buf][k][tx * 8];
            float4 b1 = *(const float4*)&Bs[buf][k][tx * 8 + 4];
            float av[8] = {a0.x, a0.y, a0.z, a0.w, a1.x, a1.y, a1.z, a1.w};
            float bv[8] = {b0.x, b0.y, b0.z, b0.w, b1.x, b1.y, b1.z, b1.w};
#pragma unroll
            for (int i = 0; i < 8; i++)
#pragma unroll
                for (int j = 0; j < 8; j++)
                    acc[i][j] += av[i] * bv[j];
        }

        if (has_next) {
            __syncthreads();
            const int nb2 = buf ^ 1;
            As[nb2][gkc + 0][grow] = ra0.x; As[nb2][gkc + 1][grow] = ra0.y;
            As[nb2][gkc + 2][grow] = ra0.z; As[nb2][gkc + 3][grow] = ra0.w;
            As[nb2][gkc + 4][grow] = ra1.x; As[nb2][gkc + 5][grow] = ra1.y;
            As[nb2][gkc + 6][grow] = ra1.z; As[nb2][gkc + 7][grow] = ra1.w;
            if (!transB) {
                *(float4*)&Bs[nb2][gkb][gnb]     = rb0;
                *(float4*)&Bs[nb2][gkb][gnb + 4] = rb1;
            } else {
                Bs[nb2][gkc + 0][grow] = rb0.x; Bs[nb2][gkc + 1][grow] = rb0.y;
                Bs[nb2][gkc + 2][grow] = rb0.z; Bs[nb2][gkc + 3][grow] = rb0.w;
                Bs[nb2][gkc + 4][grow] = rb1.x; Bs[nb2][gkc + 5][grow] = rb1.y;
                Bs[nb2][gkc + 6][grow] = rb1.z; Bs[nb2][gkc + 7][grow] = rb1.w;
            }
            __syncthreads();
            buf = nb2;
        }
    }

    // ---- epilogue ----
    const float GC = 0.7978845608028654f;
#pragma unroll
    for (int i = 0; i < 8; i++) {
        const int row = m0 + ty * 8 + i;
#pragma unroll
        for (int jj = 0; jj < 2; jj++) {
            float v[4];
#pragma unroll
            for (int j = 0; j < 4; j++) {
                float x = acc[i][jj * 4 + j] * alpha;
                if (bias) x += bias[n0 + tx * 8 + jj * 4 + j];
                if (epi == 1)
                    x = 0.5f * x * (1.0f + tanhf(GC * (x + 0.044715f * x * x * x)));
                v[j] = x;
            }
            *(float4*)&C[(size_t)row * N + n0 + tx * 8 + jj * 4] =
                make_float4(v[0], v[1], v[2], v[3]);
        }
    }
}

// ---------------------------------------------------------------------------
// Fallback GEMM (64x64x16, 4x4 microtile) for shapes not 128-divisible.
// ---------------------------------------------------------------------------
#define BM 64
#define BN 64
#define BK 16

__global__ void gemm_kernel(const float* __restrict__ A,
                            const float* __restrict__ Bm,
                            const float* __restrict__ bias,
                            float* __restrict__ C,
                            int M, int N, int K,
                            long long sA, long long sB, long long sC,
                            float alpha, int transB, int epi)
{
    const int bz = blockIdx.z;
    A  += (size_t)bz * sA;
    Bm += (size_t)bz * sB;
    C  += (size_t)bz * sC;

    const int m0 = blockIdx.y * BM;
    const int n0 = blockIdx.x * BN;

    __shared__ float As[BK][BM + 4];
    __shared__ float Bs[BK][BN + 4];

    const int t  = threadIdx.x;          // 0..255
    const int tx = t & 15;
    const int ty = t >> 4;

    float acc[4][4] = {};

    const int arow = t >> 2;             // 0..63
    const int akc  = (t & 3) * 4;        // 0,4,8,12
    const int kb   = t >> 4;             // 0..15
    const int nb   = (t & 15) * 4;       // 0..60

    for (int k0 = 0; k0 < K; k0 += BK) {
        float4 av = *(const float4*)&A[(size_t)(m0 + arow) * K + k0 + akc];
        As[akc + 0][arow] = av.x;
        As[akc + 1][arow] = av.y;
        As[akc + 2][arow] = av.z;
        As[akc + 3][arow] = av.w;

        if (!transB) {
            float4 bv = *(const float4*)&Bm[(size_t)(k0 + kb) * N + n0 + nb];
            *(float4*)&Bs[kb][nb] = bv;
        } else {
            float4 bv = *(const float4*)&Bm[(size_t)(n0 + arow) * K + k0 + akc];
            Bs[akc + 0][arow] = bv.x;
            Bs[akc + 1][arow] = bv.y;
            Bs[akc + 2][arow] = bv.z;
            Bs[akc + 3][arow] = bv.w;
        }
        __syncthreads();

#pragma unroll
        for (int k = 0; k < BK; k++) {
            float4 a = *(const float4*)&As[k][ty * 4];
            float4 b = *(const float4*)&Bs[k][tx * 4];
            acc[0][0] += a.x * b.x; acc[0][1] += a.x * b.y;
            acc[0][2] += a.x * b.z; acc[0][3] += a.x * b.w;
            acc[1][0] += a.y * b.x; acc[1][1] += a.y * b.y;
            acc[1][2] += a.y * b.z; acc[1][3] += a.y * b.w;
            acc[2][0] += a.z * b.x; acc[2][1] += a.z * b.y;
            acc[2][2] += a.z * b.z; acc[2][3] += a.z * b.w;
            acc[3][0] += a.w * b.x; acc[3][1] += a.w * b.y;
            acc[3][2] += a.w * b.z; acc[3][3] += a.w * b.w;
        }
        __syncthreads();
    }

    const float GC = 0.7978845608028654f;
#pragma unroll
    for (int i = 0; i < 4; i++) {
        const int row = m0 + ty * 4 + i;
        float v[4];
#pragma unroll
        for (int j = 0; j < 4; j++) {
            float x = acc[i][j] * alpha;
            if (bias) x += bias[n0 + tx * 4 + j];
            if (epi == 1) {
                x = 0.5f * x * (1.0f + tanhf(GC * (x + 0.044715f * x * x * x)));
            }
            v[j] = x;
        }
        float4 o = make_float4(v[0], v[1], v[2], v[3]);
        *(float4*)&C[(size_t)row * N + n0 + tx * 4] = o;
    }
}

static void gemm_launch(const float* A, const float* B, const float* bias, float* C,
                        int M, int N, int K, int batch,
                        long long sA, long long sB, long long sC,
                        float alpha, int transB, int epi)
{
    if ((M % 128 == 0) && (N % 128 == 0)) {
        dim3 grid(N / TN, M / TM, batch);
        gemm128_kernel<<<grid, 256>>>(A, B, bias, C, M, N, K, sA, sB, sC, alpha, transB, epi);
    } else {
        dim3 grid(N / BN, M / BM, batch);
        gemm_kernel<<<grid, 256>>>(A, B, bias, C, M, N, K, sA, sB, sC, alpha, transB, epi);
    }
}

// ---------------------------------------------------------------------------
// RoPE: accurate sin/cos table (double range-safe), then in-place apply
// ---------------------------------------------------------------------------
__global__ void rope_table_kernel()
{
    int s = blockIdx.x;          // 0..1023
    int i = threadIdx.x;         // 0..255
    float invf = 1.0f / powf(10000.0f, (float)i / 256.0f);
    float angf = (float)s * invf;
    double ang = (double)angf;
    g_sin[s * 256 + i] = (float)sin(ang);
    g_cos[s * 256 + i] = (float)cos(ang);
}

__global__ void rope_kernel(float* __restrict__ X)
{
    int row = blockIdx.x;
    int i   = threadIdx.x;       // 0..255
    int s   = row & (SS - 1);
    float sn = g_sin[s * 256 + i];
    float cs = g_cos[s * 256 + i];
    float* xr = X + (size_t)row * DD;
    float x1 = xr[2 * i];
    float x2 = xr[2 * i + 1];
    xr[2 * i]     = x1 * cs - x2 * sn;
    xr[2 * i + 1] = x1 * sn + x2 * cs;
}

// ---------------------------------------------------------------------------
// Softmax over rows (in place), optional per-column positional bias.
// mode: 0 = none, 1 = log(p), 2 = log(p) - log1p(-p)
// ---------------------------------------------------------------------------
__global__ void softmax_kernel(float* __restrict__ S, const float* __restrict__ pos,
                               int cols, int rows_per_batch, int mode)
{
    int row = blockIdx.x;
    float* sr = S + (size_t)row * cols;
    const float* pb = (mode != 0) ? pos + (size_t)(row / rows_per_batch) * cols : nullptr;
    int t = threadIdx.x;
    __shared__ float red[256];

    float mx = -1e30f;
    for (int c = t; c < cols; c += 256) {
        float v = sr[c];
        if (mode == 1)       v += logf(pb[c]);
        else if (mode == 2) { float p = pb[c]; v += logf(p) - log1pf(-p); }
        sr[c] = v;
        mx = fmaxf(mx, v);
    }
    red[t] = mx; __syncthreads();
    for (int s = 128; s > 0; s >>= 1) { if (t < s) red[t] = fmaxf(red[t], red[t + s]); __syncthreads(); }
    mx = red[0]; __syncthreads();

    float sum = 0.0f;
    for (int c = t; c < cols; c += 256) {
        float e = expf(sr[c] - mx);
        sr[c] = e;
        sum += e;
    }
    red[t] = sum; __syncthreads();
    for (int s = 128; s > 0; s >>= 1) { if (t < s) red[t] += red[t + s]; __syncthreads(); }
    float inv = 1.0f / red[0];

    for (int c = t; c < cols; c += 256) sr[c] *= inv;
}

// ---------------------------------------------------------------------------
// X = LayerNorm(X + R) * g + b
// ---------------------------------------------------------------------------
__global__ void ln_kernel(float* __restrict__ X, const float* __restrict__ R,
                          const float* __restrict__ g, const float* __restrict__ b)
{
    int row = blockIdx.x;
    int t   = threadIdx.x;
    float* xr = X + (size_t)row * DD;
    const float* rr = R + (size_t)row * DD;

    float v0 = xr[t] + rr[t];
    float v1 = xr[t + 256] + rr[t + 256];

    __shared__ float red[256];
    red[t] = v0 + v1; __syncthreads();
    for (int s = 128; s > 0; s >>= 1) { if (t < s) red[t] += red[t + s]; __syncthreads(); }
    float m = red[0] * (1.0f / 512.0f);
    __syncthreads();

    float d0 = v0 - m, d1 = v1 - m;
    red[t] = d0 * d0 + d1 * d1; __syncthreads();
    for (int s = 128; s > 0; s >>= 1) { if (t < s) red[t] += red[t + s]; __syncthreads(); }
    float var = red[0] * (1.0f / 512.0f);
    float inv = rsqrtf(var + 1e-5f);

    xr[t]       = d0 * inv * g[t]       + b[t];
    xr[t + 256] = d1 * inv * g[t + 256] + b[t + 256];
}

// ---------------------------------------------------------------------------
// V = raw * sigmoid(F . W_ig + b_ig)
// ---------------------------------------------------------------------------
__global__ void vgate_kernel(const float* __restrict__ F, const float* __restrict__ raw,
                             const float* __restrict__ Wig, const float* __restrict__ big,
                             float* __restrict__ V)
{
    int row = blockIdx.x;
    int t   = threadIdx.x;
    const float* fr = F + (size_t)row * DD;
    __shared__ float red[256];
    float s = fr[t] * Wig[t] + fr[t + 256] * Wig[t + 256];
    red[t] = s; __syncthreads();
    for (int k = 128; k > 0; k >>= 1) { if (t < k) red[t] += red[t + k]; __syncthreads(); }
    float gte = 1.0f / (1.0f + expf(-(red[0] + big[0])));
    const float* rr = raw + (size_t)row * DD;
    float* vr = V + (size_t)row * DD;
    vr[t]       = rr[t]       * gte;
    vr[t + 256] = rr[t + 256] * gte;
}

// ---------------------------------------------------------------------------
// SELA[b] = A1S[lookup_ids[b]]
// ---------------------------------------------------------------------------
__global__ void gather_kernel(float* __restrict__ dst, const float* __restrict__ src,
                              const int* __restrict__ ids)
{
    int idx = blockIdx.x * 256 + threadIdx.x;
    int b   = idx >> 15;
    int rem = idx & 32767;
    dst[idx] = src[(size_t)ids[b] * 32768 + rem];
}

// ---------------------------------------------------------------------------
// Final gate + output
// ---------------------------------------------------------------------------
__global__ void out_kernel(const float* __restrict__ FU, const float* __restrict__ A2,
                           const float* __restrict__ PD,
                           const float* __restrict__ Wu1, const float* __restrict__ bu1,
                           const float* __restrict__ Wu2, const float* __restrict__ bu2,
                           const float* __restrict__ b1,
                           float* __restrict__ out, float* __restrict__ gate)
{
    int row = blockIdx.x;
    int t   = threadIdx.x;
    const float* fu = FU + (size_t)row * DD;
    const float* a2 = A2 + (size_t)row * DD;
    const float* pd = PD + (size_t)row * DD;

    __shared__ float red[256];
    float s = fu[t] * Wu1[t] + fu[t + 256] * Wu1[t + 256]
            + a2[t] * Wu2[t] + a2[t + 256] * Wu2[t + 256];
    red[t] = s; __syncthreads();
    for (int k = 128; k > 0; k >>= 1) { if (t < k) red[t] += red[t + k]; __syncthreads(); }
    float z = red[0] + bu1[0] + bu2[0] + b1[0] - 4.0f;
    float g = 1.0f / (1.0f + expf(-z));

    float* orow = out + (size_t)row * DD;
    orow[t]       = pd[t]       * (1.0f - g) + a2[t]       * g;
    orow[t + 256] = pd[t + 256] * (1.0f - g) + a2[t + 256] * g;
    if (t == 0) gate[row] = g;
}

// ---------------------------------------------------------------------------
// Host orchestration
// ---------------------------------------------------------------------------
static void run_encoder(float* X, int nb, const float* pos, int posmode,
                        const float* Wqkv, const float* bqkv,
                        const float* Wo, const float* bo,
                        const float* ln, const float* Wff, const float* bff,
                        float* bQ, float* bK, float* bV, float* bS)
{
    const int rows = nb * SS;
    const float sc = 1.0f / sqrtf((float)DD);
    for (int l = 0; l < 2; l++) {
        const float* Wl = Wqkv + (size_t)l * 3 * DD * DD;
        const float* bl = bqkv + (size_t)l * 3 * DD;
        gemm_launch(X, Wl + 0 * 262144, bl + 0,    bQ, rows, DD, DD, 1, 0, 0, 0, 1.0f, 0, 0);
        gemm_launch(X, Wl + 1 * 262144, bl + 512,  bK, rows, DD, DD, 1, 0, 0, 0, 1.0f, 0, 0);
        gemm_launch(X, Wl + 2 * 262144, bl + 1024, bV, rows, DD, DD, 1, 0, 0, 0, 1.0f, 0, 0);
        rope_kernel<<<rows, 256>>>(bQ);
        rope_kernel<<<rows, 256>>>(bK);
        gemm_launch(bQ, bK, nullptr, bS, SS, SS, DD, nb, 524288, 524288, 1048576, sc, 1, 0);
        softmax_kernel<<<rows, 256>>>(bS, pos, SS, SS, posmode);
        gemm_launch(bS, bV, nullptr, bQ, SS, DD, SS, nb, 1048576, 524288, 524288, 1.0f, 0, 0);
        gemm_launch(bQ, Wo + (size_t)l * 262144, bo + l * 512, bK, rows, DD, DD, 1, 0, 0, 0, 1.0f, 0, 0);
        ln_kernel<<<rows, 256>>>(X, bK, ln + l * 2048, ln + l * 2048 + 512);
        gemm_launch(X, Wff + (size_t)l * 524288, bff + l * 1024, bQ, rows, DD, DD, 1, 0, 0, 0, 1.0f, 0, 1);
        gemm_launch(bQ, Wff + (size_t)l * 524288 + 262144, bff + l * 1024 + 512, bK,
                    rows, DD, DD, 1, 0, 0, 0, 1.0f, 0, 0);
        ln_kernel<<<rows, 256>>>(X, bK, ln + l * 2048 + 1024, ln + l * 2048 + 1536);
    }
}

extern "C" void kernel_launch(void* const* d_in, const int* in_sizes, int n_in,
                              void* d_out, int out_size)
{
    const float* raw_emb   = (const float*)d_in[0];
    const float* pos_w     = (const float*)d_in[1];
    const float* post_dec  = (const float*)d_in[2];
    const float* pos_r     = (const float*)d_in[3];
    const float* questions = (const float*)d_in[4];
    const float* W_k       = (const float*)d_in[5];
    const float* W_ig      = (const float*)d_in[6];
    const float* b_ig      = (const float*)d_in[7];
    const float* W_u1      = (const float*)d_in[8];
    const float* b_u1      = (const float*)d_in[9];
    const float* W_u2      = (const float*)d_in[10];
    const float* b_u2      = (const float*)d_in[11];
    const float* b1        = (const float*)d_in[12];
    const float* W_ok      = (const float*)d_in[13];
    const float* b_ok      = (const float*)d_in[14];
    const float* encw_Wqkv = (const float*)d_in[15];
    const float* encw_bqkv = (const float*)d_in[16];
    const float* encw_Wo   = (const float*)d_in[17];
    const float* encw_bo   = (const float*)d_in[18];
    const float* encw_ln   = (const float*)d_in[19];
    const float* encw_Wff  = (const float*)d_in[20];
    const float* encw_bff  = (const float*)d_in[21];
    const float* encr_Wqkv = (const float*)d_in[22];
    const float* encr_bqkv = (const float*)d_in[23];
    const float* encr_Wo   = (const float*)d_in[24];
    const float* encr_bo   = (const float*)d_in[25];
    const float* encr_ln   = (const float*)d_in[26];
    const float* encr_Wff  = (const float*)d_in[27];
    const float* encr_bff  = (const float*)d_in[28];
    const int*   lookup    = (const int*)d_in[29];

    float* out  = (float*)d_out;
    float* gate = out + (size_t)NBB * SS * DD;

    float *pX, *pQ, *pK, *pV, *pS, *pKd, *pVd, *pA1, *pSel, *pK2, *pA2s, *pA2;
    cudaGetSymbolAddress((void**)&pX,   g_X);
    cudaGetSymbolAddress((void**)&pQ,   g_Qb);
    cudaGetSymbolAddress((void**)&pK,   g_Kb);
    cudaGetSymbolAddress((void**)&pV,   g_Vb);
    cudaGetSymbolAddress((void**)&pS,   g_S);
    cudaGetSymbolAddress((void**)&pKd,  g_Kdoc);
    cudaGetSymbolAddress((void**)&pVd,  g_Vdoc);
    cudaGetSymbolAddress((void**)&pA1,  g_A1S);
    cudaGetSymbolAddress((void**)&pSel, g_SELA);
    cudaGetSymbolAddress((void**)&pK2,  g_K2);
    cudaGetSymbolAddress((void**)&pA2s, g_A2SC);
    cudaGetSymbolAddress((void**)&pA2,  g_A2);

    const float scD = 1.0f / sqrtf((float)DD);

    rope_table_kernel<<<1024, 256>>>();

    // ---- write-side encoder on raw_emb (8 docs) ----
    cudaMemcpyAsync(pX, raw_emb, (size_t)NDOC * SS * DD * sizeof(float),
                    cudaMemcpyDeviceToDevice, 0);
    run_encoder(pX, NDOC, pos_w, /*log*/1,
                encw_Wqkv, encw_bqkv, encw_Wo, encw_bo, encw_ln, encw_Wff, encw_bff,
                pQ, pK, pV, pS);

    vgate_kernel<<<NDOC * SS, 256>>>(pX, raw_emb, W_ig, b_ig, pVd);
    gemm_launch(raw_emb, W_k, nullptr, pKd, NDOC * SS, DD, DD, 1, 0, 0, 0, 1.0f, 0, 0);
    gemm_launch(questions, pKd, nullptr, pS, QQ, SS, DD, NDOC, 0, 524288, 65536, scD, 1, 0);
    softmax_kernel<<<NDOC * QQ, 256>>>(pS, pos_w, SS, QQ, 1);
    gemm_launch(pS, pVd, nullptr, pA1, QQ, DD, SS, NDOC, 65536, 524288, 32768, 1.0f, 0, 0);

    // ---- read-side encoder on post_dec (16 batches) ----
    cudaMemcpyAsync(pX, post_dec, (size_t)NBB * SS * DD * sizeof(float),
                    cudaMemcpyDeviceToDevice, 0);
    run_encoder(pX, NBB, pos_r, /*logit*/2,
                encr_Wqkv, encr_bqkv, encr_Wo, encr_bo, encr_ln, encr_Wff, encr_bff,
                pQ, pK, pV, pS);

    gemm_launch(post_dec, W_ok, b_ok, pK2, NBB * SS, DD, DD, 1, 0, 0, 0, 1.0f, 0, 0);
    gemm_launch(pK2, questions, nullptr, pA2s, NBB * SS, QQ, DD, 1, 0, 0, 0, 0.125f, 1, 0);
    softmax_kernel<<<NBB * SS, 256>>>(pA2s, nullptr, QQ, 1, 0);
    gather_kernel<<<(NBB * QQ * DD) / 256, 256>>>(pSel, pA1, lookup);
    gemm_launch(pA2s, pSel, nullptr, pA2, SS, DD, QQ, NBB, 65536, 32768, 524288, 1.0f, 0, 0);

    out_kernel<<<NBB * SS, 256>>>(pX, pA2, post_dec,
                                  W_u1, b_u1, W_u2, b_u2, b1,
                                  out, gate);

    (void)in_sizes; (void)n_in; (void)out_size;
}

// round 4
// speedup vs baseline: 1.6308x; 1.5123x over previous
#include <cuda_runtime.h>
#include <cuda_bf16.h>
#include <math.h>
#include <stdint.h>

// ---------------------------------------------------------------------------
// Problem constants
// ---------------------------------------------------------------------------
#define DD     512
#define SS     1024
#define NBB    16
#define QQ     64
#define NDOC   8

// ---------------------------------------------------------------------------
// Scratch (device globals; no allocation anywhere)
// ---------------------------------------------------------------------------
__device__ float g_X   [16384 * 512];
__device__ float g_Qb  [16384 * 512];
__device__ float g_Kb  [16384 * 512];
__device__ float g_Vb  [16384 * 512];
__device__ float g_S   [16 * 1024 * 1024];
__device__ float g_Kdoc[8192 * 512];
__device__ float g_Vdoc[8192 * 512];
__device__ float g_A1S [8 * 64 * 512];
__device__ float g_SELA[16 * 64 * 512];
__device__ float g_SELAT[16 * 512 * 64];
__device__ float g_K2  [16384 * 512];
__device__ float g_A2SC[16384 * 64];
__device__ float g_A2  [16384 * 512];
__device__ float g_sin [1024 * 256];
__device__ float g_cos [1024 * 256];
__device__ float g_VT  [16 * 512 * 1024];
__device__ float g_WTw [12 * 512 * 512];
__device__ float g_WTr [12 * 512 * 512];
__device__ float g_WkT [512 * 512];
__device__ float g_WokT[512 * 512];

// ---------------------------------------------------------------------------
// Warp-MMA helpers (baseline PTX, compiles for compute_103)
// ---------------------------------------------------------------------------
__device__ __forceinline__ uint32_t smem_u32(const void* p) {
    uint32_t a;
    asm("{ .reg .u64 t; cvta.to.shared.u64 t, %1; cvt.u32.u64 %0, t; }"
        : "=r"(a) : "l"(p));
    return a;
}

__device__ __forceinline__ void ldsm4(uint32_t* r, uint32_t addr) {
    asm volatile("ldmatrix.sync.aligned.m8n8.x4.shared.b16 {%0,%1,%2,%3}, [%4];"
                 : "=r"(r[0]), "=r"(r[1]), "=r"(r[2]), "=r"(r[3]) : "r"(addr));
}

__device__ __forceinline__ void mma_bf16(float* c, const uint32_t* a,
                                         uint32_t b0, uint32_t b1) {
    asm volatile(
        "mma.sync.aligned.m16n8k16.row.col.f32.bf16.bf16.f32 "
        "{%0,%1,%2,%3}, {%4,%5,%6,%7}, {%8,%9}, {%0,%1,%2,%3};"
        : "+f"(c[0]), "+f"(c[1]), "+f"(c[2]), "+f"(c[3])
        : "r"(a[0]), "r"(a[1]), "r"(a[2]), "r"(a[3]), "r"(b0), "r"(b1));
}

__device__ __forceinline__ uint32_t pack_hi(float x, float y, float& rx, float& ry) {
    __nv_bfloat162 h = __floats2bfloat162_rn(x, y);
    rx = __bfloat162float(h.x);
    ry = __bfloat162float(h.y);
    return *(uint32_t*)&h;
}
__device__ __forceinline__ uint32_t pack_lo(float x, float y) {
    __nv_bfloat162 h = __floats2bfloat162_rn(x, y);
    return *(uint32_t*)&h;
}

// ---------------------------------------------------------------------------
// Tensor GEMM via mma.sync bf16 with hi/lo split (fp32-class accuracy):
//   C[M,N] = alpha * A[M,K] @ Bt[N,K]^T + bias[N]; epi: 0=none, 1=gelu
//   M%128==0, N%128==0, K%32==0. batch via blockIdx.z.
// SMEM per stage (40960B): Ah(10240) Al(10240) Bh(10240) Bl(10240)
//   plane: 128 rows x 32 bf16, row stride 80B (conflict-free ldmatrix).
// ---------------------------------------------------------------------------
#define TG_SMEM (2 * 40960)
#define PLANE   10240
#define RSTRIDE 80

__global__ void __launch_bounds__(256)
tgemm_kernel(const float* __restrict__ A, const float* __restrict__ Bt,
             const float* __restrict__ bias, float* __restrict__ C,
             int M, int N, int K,
             long long sA, long long sB, long long sC,
             float alpha, int epi)
{
    extern __shared__ char smem[];
    const uint32_t sbu = smem_u32(smem);
    const int t    = threadIdx.x;
    const int w    = t >> 5;
    const int lane = t & 31;
    const int wm   = w & 3;          // 4 m-groups of 32 rows
    const int wn   = w >> 2;         // 2 n-groups of 64 cols

    A  += (size_t)blockIdx.z * sA;
    Bt += (size_t)blockIdx.z * sB;
    C  += (size_t)blockIdx.z * sC;
    const int m0 = blockIdx.y * 128;
    const int n0 = blockIdx.x * 128;

    const float* Ag = A  + (size_t)(m0 + (t >> 1)) * K + (t & 1) * 16;
    const float* Bg = Bt + (size_t)(n0 + (t >> 1)) * K + (t & 1) * 16;

    float acc[2][8][4];
#pragma unroll
    for (int i = 0; i < 2; i++)
#pragma unroll
        for (int j = 0; j < 8; j++)
#pragma unroll
            for (int e = 0; e < 4; e++) acc[i][j][e] = 0.0f;

    uint32_t pa[16], pb[16];     // [0..8) hi, [8..16) lo

#define LOADCV(ch) do {                                                     \
    const float* _ap = Ag + (ch) * 32;                                      \
    const float* _bp = Bg + (ch) * 32;                                      \
    _Pragma("unroll")                                                       \
    for (int j = 0; j < 4; j++) {                                           \
        float4 va = *(const float4*)(_ap + j * 4);                          \
        float4 vb = *(const float4*)(_bp + j * 4);                          \
        float hx, hy, hz, hw;                                               \
        pa[j*2+0] = pack_hi(va.x, va.y, hx, hy);                            \
        pa[j*2+1] = pack_hi(va.z, va.w, hz, hw);                            \
        pa[8+j*2+0] = pack_lo(va.x - hx, va.y - hy);                        \
        pa[8+j*2+1] = pack_lo(va.z - hz, va.w - hw);                        \
        pb[j*2+0] = pack_hi(vb.x, vb.y, hx, hy);                            \
        pb[j*2+1] = pack_hi(vb.z, vb.w, hz, hw);                            \
        pb[8+j*2+0] = pack_lo(vb.x - hx, vb.y - hy);                        \
        pb[8+j*2+1] = pack_lo(vb.z - hz, vb.w - hw);                        \
    }                                                                       \
} while (0)

    const int soff = (t >> 1) * RSTRIDE + (t & 1) * 32;
    const uint32_t lmoff = (uint32_t)((lane & 15) * RSTRIDE + (lane >> 4) * 16);
    const int nch = K >> 5;

    LOADCV(0);

    for (int ch = 0; ch < nch; ch++) {
        const int stage = ch & 1;
        char* sp = smem + stage * 40960;
        // store current regs -> smem planes
        *(uint4*)(sp + 0 * PLANE + soff)      = make_uint4(pa[0], pa[1], pa[2], pa[3]);
        *(uint4*)(sp + 0 * PLANE + soff + 16) = make_uint4(pa[4], pa[5], pa[6], pa[7]);
        *(uint4*)(sp + 1 * PLANE + soff)      = make_uint4(pa[8], pa[9], pa[10], pa[11]);
        *(uint4*)(sp + 1 * PLANE + soff + 16) = make_uint4(pa[12], pa[13], pa[14], pa[15]);
        *(uint4*)(sp + 2 * PLANE + soff)      = make_uint4(pb[0], pb[1], pb[2], pb[3]);
        *(uint4*)(sp + 2 * PLANE + soff + 16) = make_uint4(pb[4], pb[5], pb[6], pb[7]);
        *(uint4*)(sp + 3 * PLANE + soff)      = make_uint4(pb[8], pb[9], pb[10], pb[11]);
        *(uint4*)(sp + 3 * PLANE + soff + 16) = make_uint4(pb[12], pb[13], pb[14], pb[15]);
        __syncthreads();

        if (ch + 1 < nch) LOADCV(ch + 1);

        const uint32_t sAh = sbu + stage * 40960;
        const uint32_t sBh = sAh + 2 * PLANE;
#pragma unroll
        for (int kk = 0; kk < 2; kk++) {
            uint32_t ah[2][4], al[2][4];
#pragma unroll
            for (int mt = 0; mt < 2; mt++) {
                uint32_t aaddr = sAh + (uint32_t)((wm * 32 + mt * 16) * RSTRIDE + kk * 32) + lmoff;
                ldsm4(ah[mt], aaddr);
                ldsm4(al[mt], aaddr + PLANE);
            }
#pragma unroll
            for (int ng = 0; ng < 4; ng++) {
                uint32_t bh[4], bl[4];
                uint32_t baddr = sBh + (uint32_t)((wn * 64 + ng * 16) * RSTRIDE + kk * 32) + lmoff;
                ldsm4(bh, baddr);
                ldsm4(bl, baddr + PLANE);
#pragma unroll
                for (int mt = 0; mt < 2; mt++) {
#pragma unroll
                    for (int half = 0; half < 2; half++) {
                        float* c = acc[mt][ng * 2 + half];
                        mma_bf16(c, ah[mt], bh[half], bh[half + 2]);
                        mma_bf16(c, ah[mt], bl[half], bl[half + 2]);
                        mma_bf16(c, al[mt], bh[half], bh[half + 2]);
                    }
                }
            }
        }
    }

    // ---- epilogue ----
    const float GC = 0.7978845608028654f;
    const int crow = m0 + wm * 32 + (lane >> 2);
    const int ccol = n0 + wn * 64 + (lane & 3) * 2;
#pragma unroll
    for (int mt = 0; mt < 2; mt++) {
#pragma unroll
        for (int n8 = 0; n8 < 8; n8++) {
            const float* c = acc[mt][n8];
            const int col = ccol + n8 * 8;
            float b0 = bias ? bias[col]     : 0.0f;
            float b1 = bias ? bias[col + 1] : 0.0f;
#pragma unroll
            for (int h = 0; h < 2; h++) {
                const int row = crow + mt * 16 + h * 8;
                float x0 = c[h * 2 + 0] * alpha + b0;
                float x1 = c[h * 2 + 1] * alpha + b1;
                if (epi) {
                    x0 = 0.5f * x0 * (1.0f + tanhf(GC * (x0 + 0.044715f * x0 * x0 * x0)));
                    x1 = 0.5f * x1 * (1.0f + tanhf(GC * (x1 + 0.044715f * x1 * x1 * x1)));
                }
                *(float2*)&C[(size_t)row * N + col] = make_float2(x0, x1);
            }
        }
    }
}

static void tgemm_launch(const float* A, const float* Bt, const float* bias, float* C,
                         int M, int N, int K, int batch,
                         long long sA, long long sB, long long sC,
                         float alpha, int epi)
{
    dim3 grid(N / 128, M / 128, batch);
    tgemm_kernel<<<grid, 256, TG_SMEM>>>(A, Bt, bias, C, M, N, K, sA, sB, sC, alpha, epi);
}

// ---------------------------------------------------------------------------
// Transpose: out[b][c][r] = in[b][r][c]; R,C multiples of 32.
// ---------------------------------------------------------------------------
__global__ void transpose_kernel(const float* __restrict__ in, float* __restrict__ out,
                                 int R, int C, long long sI, long long sO)
{
    __shared__ float tile[32][33];
    const float* ib = in + (size_t)blockIdx.z * sI;
    float* ob = out + (size_t)blockIdx.z * sO;
    int c0 = blockIdx.x * 32, r0 = blockIdx.y * 32;
    int tx = threadIdx.x, ty = threadIdx.y;
#pragma unroll
    for (int k = 0; k < 32; k += 8)
        tile[ty + k][tx] = ib[(size_t)(r0 + ty + k) * C + c0 + tx];
    __syncthreads();
#pragma unroll
    for (int k = 0; k < 32; k += 8)
        ob[(size_t)(c0 + ty + k) * R + r0 + tx] = tile[tx][ty + k];
}

// ---------------------------------------------------------------------------
// SIMT fallback GEMM (64x64x16) for odd shapes (M=64 or N=64 cases)
// ---------------------------------------------------------------------------
#define BM 64
#define BN 64
#define BK 16

__global__ void gemm_kernel(const float* __restrict__ A,
                            const float* __restrict__ Bm,
                            const float* __restrict__ bias,
                            float* __restrict__ C,
                            int M, int N, int K,
                            long long sA, long long sB, long long sC,
                            float alpha, int transB, int epi)
{
    const int bz = blockIdx.z;
    A  += (size_t)bz * sA;
    Bm += (size_t)bz * sB;
    C  += (size_t)bz * sC;

    const int m0 = blockIdx.y * BM;
    const int n0 = blockIdx.x * BN;

    __shared__ float As[BK][BM + 4];
    __shared__ float Bs[BK][BN + 4];

    const int t  = threadIdx.x;
    const int tx = t & 15;
    const int ty = t >> 4;

    float acc[4][4] = {};

    const int arow = t >> 2;
    const int akc  = (t & 3) * 4;
    const int kb   = t >> 4;
    const int nb   = (t & 15) * 4;

    for (int k0 = 0; k0 < K; k0 += BK) {
        float4 av = *(const float4*)&A[(size_t)(m0 + arow) * K + k0 + akc];
        As[akc + 0][arow] = av.x;
        As[akc + 1][arow] = av.y;
        As[akc + 2][arow] = av.z;
        As[akc + 3][arow] = av.w;

        if (!transB) {
            float4 bv = *(const float4*)&Bm[(size_t)(k0 + kb) * N + n0 + nb];
            *(float4*)&Bs[kb][nb] = bv;
        } else {
            float4 bv = *(const float4*)&Bm[(size_t)(n0 + arow) * K + k0 + akc];
            Bs[akc + 0][arow] = bv.x;
            Bs[akc + 1][arow] = bv.y;
            Bs[akc + 2][arow] = bv.z;
            Bs[akc + 3][arow] = bv.w;
        }
        __syncthreads();

#pragma unroll
        for (int k = 0; k < BK; k++) {
            float4 a = *(const float4*)&As[k][ty * 4];
            float4 b = *(const float4*)&Bs[k][tx * 4];
            acc[0][0] += a.x * b.x; acc[0][1] += a.x * b.y;
            acc[0][2] += a.x * b.z; acc[0][3] += a.x * b.w;
            acc[1][0] += a.y * b.x; acc[1][1] += a.y * b.y;
            acc[1][2] += a.y * b.z; acc[1][3] += a.y * b.w;
            acc[2][0] += a.z * b.x; acc[2][1] += a.z * b.y;
            acc[2][2] += a.z * b.z; acc[2][3] += a.z * b.w;
            acc[3][0] += a.w * b.x; acc[3][1] += a.w * b.y;
            acc[3][2] += a.w * b.z; acc[3][3] += a.w * b.w;
        }
        __syncthreads();
    }

    const float GC = 0.7978845608028654f;
#pragma unroll
    for (int i = 0; i < 4; i++) {
        const int row = m0 + ty * 4 + i;
        float v[4];
#pragma unroll
        for (int j = 0; j < 4; j++) {
            float x = acc[i][j] * alpha;
            if (bias) x += bias[n0 + tx * 4 + j];
            if (epi == 1)
                x = 0.5f * x * (1.0f + tanhf(GC * (x + 0.044715f * x * x * x)));
            v[j] = x;
        }
        *(float4*)&C[(size_t)row * N + n0 + tx * 4] = make_float4(v[0], v[1], v[2], v[3]);
    }
}

static void sgemm_launch(const float* A, const float* B, const float* bias, float* C,
                         int M, int N, int K, int batch,
                         long long sA, long long sB, long long sC,
                         float alpha, int transB, int epi)
{
    dim3 grid(N / BN, M / BM, batch);
    gemm_kernel<<<grid, 256>>>(A, B, bias, C, M, N, K, sA, sB, sC, alpha, transB, epi);
}

// ---------------------------------------------------------------------------
// RoPE table + apply
// ---------------------------------------------------------------------------
__global__ void rope_table_kernel()
{
    int s = blockIdx.x;
    int i = threadIdx.x;
    float invf = 1.0f / powf(10000.0f, (float)i / 256.0f);
    float angf = (float)s * invf;
    double ang = (double)angf;
    g_sin[s * 256 + i] = (float)sin(ang);
    g_cos[s * 256 + i] = (float)cos(ang);
}

__global__ void rope_kernel(float* __restrict__ X)
{
    int row = blockIdx.x;
    int i   = threadIdx.x;
    int s   = row & (SS - 1);
    float sn = g_sin[s * 256 + i];
    float cs = g_cos[s * 256 + i];
    float* xr = X + (size_t)row * DD;
    float x1 = xr[2 * i];
    float x2 = xr[2 * i + 1];
    xr[2 * i]     = x1 * cs - x2 * sn;
    xr[2 * i + 1] = x1 * sn + x2 * cs;
}

// ---------------------------------------------------------------------------
// Softmax (in place), optional positional bias: 0=none,1=log(p),2=logit(p)
// ---------------------------------------------------------------------------
__global__ void softmax_kernel(float* __restrict__ S, const float* __restrict__ pos,
                               int cols, int rows_per_batch, int mode)
{
    int row = blockIdx.x;
    float* sr = S + (size_t)row * cols;
    const float* pb = (mode != 0) ? pos + (size_t)(row / rows_per_batch) * cols : nullptr;
    int t = threadIdx.x;
    __shared__ float red[256];

    float mx = -1e30f;
    for (int c = t; c < cols; c += 256) {
        float v = sr[c];
        if (mode == 1)       v += logf(pb[c]);
        else if (mode == 2) { float p = pb[c]; v += logf(p) - log1pf(-p); }
        sr[c] = v;
        mx = fmaxf(mx, v);
    }
    red[t] = mx; __syncthreads();
    for (int s = 128; s > 0; s >>= 1) { if (t < s) red[t] = fmaxf(red[t], red[t + s]); __syncthreads(); }
    mx = red[0]; __syncthreads();

    float sum = 0.0f;
    for (int c = t; c < cols; c += 256) {
        float e = expf(sr[c] - mx);
        sr[c] = e;
        sum += e;
    }
    red[t] = sum; __syncthreads();
    for (int s = 128; s > 0; s >>= 1) { if (t < s) red[t] += red[t + s]; __syncthreads(); }
    float inv = 1.0f / red[0];

    for (int c = t; c < cols; c += 256) sr[c] *= inv;
}

// ---------------------------------------------------------------------------
// X = LayerNorm(X + R) * g + b
// ---------------------------------------------------------------------------
__global__ void ln_kernel(float* __restrict__ X, const float* __restrict__ R,
                          const float* __restrict__ g, const float* __restrict__ b)
{
    int row = blockIdx.x;
    int t   = threadIdx.x;
    float* xr = X + (size_t)row * DD;
    const float* rr = R + (size_t)row * DD;

    float v0 = xr[t] + rr[t];
    float v1 = xr[t + 256] + rr[t + 256];

    __shared__ float red[256];
    red[t] = v0 + v1; __syncthreads();
    for (int s = 128; s > 0; s >>= 1) { if (t < s) red[t] += red[t + s]; __syncthreads(); }
    float m = red[0] * (1.0f / 512.0f);
    __syncthreads();

    float d0 = v0 - m, d1 = v1 - m;
    red[t] = d0 * d0 + d1 * d1; __syncthreads();
    for (int s = 128; s > 0; s >>= 1) { if (t < s) red[t] += red[t + s]; __syncthreads(); }
    float var = red[0] * (1.0f / 512.0f);
    float inv = rsqrtf(var + 1e-5f);

    xr[t]       = d0 * inv * g[t]       + b[t];
    xr[t + 256] = d1 * inv * g[t + 256] + b[t + 256];
}

// ---------------------------------------------------------------------------
// V = raw * sigmoid(F . W_ig + b_ig)
// ---------------------------------------------------------------------------
__global__ void vgate_kernel(const float* __restrict__ F, const float* __restrict__ raw,
                             const float* __restrict__ Wig, const float* __restrict__ big,
                             float* __restrict__ V)
{
    int row = blockIdx.x;
    int t   = threadIdx.x;
    const float* fr = F + (size_t)row * DD;
    __shared__ float red[256];
    float s = fr[t] * Wig[t] + fr[t + 256] * Wig[t + 256];
    red[t] = s; __syncthreads();
    for (int k = 128; k > 0; k >>= 1) { if (t < k) red[t] += red[t + k]; __syncthreads(); }
    float gte = 1.0f / (1.0f + expf(-(red[0] + big[0])));
    const float* rr = raw + (size_t)row * DD;
    float* vr = V + (size_t)row * DD;
    vr[t]       = rr[t]       * gte;
    vr[t + 256] = rr[t + 256] * gte;
}

// ---------------------------------------------------------------------------
// SELA[b] = A1S[lookup_ids[b]]
// ---------------------------------------------------------------------------
__global__ void gather_kernel(float* __restrict__ dst, const float* __restrict__ src,
                              const int* __restrict__ ids)
{
    int idx = blockIdx.x * 256 + threadIdx.x;
    int b   = idx >> 15;
    int rem = idx & 32767;
    dst[idx] = src[(size_t)ids[b] * 32768 + rem];
}

// ---------------------------------------------------------------------------
// Final gate + output
// ---------------------------------------------------------------------------
__global__ void out_kernel(const float* __restrict__ FU, const float* __restrict__ A2,
                           const float* __restrict__ PD,
                           const float* __restrict__ Wu1, const float* __restrict__ bu1,
                           const float* __restrict__ Wu2, const float* __restrict__ bu2,
                           const float* __restrict__ b1,
                           float* __restrict__ out, float* __restrict__ gate)
{
    int row = blockIdx.x;
    int t   = threadIdx.x;
    const float* fu = FU + (size_t)row * DD;
    const float* a2 = A2 + (size_t)row * DD;
    const float* pd = PD + (size_t)row * DD;

    __shared__ float red[256];
    float s = fu[t] * Wu1[t] + fu[t + 256] * Wu1[t + 256]
            + a2[t] * Wu2[t] + a2[t + 256] * Wu2[t + 256];
    red[t] = s; __syncthreads();
    for (int k = 128; k > 0; k >>= 1) { if (t < k) red[t] += red[t + k]; __syncthreads(); }
    float z = red[0] + bu1[0] + bu2[0] + b1[0] - 4.0f;
    float g = 1.0f / (1.0f + expf(-z));

    float* orow = out + (size_t)row * DD;
    orow[t]       = pd[t]       * (1.0f - g) + a2[t]       * g;
    orow[t + 256] = pd[t + 256] * (1.0f - g) + a2[t + 256] * g;
    if (t == 0) gate[row] = g;
}

// ---------------------------------------------------------------------------
// Host orchestration
// ---------------------------------------------------------------------------
// WT layout per encoder: [0..6) Wqkv (l*3+j), [6..8) Wo, [8..12) Wff (l*2+j)
static void run_encoder(float* X, int nb, const float* pos, int posmode,
                        const float* WT,
                        const float* bqkv, const float* bo,
                        const float* ln, const float* bff,
                        float* bQ, float* bK, float* bV, float* bS, float* bVT)
{
    const int rows = nb * SS;
    const float sc = 1.0f / sqrtf((float)DD);
    for (int l = 0; l < 2; l++) {
        const float* bl = bqkv + (size_t)l * 3 * DD;
        tgemm_launch(X, WT + (size_t)(l * 3 + 0) * 262144, bl + 0,    bQ, rows, DD, DD, 1, 0, 0, 0, 1.0f, 0);
        tgemm_launch(X, WT + (size_t)(l * 3 + 1) * 262144, bl + 512,  bK, rows, DD, DD, 1, 0, 0, 0, 1.0f, 0);
        tgemm_launch(X, WT + (size_t)(l * 3 + 2) * 262144, bl + 1024, bV, rows, DD, DD, 1, 0, 0, 0, 1.0f, 0);
        rope_kernel<<<rows, 256>>>(bQ);
        rope_kernel<<<rows, 256>>>(bK);
        // scores[b] = Q[b] @ K[b]^T * sc   (K buffer already [S,D] = [N,K])
        tgemm_launch(bQ, bK, nullptr, bS, SS, SS, DD, nb, 524288, 524288, 1048576, sc, 0);
        softmax_kernel<<<rows, 256>>>(bS, pos, SS, SS, posmode);
        // transpose V per batch: [S,D] -> [D,S]
        transpose_kernel<<<dim3(DD / 32, SS / 32, nb), dim3(32, 8)>>>(bV, bVT, SS, DD, 524288, 524288);
        // T = A @ V  -> bQ
        tgemm_launch(bS, bVT, nullptr, bQ, SS, DD, SS, nb, 1048576, 524288, 524288, 1.0f, 0);
        // O = T @ Wo + bo -> bK
        tgemm_launch(bQ, WT + (size_t)(6 + l) * 262144, bo + l * 512, bK, rows, DD, DD, 1, 0, 0, 0, 1.0f, 0);
        ln_kernel<<<rows, 256>>>(X, bK, ln + l * 2048, ln + l * 2048 + 512);
        // H = gelu(X @ Wff0 + bff0) -> bQ
        tgemm_launch(X, WT + (size_t)(8 + l * 2) * 262144, bff + l * 1024, bQ, rows, DD, DD, 1, 0, 0, 0, 1.0f, 1);
        // F = H @ Wff1 + bff1 -> bK
        tgemm_launch(bQ, WT + (size_t)(8 + l * 2 + 1) * 262144, bff + l * 1024 + 512, bK,
                     rows, DD, DD, 1, 0, 0, 0, 1.0f, 0);
        ln_kernel<<<rows, 256>>>(X, bK, ln + l * 2048 + 1024, ln + l * 2048 + 1536);
    }
}

extern "C" void kernel_launch(void* const* d_in, const int* in_sizes, int n_in,
                              void* d_out, int out_size)
{
    const float* raw_emb   = (const float*)d_in[0];
    const float* pos_w     = (const float*)d_in[1];
    const float* post_dec  = (const float*)d_in[2];
    const float* pos_r     = (const float*)d_in[3];
    const float* questions = (const float*)d_in[4];
    const float* W_k       = (const float*)d_in[5];
    const float* W_ig      = (const float*)d_in[6];
    const float* b_ig      = (const float*)d_in[7];
    const float* W_u1      = (const float*)d_in[8];
    const float* b_u1      = (const float*)d_in[9];
    const float* W_u2      = (const float*)d_in[10];
    const float* b_u2      = (const float*)d_in[11];
    const float* b1        = (const float*)d_in[12];
    const float* W_ok      = (const float*)d_in[13];
    const float* b_ok      = (const float*)d_in[14];
    const float* encw_Wqkv = (const float*)d_in[15];
    const float* encw_bqkv = (const float*)d_in[16];
    const float* encw_Wo   = (const float*)d_in[17];
    const float* encw_bo   = (const float*)d_in[18];
    const float* encw_ln   = (const float*)d_in[19];
    const float* encw_Wff  = (const float*)d_in[20];
    const float* encw_bff  = (const float*)d_in[21];
    const float* encr_Wqkv = (const float*)d_in[22];
    const float* encr_bqkv = (const float*)d_in[23];
    const float* encr_Wo   = (const float*)d_in[24];
    const float* encr_bo   = (const float*)d_in[25];
    const float* encr_ln   = (const float*)d_in[26];
    const float* encr_Wff  = (const float*)d_in[27];
    const float* encr_bff  = (const float*)d_in[28];
    const int*   lookup    = (const int*)d_in[29];

    float* out  = (float*)d_out;
    float* gate = out + (size_t)NBB * SS * DD;

    float *pX, *pQ, *pK, *pV, *pS, *pKd, *pVd, *pA1, *pSel, *pSelT, *pK2, *pA2s, *pA2;
    float *pVT, *pWTw, *pWTr, *pWkT, *pWokT;
    cudaGetSymbolAddress((void**)&pX,    g_X);
    cudaGetSymbolAddress((void**)&pQ,    g_Qb);
    cudaGetSymbolAddress((void**)&pK,    g_Kb);
    cudaGetSymbolAddress((void**)&pV,    g_Vb);
    cudaGetSymbolAddress((void**)&pS,    g_S);
    cudaGetSymbolAddress((void**)&pKd,   g_Kdoc);
    cudaGetSymbolAddress((void**)&pVd,   g_Vdoc);
    cudaGetSymbolAddress((void**)&pA1,   g_A1S);
    cudaGetSymbolAddress((void**)&pSel,  g_SELA);
    cudaGetSymbolAddress((void**)&pSelT, g_SELAT);
    cudaGetSymbolAddress((void**)&pK2,   g_K2);
    cudaGetSymbolAddress((void**)&pA2s,  g_A2SC);
    cudaGetSymbolAddress((void**)&pA2,   g_A2);
    cudaGetSymbolAddress((void**)&pVT,   g_VT);
    cudaGetSymbolAddress((void**)&pWTw,  g_WTw);
    cudaGetSymbolAddress((void**)&pWTr,  g_WTr);
    cudaGetSymbolAddress((void**)&pWkT,  g_WkT);
    cudaGetSymbolAddress((void**)&pWokT, g_WokT);

    cudaFuncSetAttribute(tgemm_kernel, cudaFuncAttributeMaxDynamicSharedMemorySize, TG_SMEM);

    const float scD = 1.0f / sqrtf((float)DD);

    rope_table_kernel<<<1024, 256>>>();

    // ---- pre-transpose all weight matrices (N-major for warp-MMA GEMM) ----
    transpose_kernel<<<dim3(16, 16, 6), dim3(32, 8)>>>(encw_Wqkv, pWTw,                 512, 512, 262144, 262144);
    transpose_kernel<<<dim3(16, 16, 2), dim3(32, 8)>>>(encw_Wo,   pWTw + 6  * 262144,   512, 512, 262144, 262144);
    transpose_kernel<<<dim3(16, 16, 4), dim3(32, 8)>>>(encw_Wff,  pWTw + 8  * 262144,   512, 512, 262144, 262144);
    transpose_kernel<<<dim3(16, 16, 6), dim3(32, 8)>>>(encr_Wqkv, pWTr,                 512, 512, 262144, 262144);
    transpose_kernel<<<dim3(16, 16, 2), dim3(32, 8)>>>(encr_Wo,   pWTr + 6  * 262144,   512, 512, 262144, 262144);
    transpose_kernel<<<dim3(16, 16, 4), dim3(32, 8)>>>(encr_Wff,  pWTr + 8  * 262144,   512, 512, 262144, 262144);
    transpose_kernel<<<dim3(16, 16, 1), dim3(32, 8)>>>(W_k,  pWkT,  512, 512, 0, 0);
    transpose_kernel<<<dim3(16, 16, 1), dim3(32, 8)>>>(W_ok, pWokT, 512, 512, 0, 0);

    // ---- write-side encoder on raw_emb (8 docs) ----
    cudaMemcpyAsync(pX, raw_emb, (size_t)NDOC * SS * DD * sizeof(float),
                    cudaMemcpyDeviceToDevice, 0);
    run_encoder(pX, NDOC, pos_w, /*log*/1,
                pWTw, encw_bqkv, encw_bo, encw_ln, encw_bff,
                pQ, pK, pV, pS, pVT);

    vgate_kernel<<<NDOC * SS, 256>>>(pX, raw_emb, W_ig, b_ig, pVd);
    tgemm_launch(raw_emb, pWkT, nullptr, pKd, NDOC * SS, DD, DD, 1, 0, 0, 0, 1.0f, 0);
    // S1[n] = questions @ k[n]^T * scD  (M=64 -> SIMT)
    sgemm_launch(questions, pKd, nullptr, pS, QQ, SS, DD, NDOC, 0, 524288, 65536, scD, 1, 0);
    softmax_kernel<<<NDOC * QQ, 256>>>(pS, pos_w, SS, QQ, 1);
    // A1S[n] = S1[n] @ v[n]  (M=64 -> SIMT, transB=0)
    sgemm_launch(pS, pVd, nullptr, pA1, QQ, DD, SS, NDOC, 65536, 524288, 32768, 1.0f, 0, 0);

    // ---- read-side encoder on post_dec (16 batches) ----
    cudaMemcpyAsync(pX, post_dec, (size_t)NBB * SS * DD * sizeof(float),
                    cudaMemcpyDeviceToDevice, 0);
    run_encoder(pX, NBB, pos_r, /*logit*/2,
                pWTr, encr_bqkv, encr_bo, encr_ln, encr_bff,
                pQ, pK, pV, pS, pVT);

    tgemm_launch(post_dec, pWokT, b_ok, pK2, NBB * SS, DD, DD, 1, 0, 0, 0, 1.0f, 0);
    // a2 = softmax(k2 @ questions^T / 8)  (N=64 -> SIMT)
    sgemm_launch(pK2, questions, nullptr, pA2s, NBB * SS, QQ, DD, 1, 0, 0, 0, 0.125f, 1, 0);
    softmax_kernel<<<NBB * SS, 256>>>(pA2s, nullptr, QQ, 1, 0);
    gather_kernel<<<(NBB * QQ * DD) / 256, 256>>>(pSel, pA1, lookup);
    // selA^T per batch: [64,512] -> [512,64]
    transpose_kernel<<<dim3(16, 2, 16), dim3(32, 8)>>>(pSel, pSelT, 64, 512, 32768, 32768);
    // A2[b] = a2[b] @ selA[b]
    tgemm_launch(pA2s, pSelT, nullptr, pA2, SS, DD, QQ, NBB, 65536, 32768, 524288, 1.0f, 0);

    out_kernel<<<NBB * SS, 256>>>(pX, pA2, post_dec,
                                  W_u1, b_u1, W_u2, b_u2, b1,
                                  out, gate);

    (void)in_sizes; (void)n_in; (void)out_size;
}

// round 5
// speedup vs baseline: 1.8890x; 1.1583x over previous
#include <cuda_runtime.h>
#include <cuda_bf16.h>
#include <math.h>
#include <stdint.h>

// ---------------------------------------------------------------------------
// Problem constants
// ---------------------------------------------------------------------------
#define DD     512
#define SS     1024
#define NBB    16
#define QQ     64
#define NDOC   8

// ---------------------------------------------------------------------------
// f32 scratch
// ---------------------------------------------------------------------------
__device__ float g_X   [16384 * 512];
__device__ float g_Qb  [16384 * 512];
__device__ float g_Kb  [16384 * 512];
__device__ float g_Vb  [16384 * 512];
__device__ float g_S   [16 * 1024 * 1024];
__device__ float g_Kdoc[8192 * 512];
__device__ float g_Vdoc[8192 * 512];
__device__ float g_A1S [8 * 64 * 512];
__device__ float g_K2  [16384 * 512];
__device__ float g_A2SC[16384 * 64];
__device__ float g_A2  [16384 * 512];
__device__ float g_sin [1024 * 256];
__device__ float g_cos [1024 * 256];
__device__ float g_BIASW[8 * 1024];
__device__ float g_BIASR[16 * 1024];

// ---------------------------------------------------------------------------
// bf16 hi/lo plane buffers (hi block then lo block; lo at +capacity offset)
// ---------------------------------------------------------------------------
__device__ __align__(16) __nv_bfloat16 g_PW  [26 * 524288];   // 26 transposed weights
__device__ __align__(16) __nv_bfloat16 g_Praw[2 * 4194304];
__device__ __align__(16) __nv_bfloat16 g_Ppd [2 * 8388608];
__device__ __align__(16) __nv_bfloat16 g_Px  [2 * 8388608];
__device__ __align__(16) __nv_bfloat16 g_Pq  [2 * 8388608];
__device__ __align__(16) __nv_bfloat16 g_Pk  [2 * 8388608];
__device__ __align__(16) __nv_bfloat16 g_Pvt [2 * 8388608];
__device__ __align__(16) __nv_bfloat16 g_Pp  [2 * 16777216];
__device__ __align__(16) __nv_bfloat16 g_Pbq [2 * 8388608];
__device__ __align__(16) __nv_bfloat16 g_Ph  [2 * 8388608];
__device__ __align__(16) __nv_bfloat16 g_Pa2 [2 * 1048576];
__device__ __align__(16) __nv_bfloat16 g_Psel[2 * 524288];

// ---------------------------------------------------------------------------
// Helpers
// ---------------------------------------------------------------------------
__device__ __forceinline__ uint32_t smem_u32(const void* p) {
    uint32_t a;
    asm("{ .reg .u64 t; cvta.to.shared.u64 t, %1; cvt.u32.u64 %0, t; }"
        : "=r"(a) : "l"(p));
    return a;
}

__device__ __forceinline__ void ldsm4(uint32_t* r, uint32_t addr) {
    asm volatile("ldmatrix.sync.aligned.m8n8.x4.shared.b16 {%0,%1,%2,%3}, [%4];"
                 : "=r"(r[0]), "=r"(r[1]), "=r"(r[2]), "=r"(r[3]) : "r"(addr));
}

__device__ __forceinline__ void mma_bf16(float* c, const uint32_t* a,
                                         uint32_t b0, uint32_t b1) {
    asm volatile(
        "mma.sync.aligned.m16n8k16.row.col.f32.bf16.bf16.f32 "
        "{%0,%1,%2,%3}, {%4,%5,%6,%7}, {%8,%9}, {%0,%1,%2,%3};"
        : "+f"(c[0]), "+f"(c[1]), "+f"(c[2]), "+f"(c[3])
        : "r"(a[0]), "r"(a[1]), "r"(a[2]), "r"(a[3]), "r"(b0), "r"(b1));
}

__device__ __forceinline__ void cpasync16(uint32_t dst, const void* src) {
    asm volatile("cp.async.cg.shared.global [%0], [%1], 16;" :: "r"(dst), "l"(src));
}
#define CP_COMMIT() asm volatile("cp.async.commit_group;" ::: "memory")
#define CP_WAIT(n)  asm volatile("cp.async.wait_group %0;" :: "n"(n) : "memory")

__device__ __forceinline__ void split_pair(float x0, float x1,
                                           __nv_bfloat162& h, __nv_bfloat162& l) {
    h = __floats2bfloat162_rn(x0, x1);
    l = __floats2bfloat162_rn(x0 - __bfloat162float(h.x),
                              x1 - __bfloat162float(h.y));
}

// ---------------------------------------------------------------------------
// Plane GEMM: C[M,N] = alpha * (Ah+Al)[M,K] @ (Bh+Bl)[N,K]^T + bias  (3-MMA split)
// smem: 3 stages x 4 planes x (128 rows x 32 bf16, stride 80B) = 122880B
// ---------------------------------------------------------------------------
#define PLANE 10240
#define TSTAGE 40960
#define TG2_SMEM (3 * 40960)

__global__ void __launch_bounds__(256)
tgemm2(const __nv_bfloat16* __restrict__ Ah0,
       const __nv_bfloat16* __restrict__ Bh0,
       const float* __restrict__ bias, float* __restrict__ Cf,
       __nv_bfloat16* __restrict__ Ch0,
       int M, int N, int K,
       long long loA, long long loB, long long loC,
       long long sA, long long sB, long long sC, long long sCp,
       float alpha, int epi)
{
    extern __shared__ char smem[];
    const uint32_t sbu = smem_u32(smem);
    const int t = threadIdx.x, w = t >> 5, lane = t & 31;
    const int wm = w & 3, wn = w >> 2;
    const int z = blockIdx.z;
    const int m0 = blockIdx.y * 128, n0 = blockIdx.x * 128;

    const __nv_bfloat16* Ah = Ah0 + (size_t)z * sA;
    const __nv_bfloat16* Bh = Bh0 + (size_t)z * sB;

    const int lrow = t >> 1, hf = t & 1;
    const __nv_bfloat16* pr[4];
    pr[0] = Ah + (size_t)(m0 + lrow) * K;
    pr[1] = pr[0] + loA;
    pr[2] = Bh + (size_t)(n0 + lrow) * K;
    pr[3] = pr[2] + loB;

    float acc[2][8][4];
#pragma unroll
    for (int i = 0; i < 2; i++)
#pragma unroll
        for (int j = 0; j < 8; j++)
#pragma unroll
            for (int e = 0; e < 4; e++) acc[i][j][e] = 0.0f;

    const int nch = K >> 5;
    const uint32_t sdbase = sbu + (uint32_t)(lrow * 80);

#define ISSUE(ch) do {                                                      \
    uint32_t _sd = sdbase + (uint32_t)((ch) % 3) * TSTAGE;                  \
    const int _cb = (ch) * 32;                                              \
    _Pragma("unroll")                                                       \
    for (int _p = 0; _p < 4; _p++) {                                        \
        _Pragma("unroll")                                                   \
        for (int _j = 0; _j < 2; _j++) {                                    \
            int _c16 = hf * 2 + _j;                                         \
            cpasync16(_sd + _p * PLANE + _c16 * 16, pr[_p] + _cb + _c16 * 8); \
        }                                                                   \
    }                                                                       \
    CP_COMMIT();                                                            \
} while (0)

    ISSUE(0);
    ISSUE(1);

    const uint32_t lmoff = (uint32_t)((lane & 15) * 80 + (lane >> 4) * 16);

    for (int ch = 0; ch < nch; ch++) {
        if (ch + 1 < nch) { CP_WAIT(1); } else { CP_WAIT(0); }
        __syncthreads();
        if (ch + 2 < nch) ISSUE(ch + 2);

        const uint32_t sAh = sbu + (uint32_t)(ch % 3) * TSTAGE;
        const uint32_t sBh = sAh + 2 * PLANE;
#pragma unroll
        for (int kk = 0; kk < 2; kk++) {
            uint32_t ah[2][4], al[2][4];
#pragma unroll
            for (int mt = 0; mt < 2; mt++) {
                uint32_t aaddr = sAh + (uint32_t)((wm * 32 + mt * 16) * 80 + kk * 32) + lmoff;
                ldsm4(ah[mt], aaddr);
                ldsm4(al[mt], aaddr + PLANE);
            }
#pragma unroll
            for (int ng = 0; ng < 4; ng++) {
                uint32_t bh[4], bl[4];
                uint32_t baddr = sBh + (uint32_t)((wn * 64 + ng * 16) * 80 + kk * 32) + lmoff;
                ldsm4(bh, baddr);
                ldsm4(bl, baddr + PLANE);
#pragma unroll
                for (int mt = 0; mt < 2; mt++) {
#pragma unroll
                    for (int h2 = 0; h2 < 2; h2++) {
                        float* c = acc[mt][ng * 2 + h2];
                        mma_bf16(c, ah[mt], bh[h2], bh[h2 + 2]);
                        mma_bf16(c, ah[mt], bl[h2], bl[h2 + 2]);
                        mma_bf16(c, al[mt], bh[h2], bh[h2 + 2]);
                    }
                }
            }
        }
    }
#undef ISSUE

    // ---- epilogue ----
    const float GC = 0.7978845608028654f;
    const int crow = m0 + wm * 32 + (lane >> 2);
    const int ccol = n0 + wn * 64 + (lane & 3) * 2;
    float* Cfz = Cf + (size_t)z * sC;
    __nv_bfloat16* Chz = Ch0 ? Ch0 + (size_t)z * sCp : (__nv_bfloat16*)0;
    __nv_bfloat16* Clz = Chz ? Chz + loC : (__nv_bfloat16*)0;
#pragma unroll
    for (int mt = 0; mt < 2; mt++) {
#pragma unroll
        for (int n8 = 0; n8 < 8; n8++) {
            const float* c = acc[mt][n8];
            const int col = ccol + n8 * 8;
            float b0 = bias ? bias[col]     : 0.0f;
            float b1 = bias ? bias[col + 1] : 0.0f;
#pragma unroll
            for (int h = 0; h < 2; h++) {
                const int row = crow + mt * 16 + h * 8;
                float x0 = c[h * 2 + 0] * alpha + b0;
                float x1 = c[h * 2 + 1] * alpha + b1;
                if (epi) {
                    x0 = 0.5f * x0 * (1.0f + tanhf(GC * (x0 + 0.044715f * x0 * x0 * x0)));
                    x1 = 0.5f * x1 * (1.0f + tanhf(GC * (x1 + 0.044715f * x1 * x1 * x1)));
                }
                *(float2*)&Cfz[(size_t)row * N + col] = make_float2(x0, x1);
                if (Chz) {
                    __nv_bfloat162 hh, ll;
                    split_pair(x0, x1, hh, ll);
                    *(__nv_bfloat162*)&Chz[(size_t)row * N + col] = hh;
                    *(__nv_bfloat162*)&Clz[(size_t)row * N + col] = ll;
                }
            }
        }
    }
}

static void tg2(const __nv_bfloat16* Ah, long long loA, long long sA,
                const __nv_bfloat16* Bh, long long loB, long long sB,
                const float* bias, float* Cf, long long sC,
                __nv_bfloat16* Ch, long long loC, long long sCp,
                int M, int N, int K, int batch, float alpha, int epi)
{
    dim3 grid(N / 128, M / 128, batch);
    tgemm2<<<grid, 256, TG2_SMEM>>>(Ah, Bh, bias, Cf, Ch, M, N, K,
                                    loA, loB, loC, sA, sB, sC, sCp, alpha, epi);
}

// ---------------------------------------------------------------------------
// Transpose + convert to planes: out[c][r] planes from in[r][c]
// ---------------------------------------------------------------------------
__global__ void trans_conv(const float* __restrict__ in, __nv_bfloat16* __restrict__ oh,
                           long long loOff, int R, int C,
                           long long sI, long long sO, const int* __restrict__ ids)
{
    __shared__ float tile[32][33];
    const int z = blockIdx.z;
    size_t ib = ids ? (size_t)ids[z] * sI : (size_t)z * sI;
    const float* ip = in + ib;
    __nv_bfloat16* ohz = oh + (size_t)z * sO;
    __nv_bfloat16* olz = ohz + loOff;
    const int c0 = blockIdx.x * 32, r0 = blockIdx.y * 32;
    const int tx = threadIdx.x, ty = threadIdx.y;
#pragma unroll
    for (int k = 0; k < 32; k += 8)
        tile[ty + k][tx] = ip[(size_t)(r0 + ty + k) * C + c0 + tx];
    __syncthreads();
    const int rr = (tx & 15) * 2, chf = tx >> 4;
#pragma unroll
    for (int k = 0; k < 2; k++) {
        int cc = ty + chf * 8 + k * 16;
        __nv_bfloat162 h, l;
        split_pair(tile[rr][cc], tile[rr + 1][cc], h, l);
        *(__nv_bfloat162*)&ohz[(size_t)(c0 + cc) * R + r0 + rr] = h;
        *(__nv_bfloat162*)&olz[(size_t)(c0 + cc) * R + r0 + rr] = l;
    }
}

// ---------------------------------------------------------------------------
// Convert rows (512 cols) to planes
// ---------------------------------------------------------------------------
__global__ void conv_planes(const float* __restrict__ in, __nv_bfloat16* __restrict__ oh,
                            long long lo)
{
    size_t idx = (size_t)blockIdx.x * 512 + (size_t)threadIdx.x * 2;
    float2 v = *(const float2*)&in[idx];
    __nv_bfloat162 h, l;
    split_pair(v.x, v.y, h, l);
    *(__nv_bfloat162*)&oh[idx] = h;
    *(__nv_bfloat162*)&(oh + lo)[idx] = l;
}

// ---------------------------------------------------------------------------
// RoPE table + rope->planes
// ---------------------------------------------------------------------------
__global__ void rope_table_kernel()
{
    int s = blockIdx.x;
    int i = threadIdx.x;
    float invf = 1.0f / powf(10000.0f, (float)i / 256.0f);
    float angf = (float)s * invf;
    double ang = (double)angf;
    g_sin[s * 256 + i] = (float)sin(ang);
    g_cos[s * 256 + i] = (float)cos(ang);
}

__global__ void rope_planes(const float* __restrict__ X, __nv_bfloat16* __restrict__ oh,
                            long long lo)
{
    int row = blockIdx.x, i = threadIdx.x;
    int s = row & (SS - 1);
    float sn = g_sin[s * 256 + i];
    float cs = g_cos[s * 256 + i];
    const float* xr = X + (size_t)row * DD;
    float x1 = xr[2 * i], x2 = xr[2 * i + 1];
    float y0 = x1 * cs - x2 * sn;
    float y1 = x1 * sn + x2 * cs;
    __nv_bfloat162 h, l;
    split_pair(y0, y1, h, l);
    size_t o = (size_t)row * DD + 2 * i;
    *(__nv_bfloat162*)&oh[o] = h;
    *(__nv_bfloat162*)&(oh + lo)[o] = l;
}

// ---------------------------------------------------------------------------
// Positional bias precompute: mode 1 = log(p), 2 = logit(p)
// ---------------------------------------------------------------------------
__global__ void bias_prep(const float* __restrict__ pos, float* __restrict__ out, int mode)
{
    int n = blockIdx.x, t = threadIdx.x;
    for (int c = t; c < 1024; c += 256) {
        float p = pos[n * 1024 + c];
        out[n * 1024 + c] = (mode == 1) ? logf(p) : (logf(p) - log1pf(-p));
    }
}

// ---------------------------------------------------------------------------
// Softmax over 1024 cols, bias row added, emits planes. Single pass in regs.
// ---------------------------------------------------------------------------
__global__ void softmax1024_planes(const float* __restrict__ S, const float* __restrict__ bias,
                                   __nv_bfloat16* __restrict__ oh, long long lo)
{
    const int row = blockIdx.x, t = threadIdx.x;
    const float* sr = S + (size_t)row * 1024;
    const float* pb = bias + (size_t)(row >> 10) * 1024;
    float2 a  = *(const float2*)&sr[2 * t];
    float2 b2 = *(const float2*)&sr[512 + 2 * t];
    float2 ba = *(const float2*)&pb[2 * t];
    float2 bb = *(const float2*)&pb[512 + 2 * t];
    float v0 = a.x + ba.x, v1 = a.y + ba.y, v2 = b2.x + bb.x, v3 = b2.y + bb.y;

    __shared__ float red[256];
    float mx = fmaxf(fmaxf(v0, v1), fmaxf(v2, v3));
    red[t] = mx; __syncthreads();
    for (int s = 128; s > 0; s >>= 1) { if (t < s) red[t] = fmaxf(red[t], red[t + s]); __syncthreads(); }
    mx = red[0]; __syncthreads();

    float e0 = expf(v0 - mx), e1 = expf(v1 - mx), e2 = expf(v2 - mx), e3 = expf(v3 - mx);
    red[t] = e0 + e1 + e2 + e3; __syncthreads();
    for (int s = 128; s > 0; s >>= 1) { if (t < s) red[t] += red[t + s]; __syncthreads(); }
    float inv = 1.0f / red[0];

    __nv_bfloat162 h, l;
    size_t o = (size_t)row * 1024 + 2 * t;
    split_pair(e0 * inv, e1 * inv, h, l);
    *(__nv_bfloat162*)&oh[o] = h;
    *(__nv_bfloat162*)&(oh + lo)[o] = l;
    split_pair(e2 * inv, e3 * inv, h, l);
    *(__nv_bfloat162*)&oh[o + 512] = h;
    *(__nv_bfloat162*)&(oh + lo)[o + 512] = l;
}

// ---------------------------------------------------------------------------
// Softmax over 64 cols, warp per row, emits planes.
// ---------------------------------------------------------------------------
__global__ void softmax64_planes(const float* __restrict__ S, __nv_bfloat16* __restrict__ oh,
                                 long long lo)
{
    const int row = blockIdx.x * 8 + (threadIdx.x >> 5);
    const int lane = threadIdx.x & 31;
    const float* sr = S + (size_t)row * 64;
    float2 v = *(const float2*)&sr[lane * 2];
    float mx = fmaxf(v.x, v.y);
#pragma unroll
    for (int o = 16; o > 0; o >>= 1)
        mx = fmaxf(mx, __shfl_xor_sync(0xFFFFFFFF, mx, o));
    float e0 = expf(v.x - mx), e1 = expf(v.y - mx);
    float s = e0 + e1;
#pragma unroll
    for (int o = 16; o > 0; o >>= 1)
        s += __shfl_xor_sync(0xFFFFFFFF, s, o);
    float inv = 1.0f / s;
    __nv_bfloat162 h, l;
    split_pair(e0 * inv, e1 * inv, h, l);
    size_t o2 = (size_t)row * 64 + lane * 2;
    *(__nv_bfloat162*)&oh[o2] = h;
    *(__nv_bfloat162*)&(oh + lo)[o2] = l;
}

// ---------------------------------------------------------------------------
// Softmax f32 (S1 path): bias rows precomputed
// ---------------------------------------------------------------------------
__global__ void softmax_f32(float* __restrict__ S, const float* __restrict__ bias,
                            int cols, int rpb)
{
    int row = blockIdx.x;
    float* sr = S + (size_t)row * cols;
    const float* pb = bias + (size_t)(row / rpb) * cols;
    int t = threadIdx.x;
    __shared__ float red[256];

    float mx = -1e30f;
    for (int c = t; c < cols; c += 256) {
        float v = sr[c] + pb[c];
        sr[c] = v;
        mx = fmaxf(mx, v);
    }
    red[t] = mx; __syncthreads();
    for (int s = 128; s > 0; s >>= 1) { if (t < s) red[t] = fmaxf(red[t], red[t + s]); __syncthreads(); }
    mx = red[0]; __syncthreads();

    float sum = 0.0f;
    for (int c = t; c < cols; c += 256) {
        float e = expf(sr[c] - mx);
        sr[c] = e;
        sum += e;
    }
    red[t] = sum; __syncthreads();
    for (int s = 128; s > 0; s >>= 1) { if (t < s) red[t] += red[t + s]; __syncthreads(); }
    float inv = 1.0f / red[0];
    for (int c = t; c < cols; c += 256) sr[c] *= inv;
}

// ---------------------------------------------------------------------------
// X = LayerNorm(X + R) * g + b  ; emits X f32 and X planes
// ---------------------------------------------------------------------------
__global__ void ln_kernel(float* __restrict__ X, const float* __restrict__ R,
                          const float* __restrict__ g, const float* __restrict__ b,
                          __nv_bfloat16* __restrict__ oh, long long lo)
{
    int row = blockIdx.x;
    int t   = threadIdx.x;
    float* xr = X + (size_t)row * DD;
    const float* rr = R + (size_t)row * DD;

    float v0 = xr[2 * t] + rr[2 * t];
    float v1 = xr[2 * t + 1] + rr[2 * t + 1];

    __shared__ float red[256];
    red[t] = v0 + v1; __syncthreads();
    for (int s = 128; s > 0; s >>= 1) { if (t < s) red[t] += red[t + s]; __syncthreads(); }
    float m = red[0] * (1.0f / 512.0f);
    __syncthreads();

    float d0 = v0 - m, d1 = v1 - m;
    red[t] = d0 * d0 + d1 * d1; __syncthreads();
    for (int s = 128; s > 0; s >>= 1) { if (t < s) red[t] += red[t + s]; __syncthreads(); }
    float var = red[0] * (1.0f / 512.0f);
    float inv = rsqrtf(var + 1e-5f);

    float o0 = d0 * inv * g[2 * t]     + b[2 * t];
    float o1 = d1 * inv * g[2 * t + 1] + b[2 * t + 1];
    xr[2 * t]     = o0;
    xr[2 * t + 1] = o1;

    __nv_bfloat162 h, l;
    split_pair(o0, o1, h, l);
    size_t o = (size_t)row * DD + 2 * t;
    *(__nv_bfloat162*)&oh[o] = h;
    *(__nv_bfloat162*)&(oh + lo)[o] = l;
}

// ---------------------------------------------------------------------------
// V = raw * sigmoid(F . W_ig + b_ig)
// ---------------------------------------------------------------------------
__global__ void vgate_kernel(const float* __restrict__ F, const float* __restrict__ raw,
                             const float* __restrict__ Wig, const float* __restrict__ big,
                             float* __restrict__ V)
{
    int row = blockIdx.x;
    int t   = threadIdx.x;
    const float* fr = F + (size_t)row * DD;
    __shared__ float red[256];
    float s = fr[t] * Wig[t] + fr[t + 256] * Wig[t + 256];
    red[t] = s; __syncthreads();
    for (int k = 128; k > 0; k >>= 1) { if (t < k) red[t] += red[t + k]; __syncthreads(); }
    float gte = 1.0f / (1.0f + expf(-(red[0] + big[0])));
    const float* rr = raw + (size_t)row * DD;
    float* vr = V + (size_t)row * DD;
    vr[t]       = rr[t]       * gte;
    vr[t + 256] = rr[t + 256] * gte;
}

// ---------------------------------------------------------------------------
// Final gate + output
// ---------------------------------------------------------------------------
__global__ void out_kernel(const float* __restrict__ FU, const float* __restrict__ A2,
                           const float* __restrict__ PD,
                           const float* __restrict__ Wu1, const float* __restrict__ bu1,
                           const float* __restrict__ Wu2, const float* __restrict__ bu2,
                           const float* __restrict__ b1,
                           float* __restrict__ out, float* __restrict__ gate)
{
    int row = blockIdx.x;
    int t   = threadIdx.x;
    const float* fu = FU + (size_t)row * DD;
    const float* a2 = A2 + (size_t)row * DD;
    const float* pd = PD + (size_t)row * DD;

    __shared__ float red[256];
    float s = fu[t] * Wu1[t] + fu[t + 256] * Wu1[t + 256]
            + a2[t] * Wu2[t] + a2[t + 256] * Wu2[t + 256];
    red[t] = s; __syncthreads();
    for (int k = 128; k > 0; k >>= 1) { if (t < k) red[t] += red[t + k]; __syncthreads(); }
    float z = red[0] + bu1[0] + bu2[0] + b1[0] - 4.0f;
    float g = 1.0f / (1.0f + expf(-z));

    float* orow = out + (size_t)row * DD;
    orow[t]       = pd[t]       * (1.0f - g) + a2[t]       * g;
    orow[t + 256] = pd[t + 256] * (1.0f - g) + a2[t + 256] * g;
    if (t == 0) gate[row] = g;
}

// ---------------------------------------------------------------------------
// SIMT fallback GEMM (64x64x16) for M=64 / N=64 shapes
// ---------------------------------------------------------------------------
#define BM 64
#define BN 64
#define BK 16

__global__ void gemm_kernel(const float* __restrict__ A,
                            const float* __restrict__ Bm,
                            const float* __restrict__ bias,
                            float* __restrict__ C,
                            int M, int N, int K,
                            long long sA, long long sB, long long sC,
                            float alpha, int transB, int epi)
{
    const int bz = blockIdx.z;
    A  += (size_t)bz * sA;
    Bm += (size_t)bz * sB;
    C  += (size_t)bz * sC;

    const int m0 = blockIdx.y * BM;
    const int n0 = blockIdx.x * BN;

    __shared__ float As[BK][BM + 4];
    __shared__ float Bs[BK][BN + 4];

    const int t  = threadIdx.x;
    const int tx = t & 15;
    const int ty = t >> 4;

    float acc[4][4] = {};

    const int arow = t >> 2;
    const int akc  = (t & 3) * 4;
    const int kb   = t >> 4;
    const int nb   = (t & 15) * 4;

    for (int k0 = 0; k0 < K; k0 += BK) {
        float4 av = *(const float4*)&A[(size_t)(m0 + arow) * K + k0 + akc];
        As[akc + 0][arow] = av.x;
        As[akc + 1][arow] = av.y;
        As[akc + 2][arow] = av.z;
        As[akc + 3][arow] = av.w;

        if (!transB) {
            float4 bv = *(const float4*)&Bm[(size_t)(k0 + kb) * N + n0 + nb];
            *(float4*)&Bs[kb][nb] = bv;
        } else {
            float4 bv = *(const float4*)&Bm[(size_t)(n0 + arow) * K + k0 + akc];
            Bs[akc + 0][arow] = bv.x;
            Bs[akc + 1][arow] = bv.y;
            Bs[akc + 2][arow] = bv.z;
            Bs[akc + 3][arow] = bv.w;
        }
        __syncthreads();

#pragma unroll
        for (int k = 0; k < BK; k++) {
            float4 a = *(const float4*)&As[k][ty * 4];
            float4 b = *(const float4*)&Bs[k][tx * 4];
            acc[0][0] += a.x * b.x; acc[0][1] += a.x * b.y;
            acc[0][2] += a.x * b.z; acc[0][3] += a.x * b.w;
            acc[1][0] += a.y * b.x; acc[1][1] += a.y * b.y;
            acc[1][2] += a.y * b.z; acc[1][3] += a.y * b.w;
            acc[2][0] += a.z * b.x; acc[2][1] += a.z * b.y;
            acc[2][2] += a.z * b.z; acc[2][3] += a.z * b.w;
            acc[3][0] += a.w * b.x; acc[3][1] += a.w * b.y;
            acc[3][2] += a.w * b.z; acc[3][3] += a.w * b.w;
        }
        __syncthreads();
    }

#pragma unroll
    for (int i = 0; i < 4; i++) {
        const int row = m0 + ty * 4 + i;
        float v[4];
#pragma unroll
        for (int j = 0; j < 4; j++) {
            float x = acc[i][j] * alpha;
            if (bias) x += bias[n0 + tx * 4 + j];
            v[j] = x;
        }
        *(float4*)&C[(size_t)row * N + n0 + tx * 4] = make_float4(v[0], v[1], v[2], v[3]);
    }
}

static void sgemm_launch(const float* A, const float* B, const float* bias, float* C,
                         int M, int N, int K, int batch,
                         long long sA, long long sB, long long sC,
                         float alpha, int transB)
{
    dim3 grid(N / BN, M / BM, batch);
    gemm_kernel<<<grid, 256>>>(A, B, bias, C, M, N, K, sA, sB, sC, alpha, transB, 0);
}

// ---------------------------------------------------------------------------
// Encoder
// PW layout (per encoder): [l*3+j] qkv, [6+l] Wo, [8+2l+j] ff
// ---------------------------------------------------------------------------
static void run_encoder(float* X, int nb,
                        const __nv_bfloat16* initP, long long initLo,
                        const float* biasRows,
                        const __nv_bfloat16* PW,
                        const float* bqkv, const float* bo,
                        const float* ln, const float* bff,
                        float* bQ, float* bK, float* bV, float* bS,
                        __nv_bfloat16* Pq, __nv_bfloat16* Pk, __nv_bfloat16* Pvt,
                        __nv_bfloat16* Pp, __nv_bfloat16* Pbq, __nv_bfloat16* Ph,
                        __nv_bfloat16* Px)
{
    const int rows = nb * SS;
    const float sc = 1.0f / sqrtf((float)DD);
    const long long LO = 8388608LL;
    for (int l = 0; l < 2; l++) {
        const __nv_bfloat16* AP = (l == 0) ? initP : Px;
        const long long loAP = (l == 0) ? initLo : LO;
        const float* bl = bqkv + (size_t)l * 3 * DD;
        tg2(AP, loAP, 0, PW + (size_t)(l * 3 + 0) * 524288, 262144, 0, bl,        bQ, 0, 0, 0, 0, rows, 512, 512, 1, 1.0f, 0);
        tg2(AP, loAP, 0, PW + (size_t)(l * 3 + 1) * 524288, 262144, 0, bl + 512,  bK, 0, 0, 0, 0, rows, 512, 512, 1, 1.0f, 0);
        tg2(AP, loAP, 0, PW + (size_t)(l * 3 + 2) * 524288, 262144, 0, bl + 1024, bV, 0, 0, 0, 0, rows, 512, 512, 1, 1.0f, 0);
        rope_planes<<<rows, 256>>>(bQ, Pq, LO);
        rope_planes<<<rows, 256>>>(bK, Pk, LO);
        // scores[b] = Q[b] @ K[b]^T * sc
        tg2(Pq, LO, 524288, Pk, LO, 524288, nullptr, bS, 1048576, 0, 0, 0, 1024, 1024, 512, nb, sc, 0);
        softmax1024_planes<<<rows, 256>>>(bS, biasRows, Pp, 16777216LL);
        // VT planes: [S,D] -> [D,S]
        trans_conv<<<dim3(16, 32, nb), dim3(32, 8)>>>(bV, Pvt, LO, 1024, 512, 524288, 524288, nullptr);
        // T = A @ V  -> bQ f32 + Pbq planes
        tg2(Pp, 16777216LL, 1048576, Pvt, LO, 524288, nullptr, bQ, 524288, Pbq, LO, 524288, 1024, 512, 1024, nb, 1.0f, 0);
        // O = T @ Wo + bo -> bK
        tg2(Pbq, LO, 0, PW + (size_t)(6 + l) * 524288, 262144, 0, bo + l * 512, bK, 0, 0, 0, 0, rows, 512, 512, 1, 1.0f, 0);
        ln_kernel<<<rows, 256>>>(X, bK, ln + l * 2048, ln + l * 2048 + 512, Px, LO);
        // H = gelu(X @ Wff0 + bff0) -> Ph planes
        tg2(Px, LO, 0, PW + (size_t)(8 + 2 * l) * 524288, 262144, 0, bff + l * 1024, bQ, 0, Ph, LO, 0, rows, 512, 512, 1, 1.0f, 1);
        // F = H @ Wff1 + bff1 -> bK
        tg2(Ph, LO, 0, PW + (size_t)(9 + 2 * l) * 524288, 262144, 0, bff + l * 1024 + 512, bK, 0, 0, 0, 0, rows, 512, 512, 1, 1.0f, 0);
        ln_kernel<<<rows, 256>>>(X, bK, ln + l * 2048 + 1024, ln + l * 2048 + 1536, Px, LO);
    }
}

extern "C" void kernel_launch(void* const* d_in, const int* in_sizes, int n_in,
                              void* d_out, int out_size)
{
    const float* raw_emb   = (const float*)d_in[0];
    const float* pos_w     = (const float*)d_in[1];
    const float* post_dec  = (const float*)d_in[2];
    const float* pos_r     = (const float*)d_in[3];
    const float* questions = (const float*)d_in[4];
    const float* W_k       = (const float*)d_in[5];
    const float* W_ig      = (const float*)d_in[6];
    const float* b_ig      = (const float*)d_in[7];
    const float* W_u1      = (const float*)d_in[8];
    const float* b_u1      = (const float*)d_in[9];
    const float* W_u2      = (const float*)d_in[10];
    const float* b_u2      = (const float*)d_in[11];
    const float* b1        = (const float*)d_in[12];
    const float* W_ok      = (const float*)d_in[13];
    const float* b_ok      = (const float*)d_in[14];
    const float* encw_Wqkv = (const float*)d_in[15];
    const float* encw_bqkv = (const float*)d_in[16];
    const float* encw_Wo   = (const float*)d_in[17];
    const float* encw_bo   = (const float*)d_in[18];
    const float* encw_ln   = (const float*)d_in[19];
    const float* encw_Wff  = (const float*)d_in[20];
    const float* encw_bff  = (const float*)d_in[21];
    const float* encr_Wqkv = (const float*)d_in[22];
    const float* encr_bqkv = (const float*)d_in[23];
    const float* encr_Wo   = (const float*)d_in[24];
    const float* encr_bo   = (const float*)d_in[25];
    const float* encr_ln   = (const float*)d_in[26];
    const float* encr_Wff  = (const float*)d_in[27];
    const float* encr_bff  = (const float*)d_in[28];
    const int*   lookup    = (const int*)d_in[29];

    float* out  = (float*)d_out;
    float* gate = out + (size_t)NBB * SS * DD;

    float *pX, *pQ, *pK, *pV, *pS, *pKd, *pVd, *pA1, *pK2, *pA2s, *pA2, *pBW, *pBR;
    __nv_bfloat16 *pPW, *pPraw, *pPpd, *pPx, *pPq, *pPk, *pPvt, *pPp, *pPbq, *pPh, *pPa2, *pPsel;
    cudaGetSymbolAddress((void**)&pX,    g_X);
    cudaGetSymbolAddress((void**)&pQ,    g_Qb);
    cudaGetSymbolAddress((void**)&pK,    g_Kb);
    cudaGetSymbolAddress((void**)&pV,    g_Vb);
    cudaGetSymbolAddress((void**)&pS,    g_S);
    cudaGetSymbolAddress((void**)&pKd,   g_Kdoc);
    cudaGetSymbolAddress((void**)&pVd,   g_Vdoc);
    cudaGetSymbolAddress((void**)&pA1,   g_A1S);
    cudaGetSymbolAddress((void**)&pK2,   g_K2);
    cudaGetSymbolAddress((void**)&pA2s,  g_A2SC);
    cudaGetSymbolAddress((void**)&pA2,   g_A2);
    cudaGetSymbolAddress((void**)&pBW,   g_BIASW);
    cudaGetSymbolAddress((void**)&pBR,   g_BIASR);
    cudaGetSymbolAddress((void**)&pPW,   g_PW);
    cudaGetSymbolAddress((void**)&pPraw, g_Praw);
    cudaGetSymbolAddress((void**)&pPpd,  g_Ppd);
    cudaGetSymbolAddress((void**)&pPx,   g_Px);
    cudaGetSymbolAddress((void**)&pPq,   g_Pq);
    cudaGetSymbolAddress((void**)&pPk,   g_Pk);
    cudaGetSymbolAddress((void**)&pPvt,  g_Pvt);
    cudaGetSymbolAddress((void**)&pPp,   g_Pp);
    cudaGetSymbolAddress((void**)&pPbq,  g_Pbq);
    cudaGetSymbolAddress((void**)&pPh,   g_Ph);
    cudaGetSymbolAddress((void**)&pPa2,  g_Pa2);
    cudaGetSymbolAddress((void**)&pPsel, g_Psel);

    cudaFuncSetAttribute(tgemm2, cudaFuncAttributeMaxDynamicSharedMemorySize, TG2_SMEM);

    const float scD = 1.0f / sqrtf((float)DD);

    rope_table_kernel<<<1024, 256>>>();
    bias_prep<<<NDOC, 256>>>(pos_w, pBW, 1);
    bias_prep<<<NBB, 256>>>(pos_r, pBR, 2);

    // ---- weights -> transposed planes ----
    trans_conv<<<dim3(16, 16, 6), dim3(32, 8)>>>(encw_Wqkv, pPW + 0,              262144, 512, 512, 262144, 524288, nullptr);
    trans_conv<<<dim3(16, 16, 2), dim3(32, 8)>>>(encw_Wo,   pPW + 6LL  * 524288,  262144, 512, 512, 262144, 524288, nullptr);
    trans_conv<<<dim3(16, 16, 4), dim3(32, 8)>>>(encw_Wff,  pPW + 8LL  * 524288,  262144, 512, 512, 262144, 524288, nullptr);
    trans_conv<<<dim3(16, 16, 6), dim3(32, 8)>>>(encr_Wqkv, pPW + 12LL * 524288,  262144, 512, 512, 262144, 524288, nullptr);
    trans_conv<<<dim3(16, 16, 2), dim3(32, 8)>>>(encr_Wo,   pPW + 18LL * 524288,  262144, 512, 512, 262144, 524288, nullptr);
    trans_conv<<<dim3(16, 16, 4), dim3(32, 8)>>>(encr_Wff,  pPW + 20LL * 524288,  262144, 512, 512, 262144, 524288, nullptr);
    trans_conv<<<dim3(16, 16, 1), dim3(32, 8)>>>(W_k,       pPW + 24LL * 524288,  262144, 512, 512, 262144, 524288, nullptr);
    trans_conv<<<dim3(16, 16, 1), dim3(32, 8)>>>(W_ok,      pPW + 25LL * 524288,  262144, 512, 512, 262144, 524288, nullptr);

    conv_planes<<<NDOC * SS, 256>>>(raw_emb,  pPraw, 4194304LL);
    conv_planes<<<NBB * SS, 256>>>(post_dec, pPpd,  8388608LL);

    // ---- write-side encoder on raw_emb (8 docs) ----
    cudaMemcpyAsync(pX, raw_emb, (size_t)NDOC * SS * DD * sizeof(float),
                    cudaMemcpyDeviceToDevice, 0);
    run_encoder(pX, NDOC, pPraw, 4194304LL, pBW,
                pPW, encw_bqkv, encw_bo, encw_ln, encw_bff,
                pQ, pK, pV, pS, pPq, pPk, pPvt, pPp, pPbq, pPh, pPx);

    vgate_kernel<<<NDOC * SS, 256>>>(pX, raw_emb, W_ig, b_ig, pVd);
    // k = raw_emb @ W_k
    tg2(pPraw, 4194304LL, 0, pPW + 24LL * 524288, 262144, 0, nullptr, pKd, 0, 0, 0, 0, NDOC * SS, 512, 512, 1, 1.0f, 0);
    // S1[n] = questions @ k[n]^T * scD  (M=64 -> SIMT)
    sgemm_launch(questions, pKd, nullptr, pS, QQ, SS, DD, NDOC, 0, 524288, 65536, scD, 1);
    softmax_f32<<<NDOC * QQ, 256>>>(pS, pBW, SS, QQ);
    // A1S[n] = S1[n] @ v[n]  (M=64 -> SIMT)
    sgemm_launch(pS, pVd, nullptr, pA1, QQ, DD, SS, NDOC, 65536, 524288, 32768, 1.0f, 0);

    // ---- read-side encoder on post_dec (16 batches) ----
    cudaMemcpyAsync(pX, post_dec, (size_t)NBB * SS * DD * sizeof(float),
                    cudaMemcpyDeviceToDevice, 0);
    run_encoder(pX, NBB, pPpd, 8388608LL, pBR,
                pPW + 12LL * 524288, encr_bqkv, encr_bo, encr_ln, encr_bff,
                pQ, pK, pV, pS, pPq, pPk, pPvt, pPp, pPbq, pPh, pPx);

    // k2 = post_dec @ W_ok + b_ok
    tg2(pPpd, 8388608LL, 0, pPW + 25LL * 524288, 262144, 0, b_ok, pK2, 0, 0, 0, 0, NBB * SS, 512, 512, 1, 1.0f, 0);
    // a2 = softmax(k2 @ questions^T / 8)  (N=64 -> SIMT)
    sgemm_launch(pK2, questions, nullptr, pA2s, NBB * SS, QQ, DD, 1, 0, 0, 0, 0.125f, 1);
    softmax64_planes<<<NBB * SS / 8, 256>>>(pA2s, pPa2, 1048576LL);
    // selA^T planes (gathered by lookup): [64,512] -> [512,64]
    trans_conv<<<dim3(16, 2, 16), dim3(32, 8)>>>(pA1, pPsel, 524288, 64, 512, 32768, 32768, lookup);
    // A2[b] = a2[b] @ selA[b]
    tg2(pPa2, 1048576LL, 65536, pPsel, 524288LL, 32768, nullptr, pA2, 524288, 0, 0, 0, 1024, 512, 64, NBB, 1.0f, 0);

    out_kernel<<<NBB * SS, 256>>>(pX, pA2, post_dec,
                                  W_u1, b_u1, W_u2, b_u2, b1,
                                  out, gate);

    (void)in_sizes; (void)n_in; (void)out_size;
}

// round 6
// speedup vs baseline: 2.1023x; 1.1129x over previous
#include <cuda_runtime.h>
#include <cuda_bf16.h>
#include <math.h>
#include <stdint.h>

// ---------------------------------------------------------------------------
// Problem constants
// ---------------------------------------------------------------------------
#define DD     512
#define SS     1024
#define NBB    16
#define QQ     64
#define NDOC   8

// ---------------------------------------------------------------------------
// f32 scratch
// ---------------------------------------------------------------------------
__device__ float g_X   [16384 * 512];
__device__ float g_QKV [16384 * 1536];
__device__ float g_Kb  [16384 * 512];
__device__ float g_S   [16 * 1024 * 1024];
__device__ float g_Kdoc[8192 * 512];
__device__ float g_Vdoc[8192 * 512];
__device__ float g_A1S [8 * 64 * 512];
__device__ float g_K2  [16384 * 512];
__device__ float g_A2SC[16384 * 64];
__device__ float g_A2  [16384 * 512];
__device__ float g_sin [1024 * 256];
__device__ float g_cos [1024 * 256];
__device__ float g_BIASW[8 * 1024];
__device__ float g_BIASR[16 * 1024];

// ---------------------------------------------------------------------------
// bf16 hi/lo plane buffers
// Weights: [26 x hi(262144)] then [26 x lo(262144)] => lo offset = 6815744
// ---------------------------------------------------------------------------
#define WLO 6815744LL
__device__ __align__(16) __nv_bfloat16 g_PW  [2 * 26 * 262144];
__device__ __align__(16) __nv_bfloat16 g_Praw[2 * 4194304];
__device__ __align__(16) __nv_bfloat16 g_Ppd [2 * 8388608];
__device__ __align__(16) __nv_bfloat16 g_Px  [2 * 8388608];
__device__ __align__(16) __nv_bfloat16 g_Pq  [2 * 8388608];
__device__ __align__(16) __nv_bfloat16 g_Pk  [2 * 8388608];
__device__ __align__(16) __nv_bfloat16 g_Pvt [2 * 8388608];
__device__ __align__(16) __nv_bfloat16 g_Pp  [2 * 16777216];
__device__ __align__(16) __nv_bfloat16 g_Pbq [2 * 8388608];
__device__ __align__(16) __nv_bfloat16 g_Ph  [2 * 8388608];
__device__ __align__(16) __nv_bfloat16 g_Pa2 [2 * 1048576];
__device__ __align__(16) __nv_bfloat16 g_Psel[2 * 524288];

// ---------------------------------------------------------------------------
// Helpers
// ---------------------------------------------------------------------------
__device__ __forceinline__ uint32_t smem_u32(const void* p) {
    uint32_t a;
    asm("{ .reg .u64 t; cvta.to.shared.u64 t, %1; cvt.u32.u64 %0, t; }"
        : "=r"(a) : "l"(p));
    return a;
}

__device__ __forceinline__ void ldsm4(uint32_t* r, uint32_t addr) {
    asm volatile("ldmatrix.sync.aligned.m8n8.x4.shared.b16 {%0,%1,%2,%3}, [%4];"
                 : "=r"(r[0]), "=r"(r[1]), "=r"(r[2]), "=r"(r[3]) : "r"(addr));
}

__device__ __forceinline__ void mma_bf16(float* c, const uint32_t* a,
                                         uint32_t b0, uint32_t b1) {
    asm volatile(
        "mma.sync.aligned.m16n8k16.row.col.f32.bf16.bf16.f32 "
        "{%0,%1,%2,%3}, {%4,%5,%6,%7}, {%8,%9}, {%0,%1,%2,%3};"
        : "+f"(c[0]), "+f"(c[1]), "+f"(c[2]), "+f"(c[3])
        : "r"(a[0]), "r"(a[1]), "r"(a[2]), "r"(a[3]), "r"(b0), "r"(b1));
}

__device__ __forceinline__ void cpasync16(uint32_t dst, const void* src) {
    asm volatile("cp.async.cg.shared.global [%0], [%1], 16;" :: "r"(dst), "l"(src));
}
#define CP_COMMIT() asm volatile("cp.async.commit_group;" ::: "memory")
#define CP_WAIT(n)  asm volatile("cp.async.wait_group %0;" :: "n"(n) : "memory")

__device__ __forceinline__ void split_pair(float x0, float x1,
                                           __nv_bfloat162& h, __nv_bfloat162& l) {
    h = __floats2bfloat162_rn(x0, x1);
    l = __floats2bfloat162_rn(x0 - __bfloat162float(h.x),
                              x1 - __bfloat162float(h.y));
}

// ---------------------------------------------------------------------------
// Plane GEMM, 512 threads, 16 warps, warp tile 32x32, 3-stage cp.async ring.
//   C = alpha * (Ah+Al)[M,K] @ (Bh+Bl)[N,K]^T + bias ; 3-MMA split
//   Cf (f32) optional; Ch planes optional. M%128==0, N%128==0, K%32==0.
// ---------------------------------------------------------------------------
#define PLANE  10240
#define TSTAGE 40960
#define TG_SMEM (3 * 40960)

__global__ void __launch_bounds__(512)
tgemm3(const __nv_bfloat16* __restrict__ Ah0,
       const __nv_bfloat16* __restrict__ Bh0,
       const float* __restrict__ bias, float* __restrict__ Cf,
       __nv_bfloat16* __restrict__ Ch0,
       int M, int N, int K,
       long long loA, long long loB, long long loC,
       long long sA, long long sB, long long sC, long long sCp,
       float alpha, int epi)
{
    extern __shared__ char smem[];
    const uint32_t sbu = smem_u32(smem);
    const int t = threadIdx.x, w = t >> 5, lane = t & 31;
    const int wm = w & 3, wn = w >> 2;           // 4x4 warp grid, 32x32 tiles
    const int z = blockIdx.z;
    const int m0 = blockIdx.y * 128, n0 = blockIdx.x * 128;

    const __nv_bfloat16* Ah = Ah0 + (size_t)z * sA;
    const __nv_bfloat16* Bh = Bh0 + (size_t)z * sB;

    const int lrow = t >> 2, seg = t & 3;        // 128 rows x 4 16B-segments
    const __nv_bfloat16* pr[4];
    pr[0] = Ah + (size_t)(m0 + lrow) * K + seg * 8;
    pr[1] = pr[0] + loA;
    pr[2] = Bh + (size_t)(n0 + lrow) * K + seg * 8;
    pr[3] = pr[2] + loB;

    float acc[2][4][4];
#pragma unroll
    for (int i = 0; i < 2; i++)
#pragma unroll
        for (int j = 0; j < 4; j++)
#pragma unroll
            for (int e = 0; e < 4; e++) acc[i][j][e] = 0.0f;

    const int nch = K >> 5;
    const uint32_t sdbase = sbu + (uint32_t)(lrow * 80 + seg * 16);

#define ISSUE(ch) do {                                                      \
    uint32_t _sd = sdbase + (uint32_t)((ch) % 3) * TSTAGE;                  \
    const int _cb = (ch) * 32;                                              \
    _Pragma("unroll")                                                       \
    for (int _p = 0; _p < 4; _p++)                                          \
        cpasync16(_sd + _p * PLANE, pr[_p] + _cb);                          \
    CP_COMMIT();                                                            \
} while (0)

    ISSUE(0);
    ISSUE(1);

    const uint32_t lmoff = (uint32_t)((lane & 15) * 80 + (lane >> 4) * 16);

    for (int ch = 0; ch < nch; ch++) {
        if (ch + 1 < nch) { CP_WAIT(1); } else { CP_WAIT(0); }
        __syncthreads();
        if (ch + 2 < nch) ISSUE(ch + 2);

        const uint32_t sAh = sbu + (uint32_t)(ch % 3) * TSTAGE;
        const uint32_t sBh = sAh + 2 * PLANE;
#pragma unroll
        for (int kk = 0; kk < 2; kk++) {
            uint32_t ah[2][4], al[2][4], bh[2][4], bl[2][4];
#pragma unroll
            for (int mt = 0; mt < 2; mt++) {
                uint32_t aaddr = sAh + (uint32_t)((wm * 32 + mt * 16) * 80 + kk * 32) + lmoff;
                ldsm4(ah[mt], aaddr);
                ldsm4(al[mt], aaddr + PLANE);
            }
#pragma unroll
            for (int ng = 0; ng < 2; ng++) {
                uint32_t baddr = sBh + (uint32_t)((wn * 32 + ng * 16) * 80 + kk * 32) + lmoff;
                ldsm4(bh[ng], baddr);
                ldsm4(bl[ng], baddr + PLANE);
            }
#pragma unroll
            for (int ng = 0; ng < 2; ng++)
#pragma unroll
                for (int mt = 0; mt < 2; mt++)
#pragma unroll
                    for (int h2 = 0; h2 < 2; h2++) {
                        float* c = acc[mt][ng * 2 + h2];
                        mma_bf16(c, ah[mt], bh[ng][h2], bh[ng][h2 + 2]);
                        mma_bf16(c, ah[mt], bl[ng][h2], bl[ng][h2 + 2]);
                        mma_bf16(c, al[mt], bh[ng][h2], bh[ng][h2 + 2]);
                    }
        }
    }
#undef ISSUE

    // ---- epilogue ----
    const float GC = 0.7978845608028654f;
    const int crow = m0 + wm * 32 + (lane >> 2);
    const int ccol = n0 + wn * 32 + (lane & 3) * 2;
    float* Cfz = Cf ? Cf + (size_t)z * sC : (float*)0;
    __nv_bfloat16* Chz = Ch0 ? Ch0 + (size_t)z * sCp : (__nv_bfloat16*)0;
    __nv_bfloat16* Clz = Chz ? Chz + loC : (__nv_bfloat16*)0;
#pragma unroll
    for (int mt = 0; mt < 2; mt++) {
#pragma unroll
        for (int n8 = 0; n8 < 4; n8++) {
            const float* c = acc[mt][n8];
            const int col = ccol + n8 * 8;
            float b0 = bias ? bias[col]     : 0.0f;
            float b1 = bias ? bias[col + 1] : 0.0f;
#pragma unroll
            for (int h = 0; h < 2; h++) {
                const int row = crow + mt * 16 + h * 8;
                float x0 = c[h * 2 + 0] * alpha + b0;
                float x1 = c[h * 2 + 1] * alpha + b1;
                if (epi) {
                    x0 = 0.5f * x0 * (1.0f + tanhf(GC * (x0 + 0.044715f * x0 * x0 * x0)));
                    x1 = 0.5f * x1 * (1.0f + tanhf(GC * (x1 + 0.044715f * x1 * x1 * x1)));
                }
                if (Cfz)
                    *(float2*)&Cfz[(size_t)row * N + col] = make_float2(x0, x1);
                if (Chz) {
                    __nv_bfloat162 hh, ll;
                    split_pair(x0, x1, hh, ll);
                    *(__nv_bfloat162*)&Chz[(size_t)row * N + col] = hh;
                    *(__nv_bfloat162*)&Clz[(size_t)row * N + col] = ll;
                }
            }
        }
    }
}

static void tg3(const __nv_bfloat16* Ah, long long loA, long long sA,
                const __nv_bfloat16* Bh, long long loB, long long sB,
                const float* bias, float* Cf, long long sC,
                __nv_bfloat16* Ch, long long loC, long long sCp,
                int M, int N, int K, int batch, float alpha, int epi)
{
    dim3 grid(N / 128, M / 128, batch);
    tgemm3<<<grid, 512, TG_SMEM>>>(Ah, Bh, bias, Cf, Ch, M, N, K,
                                   loA, loB, loC, sA, sB, sC, sCp, alpha, epi);
}

// ---------------------------------------------------------------------------
// Transpose + convert to planes: out[c][r] planes from in[r][c].
// cols handled = gridDim.x*32 (may be < C row stride). ids: optional gather.
// ---------------------------------------------------------------------------
__global__ void trans_conv(const float* __restrict__ in, __nv_bfloat16* __restrict__ oh,
                           long long loOff, int R, int C,
                           long long sI, long long sO, const int* __restrict__ ids)
{
    __shared__ float tile[32][33];
    const int z = blockIdx.z;
    size_t ib = ids ? (size_t)ids[z] * sI : (size_t)z * sI;
    const float* ip = in + ib;
    __nv_bfloat16* ohz = oh + (size_t)z * sO;
    __nv_bfloat16* olz = ohz + loOff;
    const int c0 = blockIdx.x * 32, r0 = blockIdx.y * 32;
    const int tx = threadIdx.x, ty = threadIdx.y;
#pragma unroll
    for (int k = 0; k < 32; k += 8)
        tile[ty + k][tx] = ip[(size_t)(r0 + ty + k) * C + c0 + tx];
    __syncthreads();
    const int rr = (tx & 15) * 2, chf = tx >> 4;
#pragma unroll
    for (int k = 0; k < 2; k++) {
        int cc = ty + chf * 8 + k * 16;
        __nv_bfloat162 h, l;
        split_pair(tile[rr][cc], tile[rr + 1][cc], h, l);
        *(__nv_bfloat162*)&ohz[(size_t)(c0 + cc) * R + r0 + rr] = h;
        *(__nv_bfloat162*)&olz[(size_t)(c0 + cc) * R + r0 + rr] = l;
    }
}

// ---------------------------------------------------------------------------
// Convert rows (512 cols) to planes
// ---------------------------------------------------------------------------
__global__ void conv_planes(const float* __restrict__ in, __nv_bfloat16* __restrict__ oh,
                            long long lo)
{
    size_t idx = (size_t)blockIdx.x * 512 + (size_t)threadIdx.x * 2;
    float2 v = *(const float2*)&in[idx];
    __nv_bfloat162 h, l;
    split_pair(v.x, v.y, h, l);
    *(__nv_bfloat162*)&oh[idx] = h;
    *(__nv_bfloat162*)&(oh + lo)[idx] = l;
}

// ---------------------------------------------------------------------------
// RoPE table + fused Q/K rope->planes (reads packed QKV rows of 1536)
// ---------------------------------------------------------------------------
__global__ void rope_table_kernel()
{
    int s = blockIdx.x;
    int i = threadIdx.x;
    float invf = 1.0f / powf(10000.0f, (float)i / 256.0f);
    float angf = (float)s * invf;
    double ang = (double)angf;
    g_sin[s * 256 + i] = (float)sin(ang);
    g_cos[s * 256 + i] = (float)cos(ang);
}

__global__ void rope2_planes(const float* __restrict__ QKV,
                             __nv_bfloat16* __restrict__ Pq,
                             __nv_bfloat16* __restrict__ Pk, long long lo)
{
    int row = blockIdx.x, i = threadIdx.x;
    int s = row & (SS - 1);
    float sn = g_sin[s * 256 + i];
    float cs = g_cos[s * 256 + i];
    const float* base = QKV + (size_t)row * 1536;
    size_t o = (size_t)row * DD + 2 * i;
    __nv_bfloat162 h, l;
    {
        float x1 = base[2 * i], x2 = base[2 * i + 1];
        split_pair(x1 * cs - x2 * sn, x1 * sn + x2 * cs, h, l);
        *(__nv_bfloat162*)&Pq[o] = h;
        *(__nv_bfloat162*)&(Pq + lo)[o] = l;
    }
    {
        float x1 = base[512 + 2 * i], x2 = base[512 + 2 * i + 1];
        split_pair(x1 * cs - x2 * sn, x1 * sn + x2 * cs, h, l);
        *(__nv_bfloat162*)&Pk[o] = h;
        *(__nv_bfloat162*)&(Pk + lo)[o] = l;
    }
}

// ---------------------------------------------------------------------------
// Positional bias precompute: mode 1 = log(p), 2 = logit(p)
// ---------------------------------------------------------------------------
__global__ void bias_prep(const float* __restrict__ pos, float* __restrict__ out, int mode)
{
    int n = blockIdx.x, t = threadIdx.x;
    for (int c = t; c < 1024; c += 256) {
        float p = pos[n * 1024 + c];
        out[n * 1024 + c] = (mode == 1) ? logf(p) : (logf(p) - log1pf(-p));
    }
}

// ---------------------------------------------------------------------------
// Softmax over 1024 cols + bias row, emits planes (single pass in regs)
// ---------------------------------------------------------------------------
__global__ void softmax1024_planes(const float* __restrict__ S, const float* __restrict__ bias,
                                   __nv_bfloat16* __restrict__ oh, long long lo)
{
    const int row = blockIdx.x, t = threadIdx.x;
    const float* sr = S + (size_t)row * 1024;
    const float* pb = bias + (size_t)(row >> 10) * 1024;
    float2 a  = *(const float2*)&sr[2 * t];
    float2 b2 = *(const float2*)&sr[512 + 2 * t];
    float2 ba = *(const float2*)&pb[2 * t];
    float2 bb = *(const float2*)&pb[512 + 2 * t];
    float v0 = a.x + ba.x, v1 = a.y + ba.y, v2 = b2.x + bb.x, v3 = b2.y + bb.y;

    __shared__ float red[256];
    float mx = fmaxf(fmaxf(v0, v1), fmaxf(v2, v3));
    red[t] = mx; __syncthreads();
    for (int s = 128; s > 0; s >>= 1) { if (t < s) red[t] = fmaxf(red[t], red[t + s]); __syncthreads(); }
    mx = red[0]; __syncthreads();

    float e0 = expf(v0 - mx), e1 = expf(v1 - mx), e2 = expf(v2 - mx), e3 = expf(v3 - mx);
    red[t] = e0 + e1 + e2 + e3; __syncthreads();
    for (int s = 128; s > 0; s >>= 1) { if (t < s) red[t] += red[t + s]; __syncthreads(); }
    float inv = 1.0f / red[0];

    __nv_bfloat162 h, l;
    size_t o = (size_t)row * 1024 + 2 * t;
    split_pair(e0 * inv, e1 * inv, h, l);
    *(__nv_bfloat162*)&oh[o] = h;
    *(__nv_bfloat162*)&(oh + lo)[o] = l;
    split_pair(e2 * inv, e3 * inv, h, l);
    *(__nv_bfloat162*)&oh[o + 512] = h;
    *(__nv_bfloat162*)&(oh + lo)[o + 512] = l;
}

// ---------------------------------------------------------------------------
// Softmax over 64 cols, warp per row, emits planes
// ---------------------------------------------------------------------------
__global__ void softmax64_planes(const float* __restrict__ S, __nv_bfloat16* __restrict__ oh,
                                 long long lo)
{
    const int row = blockIdx.x * 8 + (threadIdx.x >> 5);
    const int lane = threadIdx.x & 31;
    const float* sr = S + (size_t)row * 64;
    float2 v = *(const float2*)&sr[lane * 2];
    float mx = fmaxf(v.x, v.y);
#pragma unroll
    for (int o = 16; o > 0; o >>= 1)
        mx = fmaxf(mx, __shfl_xor_sync(0xFFFFFFFF, mx, o));
    float e0 = expf(v.x - mx), e1 = expf(v.y - mx);
    float s = e0 + e1;
#pragma unroll
    for (int o = 16; o > 0; o >>= 1)
        s += __shfl_xor_sync(0xFFFFFFFF, s, o);
    float inv = 1.0f / s;
    __nv_bfloat162 h, l;
    split_pair(e0 * inv, e1 * inv, h, l);
    size_t o2 = (size_t)row * 64 + lane * 2;
    *(__nv_bfloat162*)&oh[o2] = h;
    *(__nv_bfloat162*)&(oh + lo)[o2] = l;
}

// ---------------------------------------------------------------------------
// Softmax f32 (S1 path)
// ---------------------------------------------------------------------------
__global__ void softmax_f32(float* __restrict__ S, const float* __restrict__ bias,
                            int cols, int rpb)
{
    int row = blockIdx.x;
    float* sr = S + (size_t)row * cols;
    const float* pb = bias + (size_t)(row / rpb) * cols;
    int t = threadIdx.x;
    __shared__ float red[256];

    float mx = -1e30f;
    for (int c = t; c < cols; c += 256) {
        float v = sr[c] + pb[c];
        sr[c] = v;
        mx = fmaxf(mx, v);
    }
    red[t] = mx; __syncthreads();
    for (int s = 128; s > 0; s >>= 1) { if (t < s) red[t] = fmaxf(red[t], red[t + s]); __syncthreads(); }
    mx = red[0]; __syncthreads();

    float sum = 0.0f;
    for (int c = t; c < cols; c += 256) {
        float e = expf(sr[c] - mx);
        sr[c] = e;
        sum += e;
    }
    red[t] = sum; __syncthreads();
    for (int s = 128; s > 0; s >>= 1) { if (t < s) red[t] += red[t + s]; __syncthreads(); }
    float inv = 1.0f / red[0];
    for (int c = t; c < cols; c += 256) sr[c] *= inv;
}

// ---------------------------------------------------------------------------
// X = LayerNorm(X + R) * g + b ; emits X f32 and X planes
// ---------------------------------------------------------------------------
__global__ void ln_kernel(float* __restrict__ X, const float* __restrict__ R,
                          const float* __restrict__ g, const float* __restrict__ b,
                          __nv_bfloat16* __restrict__ oh, long long lo)
{
    int row = blockIdx.x;
    int t   = threadIdx.x;
    float* xr = X + (size_t)row * DD;
    const float* rr = R + (size_t)row * DD;

    float v0 = xr[2 * t] + rr[2 * t];
    float v1 = xr[2 * t + 1] + rr[2 * t + 1];

    __shared__ float red[256];
    red[t] = v0 + v1; __syncthreads();
    for (int s = 128; s > 0; s >>= 1) { if (t < s) red[t] += red[t + s]; __syncthreads(); }
    float m = red[0] * (1.0f / 512.0f);
    __syncthreads();

    float d0 = v0 - m, d1 = v1 - m;
    red[t] = d0 * d0 + d1 * d1; __syncthreads();
    for (int s = 128; s > 0; s >>= 1) { if (t < s) red[t] += red[t + s]; __syncthreads(); }
    float var = red[0] * (1.0f / 512.0f);
    float inv = rsqrtf(var + 1e-5f);

    float o0 = d0 * inv * g[2 * t]     + b[2 * t];
    float o1 = d1 * inv * g[2 * t + 1] + b[2 * t + 1];
    xr[2 * t]     = o0;
    xr[2 * t + 1] = o1;

    __nv_bfloat162 h, l;
    split_pair(o0, o1, h, l);
    size_t o = (size_t)row * DD + 2 * t;
    *(__nv_bfloat162*)&oh[o] = h;
    *(__nv_bfloat162*)&(oh + lo)[o] = l;
}

// ---------------------------------------------------------------------------
// V = raw * sigmoid(F . W_ig + b_ig)
// ---------------------------------------------------------------------------
__global__ void vgate_kernel(const float* __restrict__ F, const float* __restrict__ raw,
                             const float* __restrict__ Wig, const float* __restrict__ big,
                             float* __restrict__ V)
{
    int row = blockIdx.x;
    int t   = threadIdx.x;
    const float* fr = F + (size_t)row * DD;
    __shared__ float red[256];
    float s = fr[t] * Wig[t] + fr[t + 256] * Wig[t + 256];
    red[t] = s; __syncthreads();
    for (int k = 128; k > 0; k >>= 1) { if (t < k) red[t] += red[t + k]; __syncthreads(); }
    float gte = 1.0f / (1.0f + expf(-(red[0] + big[0])));
    const float* rr = raw + (size_t)row * DD;
    float* vr = V + (size_t)row * DD;
    vr[t]       = rr[t]       * gte;
    vr[t + 256] = rr[t + 256] * gte;
}

// ---------------------------------------------------------------------------
// Final gate + output
// ---------------------------------------------------------------------------
__global__ void out_kernel(const float* __restrict__ FU, const float* __restrict__ A2,
                           const float* __restrict__ PD,
                           const float* __restrict__ Wu1, const float* __restrict__ bu1,
                           const float* __restrict__ Wu2, const float* __restrict__ bu2,
                           const float* __restrict__ b1,
                           float* __restrict__ out, float* __restrict__ gate)
{
    int row = blockIdx.x;
    int t   = threadIdx.x;
    const float* fu = FU + (size_t)row * DD;
    const float* a2 = A2 + (size_t)row * DD;
    const float* pd = PD + (size_t)row * DD;

    __shared__ float red[256];
    float s = fu[t] * Wu1[t] + fu[t + 256] * Wu1[t + 256]
            + a2[t] * Wu2[t] + a2[t + 256] * Wu2[t + 256];
    red[t] = s; __syncthreads();
    for (int k = 128; k > 0; k >>= 1) { if (t < k) red[t] += red[t + k]; __syncthreads(); }
    float z = red[0] + bu1[0] + bu2[0] + b1[0] - 4.0f;
    float g = 1.0f / (1.0f + expf(-z));

    float* orow = out + (size_t)row * DD;
    orow[t]       = pd[t]       * (1.0f - g) + a2[t]       * g;
    orow[t + 256] = pd[t + 256] * (1.0f - g) + a2[t + 256] * g;
    if (t == 0) gate[row] = g;
}

// ---------------------------------------------------------------------------
// SIMT fallback GEMM (64x64x16) for M=64 / N=64 shapes
// ---------------------------------------------------------------------------
#define BM 64
#define BN 64
#define BK 16

__global__ void gemm_kernel(const float* __restrict__ A,
                            const float* __restrict__ Bm,
                            const float* __restrict__ bias,
                            float* __restrict__ C,
                            int M, int N, int K,
                            long long sA, long long sB, long long sC,
                            float alpha, int transB, int epi)
{
    const int bz = blockIdx.z;
    A  += (size_t)bz * sA;
    Bm += (size_t)bz * sB;
    C  += (size_t)bz * sC;

    const int m0 = blockIdx.y * BM;
    const int n0 = blockIdx.x * BN;

    __shared__ float As[BK][BM + 4];
    __shared__ float Bs[BK][BN + 4];

    const int t  = threadIdx.x;
    const int tx = t & 15;
    const int ty = t >> 4;

    float acc[4][4] = {};

    const int arow = t >> 2;
    const int akc  = (t & 3) * 4;
    const int kb   = t >> 4;
    const int nb   = (t & 15) * 4;

    for (int k0 = 0; k0 < K; k0 += BK) {
        float4 av = *(const float4*)&A[(size_t)(m0 + arow) * K + k0 + akc];
        As[akc + 0][arow] = av.x;
        As[akc + 1][arow] = av.y;
        As[akc + 2][arow] = av.z;
        As[akc + 3][arow] = av.w;

        if (!transB) {
            float4 bv = *(const float4*)&Bm[(size_t)(k0 + kb) * N + n0 + nb];
            *(float4*)&Bs[kb][nb] = bv;
        } else {
            float4 bv = *(const float4*)&Bm[(size_t)(n0 + arow) * K + k0 + akc];
            Bs[akc + 0][arow] = bv.x;
            Bs[akc + 1][arow] = bv.y;
            Bs[akc + 2][arow] = bv.z;
            Bs[akc + 3][arow] = bv.w;
        }
        __syncthreads();

#pragma unroll
        for (int k = 0; k < BK; k++) {
            float4 a = *(const float4*)&As[k][ty * 4];
            float4 b = *(const float4*)&Bs[k][tx * 4];
            acc[0][0] += a.x * b.x; acc[0][1] += a.x * b.y;
            acc[0][2] += a.x * b.z; acc[0][3] += a.x * b.w;
            acc[1][0] += a.y * b.x; acc[1][1] += a.y * b.y;
            acc[1][2] += a.y * b.z; acc[1][3] += a.y * b.w;
            acc[2][0] += a.z * b.x; acc[2][1] += a.z * b.y;
            acc[2][2] += a.z * b.z; acc[2][3] += a.z * b.w;
            acc[3][0] += a.w * b.x; acc[3][1] += a.w * b.y;
            acc[3][2] += a.w * b.z; acc[3][3] += a.w * b.w;
        }
        __syncthreads();
    }

#pragma unroll
    for (int i = 0; i < 4; i++) {
        const int row = m0 + ty * 4 + i;
        float v[4];
#pragma unroll
        for (int j = 0; j < 4; j++) {
            float x = acc[i][j] * alpha;
            if (bias) x += bias[n0 + tx * 4 + j];
            v[j] = x;
        }
        *(float4*)&C[(size_t)row * N + n0 + tx * 4] = make_float4(v[0], v[1], v[2], v[3]);
    }
}

static void sgemm_launch(const float* A, const float* B, const float* bias, float* C,
                         int M, int N, int K, int batch,
                         long long sA, long long sB, long long sC,
                         float alpha, int transB)
{
    dim3 grid(N / BN, M / BM, batch);
    gemm_kernel<<<grid, 256>>>(A, B, bias, C, M, N, K, sA, sB, sC, alpha, transB, 0);
}

// ---------------------------------------------------------------------------
// Encoder. Weight hi planes at pPW + wi*262144, lo at +WLO.
// Per-encoder weight order: [l*3+j] qkv, [6+l] Wo, [8+2l+j] ff
// ---------------------------------------------------------------------------
static void run_encoder(float* X, int nb,
                        const __nv_bfloat16* initP, long long initLo,
                        const float* biasRows,
                        const __nv_bfloat16* PW,
                        const float* bqkv, const float* bo,
                        const float* ln, const float* bff,
                        float* bQKV, float* bK, float* bS,
                        __nv_bfloat16* Pq, __nv_bfloat16* Pk, __nv_bfloat16* Pvt,
                        __nv_bfloat16* Pp, __nv_bfloat16* Pbq, __nv_bfloat16* Ph,
                        __nv_bfloat16* Px)
{
    const int rows = nb * SS;
    const float sc = 1.0f / sqrtf((float)DD);
    const long long LO = 8388608LL;
    for (int l = 0; l < 2; l++) {
        const __nv_bfloat16* AP = (l == 0) ? initP : Px;
        const long long loAP = (l == 0) ? initLo : LO;
        // fused QKV: N=1536
        tg3(AP, loAP, 0, PW + (size_t)(l * 3) * 262144, WLO, 0,
            bqkv + (size_t)l * 1536, bQKV, 0, 0, 0, 0, rows, 1536, 512, 1, 1.0f, 0);
        rope2_planes<<<rows, 256>>>(bQKV, Pq, Pk, LO);
        // V transpose planes: [S,512] (stride 1536, col offset 1024) -> [512,S]
        trans_conv<<<dim3(16, 32, nb), dim3(32, 8)>>>(bQKV + 1024, Pvt, LO, 1024, 1536,
                                                      (long long)SS * 1536, 524288, nullptr);
        // scores = Q @ K^T * sc
        tg3(Pq, LO, 524288, Pk, LO, 524288, nullptr, bS, 1048576, 0, 0, 0,
            1024, 1024, 512, nb, sc, 0);
        softmax1024_planes<<<rows, 256>>>(bS, biasRows, Pp, 16777216LL);
        // T = A @ V -> planes only
        tg3(Pp, 16777216LL, 1048576, Pvt, LO, 524288, nullptr, nullptr, 0, Pbq, LO, 524288,
            1024, 512, 1024, nb, 1.0f, 0);
        // O = T @ Wo + bo -> bK f32
        tg3(Pbq, LO, 0, PW + (size_t)(6 + l) * 262144, WLO, 0, bo + l * 512,
            bK, 0, 0, 0, 0, rows, 512, 512, 1, 1.0f, 0);
        ln_kernel<<<rows, 256>>>(X, bK, ln + l * 2048, ln + l * 2048 + 512, Px, LO);
        // H = gelu(X @ Wff0 + bff0) -> planes only
        tg3(Px, LO, 0, PW + (size_t)(8 + 2 * l) * 262144, WLO, 0, bff + l * 1024,
            nullptr, 0, Ph, LO, 0, rows, 512, 512, 1, 1.0f, 1);
        // F = H @ Wff1 + bff1 -> bK f32
        tg3(Ph, LO, 0, PW + (size_t)(9 + 2 * l) * 262144, WLO, 0, bff + l * 1024 + 512,
            bK, 0, 0, 0, 0, rows, 512, 512, 1, 1.0f, 0);
        ln_kernel<<<rows, 256>>>(X, bK, ln + l * 2048 + 1024, ln + l * 2048 + 1536, Px, LO);
    }
}

extern "C" void kernel_launch(void* const* d_in, const int* in_sizes, int n_in,
                              void* d_out, int out_size)
{
    const float* raw_emb   = (const float*)d_in[0];
    const float* pos_w     = (const float*)d_in[1];
    const float* post_dec  = (const float*)d_in[2];
    const float* pos_r     = (const float*)d_in[3];
    const float* questions = (const float*)d_in[4];
    const float* W_k       = (const float*)d_in[5];
    const float* W_ig      = (const float*)d_in[6];
    const float* b_ig      = (const float*)d_in[7];
    const float* W_u1      = (const float*)d_in[8];
    const float* b_u1      = (const float*)d_in[9];
    const float* W_u2      = (const float*)d_in[10];
    const float* b_u2      = (const float*)d_in[11];
    const float* b1        = (const float*)d_in[12];
    const float* W_ok      = (const float*)d_in[13];
    const float* b_ok      = (const float*)d_in[14];
    const float* encw_Wqkv = (const float*)d_in[15];
    const float* encw_bqkv = (const float*)d_in[16];
    const float* encw_Wo   = (const float*)d_in[17];
    const float* encw_bo   = (const float*)d_in[18];
    const float* encw_ln   = (const float*)d_in[19];
    const float* encw_Wff  = (const float*)d_in[20];
    const float* encw_bff  = (const float*)d_in[21];
    const float* encr_Wqkv = (const float*)d_in[22];
    const float* encr_bqkv = (const float*)d_in[23];
    const float* encr_Wo   = (const float*)d_in[24];
    const float* encr_bo   = (const float*)d_in[25];
    const float* encr_ln   = (const float*)d_in[26];
    const float* encr_Wff  = (const float*)d_in[27];
    const float* encr_bff  = (const float*)d_in[28];
    const int*   lookup    = (const int*)d_in[29];

    float* out  = (float*)d_out;
    float* gate = out + (size_t)NBB * SS * DD;

    float *pX, *pQKV, *pK, *pS, *pKd, *pVd, *pA1, *pK2, *pA2s, *pA2, *pBW, *pBR;
    __nv_bfloat16 *pPW, *pPraw, *pPpd, *pPx, *pPq, *pPk, *pPvt, *pPp, *pPbq, *pPh, *pPa2, *pPsel;
    cudaGetSymbolAddress((void**)&pX,    g_X);
    cudaGetSymbolAddress((void**)&pQKV,  g_QKV);
    cudaGetSymbolAddress((void**)&pK,    g_Kb);
    cudaGetSymbolAddress((void**)&pS,    g_S);
    cudaGetSymbolAddress((void**)&pKd,   g_Kdoc);
    cudaGetSymbolAddress((void**)&pVd,   g_Vdoc);
    cudaGetSymbolAddress((void**)&pA1,   g_A1S);
    cudaGetSymbolAddress((void**)&pK2,   g_K2);
    cudaGetSymbolAddress((void**)&pA2s,  g_A2SC);
    cudaGetSymbolAddress((void**)&pA2,   g_A2);
    cudaGetSymbolAddress((void**)&pBW,   g_BIASW);
    cudaGetSymbolAddress((void**)&pBR,   g_BIASR);
    cudaGetSymbolAddress((void**)&pPW,   g_PW);
    cudaGetSymbolAddress((void**)&pPraw, g_Praw);
    cudaGetSymbolAddress((void**)&pPpd,  g_Ppd);
    cudaGetSymbolAddress((void**)&pPx,   g_Px);
    cudaGetSymbolAddress((void**)&pPq,   g_Pq);
    cudaGetSymbolAddress((void**)&pPk,   g_Pk);
    cudaGetSymbolAddress((void**)&pPvt,  g_Pvt);
    cudaGetSymbolAddress((void**)&pPp,   g_Pp);
    cudaGetSymbolAddress((void**)&pPbq,  g_Pbq);
    cudaGetSymbolAddress((void**)&pPh,   g_Ph);
    cudaGetSymbolAddress((void**)&pPa2,  g_Pa2);
    cudaGetSymbolAddress((void**)&pPsel, g_Psel);

    cudaFuncSetAttribute(tgemm3, cudaFuncAttributeMaxDynamicSharedMemorySize, TG_SMEM);

    const float scD = 1.0f / sqrtf((float)DD);

    rope_table_kernel<<<1024, 256>>>();
    bias_prep<<<NDOC, 256>>>(pos_w, pBW, 1);
    bias_prep<<<NBB, 256>>>(pos_r, pBR, 2);

    // ---- weights -> transposed planes (hi block, shared lo offset WLO) ----
    trans_conv<<<dim3(16, 16, 6), dim3(32, 8)>>>(encw_Wqkv, pPW + 0LL  * 262144, WLO, 512, 512, 262144, 262144, nullptr);
    trans_conv<<<dim3(16, 16, 2), dim3(32, 8)>>>(encw_Wo,   pPW + 6LL  * 262144, WLO, 512, 512, 262144, 262144, nullptr);
    trans_conv<<<dim3(16, 16, 4), dim3(32, 8)>>>(encw_Wff,  pPW + 8LL  * 262144, WLO, 512, 512, 262144, 262144, nullptr);
    trans_conv<<<dim3(16, 16, 6), dim3(32, 8)>>>(encr_Wqkv, pPW + 12LL * 262144, WLO, 512, 512, 262144, 262144, nullptr);
    trans_conv<<<dim3(16, 16, 2), dim3(32, 8)>>>(encr_Wo,   pPW + 18LL * 262144, WLO, 512, 512, 262144, 262144, nullptr);
    trans_conv<<<dim3(16, 16, 4), dim3(32, 8)>>>(encr_Wff,  pPW + 20LL * 262144, WLO, 512, 512, 262144, 262144, nullptr);
    trans_conv<<<dim3(16, 16, 1), dim3(32, 8)>>>(W_k,       pPW + 24LL * 262144, WLO, 512, 512, 262144, 262144, nullptr);
    trans_conv<<<dim3(16, 16, 1), dim3(32, 8)>>>(W_ok,      pPW + 25LL * 262144, WLO, 512, 512, 262144, 262144, nullptr);

    conv_planes<<<NDOC * SS, 256>>>(raw_emb,  pPraw, 4194304LL);
    conv_planes<<<NBB * SS, 256>>>(post_dec, pPpd,  8388608LL);

    // ---- write-side encoder on raw_emb (8 docs) ----
    cudaMemcpyAsync(pX, raw_emb, (size_t)NDOC * SS * DD * sizeof(float),
                    cudaMemcpyDeviceToDevice, 0);
    run_encoder(pX, NDOC, pPraw, 4194304LL, pBW,
                pPW, encw_bqkv, encw_bo, encw_ln, encw_bff,
                pQKV, pK, pS, pPq, pPk, pPvt, pPp, pPbq, pPh, pPx);

    vgate_kernel<<<NDOC * SS, 256>>>(pX, raw_emb, W_ig, b_ig, pVd);
    // k = raw_emb @ W_k
    tg3(pPraw, 4194304LL, 0, pPW + 24LL * 262144, WLO, 0, nullptr, pKd, 0, 0, 0, 0,
        NDOC * SS, 512, 512, 1, 1.0f, 0);
    // S1[n] = questions @ k[n]^T * scD  (M=64 -> SIMT)
    sgemm_launch(questions, pKd, nullptr, pS, QQ, SS, DD, NDOC, 0, 524288, 65536, scD, 1);
    softmax_f32<<<NDOC * QQ, 256>>>(pS, pBW, SS, QQ);
    // A1S[n] = S1[n] @ v[n]  (M=64 -> SIMT)
    sgemm_launch(pS, pVd, nullptr, pA1, QQ, DD, SS, NDOC, 65536, 524288, 32768, 1.0f, 0);

    // ---- read-side encoder on post_dec (16 batches) ----
    cudaMemcpyAsync(pX, post_dec, (size_t)NBB * SS * DD * sizeof(float),
                    cudaMemcpyDeviceToDevice, 0);
    run_encoder(pX, NBB, pPpd, 8388608LL, pBR,
                pPW + 12LL * 262144, encr_bqkv, encr_bo, encr_ln, encr_bff,
                pQKV, pK, pS, pPq, pPk, pPvt, pPp, pPbq, pPh, pPx);

    // k2 = post_dec @ W_ok + b_ok
    tg3(pPpd, 8388608LL, 0, pPW + 25LL * 262144, WLO, 0, b_ok, pK2, 0, 0, 0, 0,
        NBB * SS, 512, 512, 1, 1.0f, 0);
    // a2 = softmax(k2 @ questions^T / 8)  (N=64 -> SIMT)
    sgemm_launch(pK2, questions, nullptr, pA2s, NBB * SS, QQ, DD, 1, 0, 0, 0, 0.125f, 1);
    softmax64_planes<<<NBB * SS / 8, 256>>>(pA2s, pPa2, 1048576LL);
    // selA^T planes (gathered by lookup): [64,512] -> [512,64]
    trans_conv<<<dim3(16, 2, 16), dim3(32, 8)>>>(pA1, pPsel, 524288, 64, 512, 32768, 32768, lookup);
    // A2[b] = a2[b] @ selA[b]
    tg3(pPa2, 1048576LL, 65536, pPsel, 524288LL, 32768, nullptr, pA2, 524288, 0, 0, 0,
        1024, 512, 64, NBB, 1.0f, 0);

    out_kernel<<<NBB * SS, 256>>>(pX, pA2, post_dec,
                                  W_u1, b_u1, W_u2, b_u2, b1,
                                  out, gate);

    (void)in_sizes; (void)n_in; (void)out_size;
}

// round 7
// speedup vs baseline: 2.1226x; 1.0096x over previous
#include <cuda_runtime.h>
#include <cuda_bf16.h>
#include <math.h>
#include <stdint.h>

#define DD     512
#define SS     1024
#define NBB    16
#define QQ     64
#define NDOC   8

__device__ float g_X   [16384 * 512];
__device__ float g_V   [16384 * 512];
__device__ float g_Kb  [16384 * 512];
__device__ float g_S   [16 * 1024 * 1024];
__device__ float g_Kdoc[8192 * 512];
__device__ float g_Vdoc[8192 * 512];
__device__ float g_A1S [8 * 64 * 512];
__device__ float g_A2SC[16384 * 64];
__device__ float g_A2  [16384 * 512];
__device__ float g_sin [1024 * 256];
__device__ float g_cos [1024 * 256];
__device__ float g_BIASW[8 * 1024];
__device__ float g_BIASR[16 * 1024];

#define WLO 6815744LL
#define LO  8388608LL
__device__ __align__(16) __nv_bfloat16 g_PW  [2 * 26 * 262144];
__device__ __align__(16) __nv_bfloat16 g_Praw[2 * 4194304];
__device__ __align__(16) __nv_bfloat16 g_Ppd [2 * 8388608];
__device__ __align__(16) __nv_bfloat16 g_Px  [2 * 8388608];
__device__ __align__(16) __nv_bfloat16 g_Pq  [2 * 8388608];
__device__ __align__(16) __nv_bfloat16 g_Pk  [2 * 8388608];
__device__ __align__(16) __nv_bfloat16 g_Pvt [2 * 8388608];
__device__ __align__(16) __nv_bfloat16 g_Pp  [2 * 16777216];
__device__ __align__(16) __nv_bfloat16 g_Pbq [2 * 8388608];
__device__ __align__(16) __nv_bfloat16 g_Ph  [2 * 8388608];
__device__ __align__(16) __nv_bfloat16 g_Pa2 [2 * 1048576];
__device__ __align__(16) __nv_bfloat16 g_Psel[2 * 524288];
__device__ __align__(16) __nv_bfloat16 g_Pqst[2 * 32768];

__device__ __forceinline__ uint32_t smem_u32(const void* p) {
    uint32_t a;
    asm("{ .reg .u64 t; cvta.to.shared.u64 t, %1; cvt.u32.u64 %0, t; }"
        : "=r"(a) : "l"(p));
    return a;
}

__device__ __forceinline__ void ldsm4(uint32_t* r, uint32_t addr) {
    asm volatile("ldmatrix.sync.aligned.m8n8.x4.shared.b16 {%0,%1,%2,%3}, [%4];"
                 : "=r"(r[0]), "=r"(r[1]), "=r"(r[2]), "=r"(r[3]) : "r"(addr));
}

__device__ __forceinline__ void mma_bf16(float* c, const uint32_t* a,
                                         uint32_t b0, uint32_t b1) {
    asm volatile(
        "mma.sync.aligned.m16n8k16.row.col.f32.bf16.bf16.f32 "
        "{%0,%1,%2,%3}, {%4,%5,%6,%7}, {%8,%9}, {%0,%1,%2,%3};"
        : "+f"(c[0]), "+f"(c[1]), "+f"(c[2]), "+f"(c[3])
        : "r"(a[0]), "r"(a[1]), "r"(a[2]), "r"(a[3]), "r"(b0), "r"(b1));
}

__device__ __forceinline__ void cpasync16(uint32_t dst, const void* src) {
    asm volatile("cp.async.cg.shared.global [%0], [%1], 16;" :: "r"(dst), "l"(src));
}
#define CP_COMMIT() asm volatile("cp.async.commit_group;" ::: "memory")
#define CP_WAIT(n)  asm volatile("cp.async.wait_group %0;" :: "n"(n) : "memory")

__device__ __forceinline__ void split_pair(float x0, float x1,
                                           __nv_bfloat162& h, __nv_bfloat162& l) {
    h = __floats2bfloat162_rn(x0, x1);
    l = __floats2bfloat162_rn(x0 - __bfloat162float(h.x),
                              x1 - __bfloat162float(h.y));
}

#define PLANE  10240
#define TSTAGE 40960
#define TG_SMEM (3 * 40960)

__global__ void __launch_bounds__(512)
tgemm3(const __nv_bfloat16* __restrict__ Ah0,
       const __nv_bfloat16* __restrict__ Bh0,
       const float* __restrict__ bias, float* __restrict__ Cf,
       __nv_bfloat16* __restrict__ Ch0, __nv_bfloat16* __restrict__ Ch2,
       int M, int N, int K,
       long long loA, long long loB, long long loC,
       long long sA, long long sB, long long sC, long long sCp,
       float alpha, int epi)
{
    extern __shared__ char smem[];
    const uint32_t sbu = smem_u32(smem);
    const int t = threadIdx.x, w = t >> 5, lane = t & 31;
    const int wm = w & 3, wn = w >> 2;
    const int z = blockIdx.z;
    const int m0 = blockIdx.y * 128, n0 = blockIdx.x * 128;

    const __nv_bfloat16* Ah = Ah0 + (size_t)z * sA;
    const __nv_bfloat16* Bh = Bh0 + (size_t)z * sB;

    const int lrow = t >> 2, seg = t & 3;
    const __nv_bfloat16* pr[4];
    pr[0] = Ah + (size_t)(m0 + lrow) * K + seg * 8;
    pr[1] = pr[0] + loA;
    pr[2] = Bh + (size_t)(n0 + lrow) * K + seg * 8;
    pr[3] = pr[2] + loB;

    float acc[2][4][4];
#pragma unroll
    for (int i = 0; i < 2; i++)
#pragma unroll
        for (int j = 0; j < 4; j++)
#pragma unroll
            for (int e = 0; e < 4; e++) acc[i][j][e] = 0.0f;

    const int nch = K >> 5;
    const uint32_t sdbase = sbu + (uint32_t)(lrow * 80 + seg * 16);

#define ISSUE(ch) do {                                                      \
    uint32_t _sd = sdbase + (uint32_t)((ch) % 3) * TSTAGE;                  \
    const int _cb = (ch) * 32;                                              \
    _Pragma("unroll")                                                       \
    for (int _p = 0; _p < 4; _p++)                                          \
        cpasync16(_sd + _p * PLANE, pr[_p] + _cb);                          \
    CP_COMMIT();                                                            \
} while (0)

    ISSUE(0);
    ISSUE(1);

    const uint32_t lmoff = (uint32_t)((lane & 15) * 80 + (lane >> 4) * 16);

    for (int ch = 0; ch < nch; ch++) {
        if (ch + 1 < nch) { CP_WAIT(1); } else { CP_WAIT(0); }
        __syncthreads();
        if (ch + 2 < nch) ISSUE(ch + 2);

        const uint32_t sAh = sbu + (uint32_t)(ch % 3) * TSTAGE;
        const uint32_t sBh = sAh + 2 * PLANE;
#pragma unroll
        for (int kk = 0; kk < 2; kk++) {
            uint32_t ah[2][4], al[2][4], bh[2][4], bl[2][4];
#pragma unroll
            for (int mt = 0; mt < 2; mt++) {
                uint32_t aaddr = sAh + (uint32_t)((wm * 32 + mt * 16) * 80 + kk * 32) + lmoff;
                ldsm4(ah[mt], aaddr);
                ldsm4(al[mt], aaddr + PLANE);
            }
#pragma unroll
            for (int ng = 0; ng < 2; ng++) {
                uint32_t baddr = sBh + (uint32_t)((wn * 32 + ng * 16) * 80 + kk * 32) + lmoff;
                ldsm4(bh[ng], baddr);
                ldsm4(bl[ng], baddr + PLANE);
            }
#pragma unroll
            for (int ng = 0; ng < 2; ng++)
#pragma unroll
                for (int mt = 0; mt < 2; mt++)
#pragma unroll
                    for (int h2 = 0; h2 < 2; h2++) {
                        float* c = acc[mt][ng * 2 + h2];
                        mma_bf16(c, ah[mt], bh[ng][h2], bh[ng][h2 + 2]);
                        mma_bf16(c, ah[mt], bl[ng][h2], bl[ng][h2 + 2]);
                        mma_bf16(c, al[mt], bh[ng][h2], bh[ng][h2 + 2]);
                    }
        }
    }
#undef ISSUE

    const float GC = 0.7978845608028654f;
    const int crow = m0 + wm * 32 + (lane >> 2);
    const int ccol = n0 + wn * 32 + (lane & 3) * 2;

    if (epi == 2) {
#pragma unroll
        for (int mt = 0; mt < 2; mt++) {
#pragma unroll
            for (int n8 = 0; n8 < 4; n8++) {
                const float* c = acc[mt][n8];
                const int col = ccol + n8 * 8;
                float b0 = bias[col], b1 = bias[col + 1];
#pragma unroll
                for (int h = 0; h < 2; h++) {
                    const int row = crow + mt * 16 + h * 8;
                    float x0 = c[h * 2 + 0] + b0;
                    float x1 = c[h * 2 + 1] + b1;
                    if (col < 1024) {
                        const int s = row & (SS - 1);
                        const int i = (col & 511) >> 1;
                        float sn = g_sin[s * 256 + i];
                        float cs = g_cos[s * 256 + i];
                        float y0 = x0 * cs - x1 * sn;
                        float y1 = x0 * sn + x1 * cs;
                        __nv_bfloat162 hh, ll;
                        split_pair(y0, y1, hh, ll);
                        __nv_bfloat16* dst = (col < 512) ? Ch0 : Ch2;
                        size_t off = (size_t)row * 512 + (col & 511);
                        *(__nv_bfloat162*)&dst[off] = hh;
                        *(__nv_bfloat162*)&(dst + loC)[off] = ll;
                    } else {
                        *(float2*)&Cf[(size_t)row * 512 + (col - 1024)] =
                            make_float2(x0, x1);
                    }
                }
            }
        }
        return;
    }

    float* Cfz = Cf ? Cf + (size_t)z * sC : (float*)0;
    __nv_bfloat16* Chz = Ch0 ? Ch0 + (size_t)z * sCp : (__nv_bfloat16*)0;
    __nv_bfloat16* Clz = Chz ? Chz + loC : (__nv_bfloat16*)0;
#pragma unroll
    for (int mt = 0; mt < 2; mt++) {
#pragma unroll
        for (int n8 = 0; n8 < 4; n8++) {
            const float* c = acc[mt][n8];
            const int col = ccol + n8 * 8;
            float b0 = bias ? bias[col]     : 0.0f;
            float b1 = bias ? bias[col + 1] : 0.0f;
#pragma unroll
            for (int h = 0; h < 2; h++) {
                const int row = crow + mt * 16 + h * 8;
                float x0 = c[h * 2 + 0] * alpha + b0;
                float x1 = c[h * 2 + 1] * alpha + b1;
                if (epi == 1) {
                    x0 = 0.5f * x0 * (1.0f + tanhf(GC * (x0 + 0.044715f * x0 * x0 * x0)));
                    x1 = 0.5f * x1 * (1.0f + tanhf(GC * (x1 + 0.044715f * x1 * x1 * x1)));
                }
                if (Cfz)
                    *(float2*)&Cfz[(size_t)row * N + col] = make_float2(x0, x1);
                if (Chz) {
                    __nv_bfloat162 hh, ll;
                    split_pair(x0, x1, hh, ll);
                    *(__nv_bfloat162*)&Chz[(size_t)row * N + col] = hh;
                    *(__nv_bfloat162*)&Clz[(size_t)row * N + col] = ll;
                }
            }
        }
    }
}

static void tg3(const __nv_bfloat16* Ah, long long loA, long long sA,
                const __nv_bfloat16* Bh, long long loB, long long sB,
                const float* bias, float* Cf, long long sC,
                __nv_bfloat16* Ch, __nv_bfloat16* Ch2, long long loC, long long sCp,
                int M, int N, int K, int batch, float alpha, int epi)
{
    dim3 grid(N / 128, M / 128, batch);
    tgemm3<<<grid, 512, TG_SMEM>>>(Ah, Bh, bias, Cf, Ch, Ch2, M, N, K,
                                   loA, loB, loC, sA, sB, sC, sCp, alpha, epi);
}

// N-tile 64 variant: 256 threads, 8 warps (4x2), tile 128x64
#define BPLANE  5120
#define BSTAGE  30720
#define TGN_SMEM (3 * 30720)

__global__ void __launch_bounds__(256)
tgemm3n64(const __nv_bfloat16* __restrict__ Ah0,
          const __nv_bfloat16* __restrict__ Bh0,
          const float* __restrict__ bias, float* __restrict__ Cf,
          int M, int N, int K,
          long long loA, long long loB,
          long long sA, long long sB, long long sC,
          float alpha)
{
    extern __shared__ char smem[];
    const uint32_t sbu = smem_u32(smem);
    const int t = threadIdx.x, w = t >> 5, lane = t & 31;
    const int wm = w & 3, wn = w >> 2;
    const int z = blockIdx.z;
    const int m0 = blockIdx.y * 128, n0 = blockIdx.x * 64;

    const __nv_bfloat16* Ah = Ah0 + (size_t)z * sA;
    const __nv_bfloat16* Bh = Bh0 + (size_t)z * sB;

    const int arow = t >> 1, aseg = (t & 1) * 2;
    const int brow = t >> 2, bseg = t & 3;
    const __nv_bfloat16* pa0 = Ah + (size_t)(m0 + arow) * K + aseg * 8;
    const __nv_bfloat16* pa1 = pa0 + loA;
    const __nv_bfloat16* pb0 = Bh + (size_t)(n0 + brow) * K + bseg * 8;
    const __nv_bfloat16* pb1 = pb0 + loB;

    const uint32_t adst = sbu + (uint32_t)(arow * 80 + aseg * 16);
    const uint32_t bdst = sbu + 20480u + (uint32_t)(brow * 80 + bseg * 16);

    float acc[2][4][4];
#pragma unroll
    for (int i = 0; i < 2; i++)
#pragma unroll
        for (int j = 0; j < 4; j++)
#pragma unroll
            for (int e = 0; e < 4; e++) acc[i][j][e] = 0.0f;

    const int nch = K >> 5;

#define ISSUEN(ch) do {                                                     \
    uint32_t _st = (uint32_t)((ch) % 3) * BSTAGE;                           \
    const int _cb = (ch) * 32;                                              \
    cpasync16(adst + _st,              pa0 + _cb);                          \
    cpasync16(adst + _st + 32,         pa0 + _cb + 16);                     \
    cpasync16(adst + _st + PLANE,      pa1 + _cb);                          \
    cpasync16(adst + _st + PLANE + 32, pa1 + _cb + 16);                     \
    cpasync16(bdst + _st,              pb0 + _cb);                          \
    cpasync16(bdst + _st + BPLANE,     pb1 + _cb);                          \
    CP_COMMIT();                                                            \
} while (0)

    ISSUEN(0);
    ISSUEN(1);

    const uint32_t lmoff = (uint32_t)((lane & 15) * 80 + (lane >> 4) * 16);

    for (int ch = 0; ch < nch; ch++) {
        if (ch + 1 < nch) { CP_WAIT(1); } else { CP_WAIT(0); }
        __syncthreads();
        if (ch + 2 < nch) ISSUEN(ch + 2);

        const uint32_t sAh = sbu + (uint32_t)(ch % 3) * BSTAGE;
        const uint32_t sBh = sAh + 20480u;
#pragma unroll
        for (int kk = 0; kk < 2; kk++) {
            uint32_t ah[2][4], al[2][4], bh[2][4], bl[2][4];
#pragma unroll
            for (int mt = 0; mt < 2; mt++) {
                uint32_t aaddr = sAh + (uint32_t)((wm * 32 + mt * 16) * 80 + kk * 32) + lmoff;
                ldsm4(ah[mt], aaddr);
                ldsm4(al[mt], aaddr + PLANE);
            }
#pragma unroll
            for (int ng = 0; ng < 2; ng++) {
                uint32_t baddr = sBh + (uint32_t)((wn * 32 + ng * 16) * 80 + kk * 32) + lmoff;
                ldsm4(bh[ng], baddr);
                ldsm4(bl[ng], baddr + BPLANE);
            }
#pragma unroll
            for (int ng = 0; ng < 2; ng++)
#pragma unroll
                for (int mt = 0; mt < 2; mt++)
#pragma unroll
                    for (int h2 = 0; h2 < 2; h2++) {
                        float* c = acc[mt][ng * 2 + h2];
                        mma_bf16(c, ah[mt], bh[ng][h2], bh[ng][h2 + 2]);
                        mma_bf16(c, ah[mt], bl[ng][h2], bl[ng][h2 + 2]);
                        mma_bf16(c, al[mt], bh[ng][h2], bh[ng][h2 + 2]);
                    }
        }
    }
#undef ISSUEN

    const int crow = m0 + wm * 32 + (lane >> 2);
    const int ccol = n0 + wn * 32 + (lane & 3) * 2;
    float* Cfz = Cf + (size_t)z * sC;
#pragma unroll
    for (int mt = 0; mt < 2; mt++)
#pragma unroll
        for (int n8 = 0; n8 < 4; n8++) {
            const float* c = acc[mt][n8];
            const int col = ccol + n8 * 8;
            float b0 = bias ? bias[col]     : 0.0f;
            float b1 = bias ? bias[col + 1] : 0.0f;
#pragma unroll
            for (int h = 0; h < 2; h++) {
                const int row = crow + mt * 16 + h * 8;
                float x0 = c[h * 2 + 0] * alpha + b0;
                float x1 = c[h * 2 + 1] * alpha + b1;
                *(float2*)&Cfz[(size_t)row * N + col] = make_float2(x0, x1);
            }
        }
}

__global__ void trans_conv(const float* __restrict__ in, __nv_bfloat16* __restrict__ oh,
                           long long loOff, int R, int C,
                           long long sI, long long sO, const int* __restrict__ ids)
{
    __shared__ float tile[32][33];
    const int z = blockIdx.z;
    size_t ib = ids ? (size_t)ids[z] * sI : (size_t)z * sI;
    const float* ip = in + ib;
    __nv_bfloat16* ohz = oh + (size_t)z * sO;
    __nv_bfloat16* olz = ohz + loOff;
    const int c0 = blockIdx.x * 32, r0 = blockIdx.y * 32;
    const int tx = threadIdx.x, ty = threadIdx.y;
#pragma unroll
    for (int k = 0; k < 32; k += 8)
        tile[ty + k][tx] = ip[(size_t)(r0 + ty + k) * C + c0 + tx];
    __syncthreads();
    const int rr = (tx & 15) * 2, chf = tx >> 4;
#pragma unroll
    for (int k = 0; k < 2; k++) {
        int cc = ty + chf * 8 + k * 16;
        __nv_bfloat162 h, l;
        split_pair(tile[rr][cc], tile[rr + 1][cc], h, l);
        *(__nv_bfloat162*)&ohz[(size_t)(c0 + cc) * R + r0 + rr] = h;
        *(__nv_bfloat162*)&olz[(size_t)(c0 + cc) * R + r0 + rr] = l;
    }
}

__global__ void conv_planes(const float* __restrict__ in, __nv_bfloat16* __restrict__ oh,
                            long long lo)
{
    size_t idx = (size_t)blockIdx.x * 512 + (size_t)threadIdx.x * 2;
    float2 v = *(const float2*)&in[idx];
    __nv_bfloat162 h, l;
    split_pair(v.x, v.y, h, l);
    *(__nv_bfloat162*)&oh[idx] = h;
    *(__nv_bfloat162*)&(oh + lo)[idx] = l;
}

__global__ void rope_table_kernel()
{
    int s = blockIdx.x;
    int i = threadIdx.x;
    float invf = 1.0f / powf(10000.0f, (float)i / 256.0f);
    float angf = (float)s * invf;
    double ang = (double)angf;
    g_sin[s * 256 + i] = (float)sin(ang);
    g_cos[s * 256 + i] = (float)cos(ang);
}

__global__ void bias_prep(const float* __restrict__ pos, float* __restrict__ out, int mode)
{
    int n = blockIdx.x, t = threadIdx.x;
    for (int c = t; c < 1024; c += 256) {
        float p = pos[n * 1024 + c];
        out[n * 1024 + c] = (mode == 1) ? logf(p) : (logf(p) - log1pf(-p));
    }
}

__global__ void softmax1024_planes(const float* __restrict__ S, const float* __restrict__ bias,
                                   __nv_bfloat16* __restrict__ oh, long long lo)
{
    const int row = blockIdx.x, t = threadIdx.x;
    const float* sr = S + (size_t)row * 1024;
    const float* pb = bias + (size_t)(row >> 10) * 1024;
    float2 a  = *(const float2*)&sr[2 * t];
    float2 b2 = *(const float2*)&sr[512 + 2 * t];
    float2 ba = *(const float2*)&pb[2 * t];
    float2 bb = *(const float2*)&pb[512 + 2 * t];
    float v0 = a.x + ba.x, v1 = a.y + ba.y, v2 = b2.x + bb.x, v3 = b2.y + bb.y;

    __shared__ float red[256];
    float mx = fmaxf(fmaxf(v0, v1), fmaxf(v2, v3));
    red[t] = mx; __syncthreads();
    for (int s = 128; s > 0; s >>= 1) { if (t < s) red[t] = fmaxf(red[t], red[t + s]); __syncthreads(); }
    mx = red[0]; __syncthreads();

    float e0 = expf(v0 - mx), e1 = expf(v1 - mx), e2 = expf(v2 - mx), e3 = expf(v3 - mx);
    red[t] = e0 + e1 + e2 + e3; __syncthreads();
    for (int s = 128; s > 0; s >>= 1) { if (t < s) red[t] += red[t + s]; __syncthreads(); }
    float inv = 1.0f / red[0];

    __nv_bfloat162 h, l;
    size_t o = (size_t)row * 1024 + 2 * t;
    split_pair(e0 * inv, e1 * inv, h, l);
    *(__nv_bfloat162*)&oh[o] = h;
    *(__nv_bfloat162*)&(oh + lo)[o] = l;
    split_pair(e2 * inv, e3 * inv, h, l);
    *(__nv_bfloat162*)&oh[o + 512] = h;
    *(__nv_bfloat162*)&(oh + lo)[o + 512] = l;
}

__global__ void softmax64_planes(const float* __restrict__ S, __nv_bfloat16* __restrict__ oh,
                                 long long lo)
{
    const int row = blockIdx.x * 8 + (threadIdx.x >> 5);
    const int lane = threadIdx.x & 31;
    const float* sr = S + (size_t)row * 64;
    float2 v = *(const float2*)&sr[lane * 2];
    float mx = fmaxf(v.x, v.y);
#pragma unroll
    for (int o = 16; o > 0; o >>= 1)
        mx = fmaxf(mx, __shfl_xor_sync(0xFFFFFFFF, mx, o));
    float e0 = expf(v.x - mx), e1 = expf(v.y - mx);
    float s = e0 + e1;
#pragma unroll
    for (int o = 16; o > 0; o >>= 1)
        s += __shfl_xor_sync(0xFFFFFFFF, s, o);
    float inv = 1.0f / s;
    __nv_bfloat162 h, l;
    split_pair(e0 * inv, e1 * inv, h, l);
    size_t o2 = (size_t)row * 64 + lane * 2;
    *(__nv_bfloat162*)&oh[o2] = h;
    *(__nv_bfloat162*)&(oh + lo)[o2] = l;
}

__global__ void softmax_f32(float* __restrict__ S, const float* __restrict__ bias,
                            int cols, int rpb)
{
    int row = blockIdx.x;
    float* sr = S + (size_t)row * cols;
    const float* pb = bias + (size_t)(row / rpb) * cols;
    int t = threadIdx.x;
    __shared__ float red[256];

    float mx = -1e30f;
    for (int c = t; c < cols; c += 256) {
        float v = sr[c] + pb[c];
        sr[c] = v;
        mx = fmaxf(mx, v);
    }
    red[t] = mx; __syncthreads();
    for (int s = 128; s > 0; s >>= 1) { if (t < s) red[t] = fmaxf(red[t], red[t + s]); __syncthreads(); }
    mx = red[0]; __syncthreads();

    float sum = 0.0f;
    for (int c = t; c < cols; c += 256) {
        float e = expf(sr[c] - mx);
        sr[c] = e;
        sum += e;
    }
    red[t] = sum; __syncthreads();
    for (int s = 128; s > 0; s >>= 1) { if (t < s) red[t] += red[t + s]; __syncthreads(); }
    float inv = 1.0f / red[0];
    for (int c = t; c < cols; c += 256) sr[c] *= inv;
}

__global__ void ln_kernel(const float* __restrict__ Xin, const float* __restrict__ R,
                          const float* __restrict__ g, const float* __restrict__ b,
                          float* __restrict__ Xout,
                          __nv_bfloat16* __restrict__ oh, long long lo)
{
    int row = blockIdx.x;
    int t   = threadIdx.x;
    const float* xr = Xin + (size_t)row * DD;
    const float* rr = R + (size_t)row * DD;

    float v0 = xr[2 * t] + rr[2 * t];
    float v1 = xr[2 * t + 1] + rr[2 * t + 1];

    __shared__ float red[256];
    red[t] = v0 + v1; __syncthreads();
    for (int s = 128; s > 0; s >>= 1) { if (t < s) red[t] += red[t + s]; __syncthreads(); }
    float m = red[0] * (1.0f / 512.0f);
    __syncthreads();

    float d0 = v0 - m, d1 = v1 - m;
    red[t] = d0 * d0 + d1 * d1; __syncthreads();
    for (int s = 128; s > 0; s >>= 1) { if (t < s) red[t] += red[t + s]; __syncthreads(); }
    float var = red[0] * (1.0f / 512.0f);
    float inv = rsqrtf(var + 1e-5f);

    float o0 = d0 * inv * g[2 * t]     + b[2 * t];
    float o1 = d1 * inv * g[2 * t + 1] + b[2 * t + 1];
    float* xo = Xout + (size_t)row * DD;
    xo[2 * t]     = o0;
    xo[2 * t + 1] = o1;

    __nv_bfloat162 h, l;
    split_pair(o0, o1, h, l);
    size_t o = (size_t)row * DD + 2 * t;
    *(__nv_bfloat162*)&oh[o] = h;
    *(__nv_bfloat162*)&(oh + lo)[o] = l;
}

__global__ void vgate_kernel(const float* __restrict__ F, const float* __restrict__ raw,
                             const float* __restrict__ Wig, const float* __restrict__ big,
                             float* __restrict__ V)
{
    int row = blockIdx.x;
    int t   = threadIdx.x;
    const float* fr = F + (size_t)row * DD;
    __shared__ float red[256];
    float s = fr[t] * Wig[t] + fr[t + 256] * Wig[t + 256];
    red[t] = s; __syncthreads();
    for (int k = 128; k > 0; k >>= 1) { if (t < k) red[t] += red[t + k]; __syncthreads(); }
    float gte = 1.0f / (1.0f + expf(-(red[0] + big[0])));
    const float* rr = raw + (size_t)row * DD;
    float* vr = V + (size_t)row * DD;
    vr[t]       = rr[t]       * gte;
    vr[t + 256] = rr[t + 256] * gte;
}

__global__ void out_kernel(const float* __restrict__ FU, const float* __restrict__ A2,
                           const float* __restrict__ PD,
                           const float* __restrict__ Wu1, const float* __restrict__ bu1,
                           const float* __restrict__ Wu2, const float* __restrict__ bu2,
                           const float* __restrict__ b1,
                           float* __restrict__ out, float* __restrict__ gate)
{
    int row = blockIdx.x;
    int t   = threadIdx.x;
    const float* fu = FU + (size_t)row * DD;
    const float* a2 = A2 + (size_t)row * DD;
    const float* pd = PD + (size_t)row * DD;

    __shared__ float red[256];
    float s = fu[t] * Wu1[t] + fu[t + 256] * Wu1[t + 256]
            + a2[t] * Wu2[t] + a2[t + 256] * Wu2[t + 256];
    red[t] = s; __syncthreads();
    for (int k = 128; k > 0; k >>= 1) { if (t < k) red[t] += red[t + k]; __syncthreads(); }
    float z = red[0] + bu1[0] + bu2[0] + b1[0] - 4.0f;
    float g = 1.0f / (1.0f + expf(-z));

    float* orow = out + (size_t)row * DD;
    orow[t]       = pd[t]       * (1.0f - g) + a2[t]       * g;
    orow[t + 256] = pd[t + 256] * (1.0f - g) + a2[t + 256] * g;
    if (t == 0) gate[row] = g;
}

#define BM 64
#define BN 64
#define BK 16

__global__ void gemm_kernel(const float* __restrict__ A,
                            const float* __restrict__ Bm,
                            const float* __restrict__ bias,
                            float* __restrict__ C,
                            int M, int N, int K,
                            long long sA, long long sB, long long sC,
                            float alpha, int transB, int epi)
{
    const int bz = blockIdx.z;
    A  += (size_t)bz * sA;
    Bm += (size_t)bz * sB;
    C  += (size_t)bz * sC;

    const int m0 = blockIdx.y * BM;
    const int n0 = blockIdx.x * BN;

    __shared__ float As[BK][BM + 4];
    __shared__ float Bs[BK][BN + 4];

    const int t  = threadIdx.x;
    const int tx = t & 15;
    const int ty = t >> 4;

    float acc[4][4] = {};

    const int arow = t >> 2;
    const int akc  = (t & 3) * 4;
    const int kb   = t >> 4;
    const int nb   = (t & 15) * 4;

    for (int k0 = 0; k0 < K; k0 += BK) {
        float4 av = *(const float4*)&A[(size_t)(m0 + arow) * K + k0 + akc];
        As[akc + 0][arow] = av.x;
        As[akc + 1][arow] = av.y;
        As[akc + 2][arow] = av.z;
        As[akc + 3][arow] = av.w;

        if (!transB) {
            float4 bv = *(const float4*)&Bm[(size_t)(k0 + kb) * N + n0 + nb];
            *(float4*)&Bs[kb][nb] = bv;
        } else {
            float4 bv = *(const float4*)&Bm[(size_t)(n0 + arow) * K + k0 + akc];
            Bs[akc + 0][arow] = bv.x;
            Bs[akc + 1][arow] = bv.y;
            Bs[akc + 2][arow] = bv.z;
            Bs[akc + 3][arow] = bv.w;
        }
        __syncthreads();

#pragma unroll
        for (int k = 0; k < BK; k++) {
            float4 a = *(const float4*)&As[k][ty * 4];
            float4 b = *(const float4*)&Bs[k][tx * 4];
            acc[0][0] += a.x * b.x; acc[0][1] += a.x * b.y;
            acc[0][2] += a.x * b.z; acc[0][3] += a.x * b.w;
            acc[1][0] += a.y * b.x; acc[1][1] += a.y * b.y;
            acc[1][2] += a.y * b.z; acc[1][3] += a.y * b.w;
            acc[2][0] += a.z * b.x; acc[2][1] += a.z * b.y;
            acc[2][2] += a.z * b.z; acc[2][3] += a.z * b.w;
            acc[3][0] += a.w * b.x; acc[3][1] += a.w * b.y;
            acc[3][2] += a.w * b.z; acc[3][3] += a.w * b.w;
        }
        __syncthreads();
    }

#pragma unroll
    for (int i = 0; i < 4; i++) {
        const int row = m0 + ty * 4 + i;
        float v[4];
#pragma unroll
        for (int j = 0; j < 4; j++) {
            float x = acc[i][j] * alpha;
            if (bias) x += bias[n0 + tx * 4 + j];
            v[j] = x;
        }
        *(float4*)&C[(size_t)row * N + n0 + tx * 4] = make_float4(v[0], v[1], v[2], v[3]);
    }
}

static void sgemm_launch(const float* A, const float* B, const float* bias, float* C,
                         int M, int N, int K, int batch,
                         long long sA, long long sB, long long sC,
                         float alpha, int transB)
{
    dim3 grid(N / BN, M / BM, batch);
    gemm_kernel<<<grid, 256>>>(A, B, bias, C, M, N, K, sA, sB, sC, alpha, transB, 0);
}

static void run_encoder(const float* Xin0, float* X, int nb,
                        const __nv_bfloat16* initP, long long initLo,
                        const float* biasRows,
                        const __nv_bfloat16* PW,
                        const float* bqkv, const float* bo,
                        const float* ln, const float* bff,
                        float* bV, float* bK, float* bS,
                        __nv_bfloat16* Pq, __nv_bfloat16* Pk, __nv_bfloat16* Pvt,
                        __nv_bfloat16* Pp, __nv_bfloat16* Pbq, __nv_bfloat16* Ph,
                        __nv_bfloat16* Px, int skip_first_qkv)
{
    const int rows = nb * SS;
    const float sc = 1.0f / sqrtf((float)DD);
    for (int l = 0; l < 2; l++) {
        const __nv_bfloat16* AP = (l == 0) ? initP : Px;
        const long long loAP = (l == 0) ? initLo : LO;
        if (!(l == 0 && skip_first_qkv))
            tg3(AP, loAP, 0, PW + (size_t)(l * 3) * 262144, WLO, 0,
                bqkv + (size_t)l * 1536, bV, 0, Pq, Pk, LO, 0,
                rows, 1536, 512, 1, 1.0f, 2);
        trans_conv<<<dim3(16, 32, nb), dim3(32, 8)>>>(bV, Pvt, LO, 1024, 512,
                                                      524288, 524288, nullptr);
        tg3(Pq, LO, 524288, Pk, LO, 524288, nullptr, bS, 1048576,
            nullptr, nullptr, 0, 0, 1024, 1024, 512, nb, sc, 0);
        softmax1024_planes<<<rows, 256>>>(bS, biasRows, Pp, 16777216LL);
        tg3(Pp, 16777216LL, 1048576, Pvt, LO, 524288, nullptr, nullptr, 0,
            Pbq, nullptr, LO, 524288, 1024, 512, 1024, nb, 1.0f, 0);
        tg3(Pbq, LO, 0, PW + (size_t)(6 + l) * 262144, WLO, 0, bo + l * 512,
            bK, 0, nullptr, nullptr, 0, 0, rows, 512, 512, 1, 1.0f, 0);
        ln_kernel<<<rows, 256>>>((l == 0) ? Xin0 : X, bK,
                                 ln + l * 2048, ln + l * 2048 + 512, X, Px, LO);
        tg3(Px, LO, 0, PW + (size_t)(8 + 2 * l) * 262144, WLO, 0, bff + l * 1024,
            nullptr, 0, Ph, nullptr, LO, 0, rows, 512, 512, 1, 1.0f, 1);
        tg3(Ph, LO, 0, PW + (size_t)(9 + 2 * l) * 262144, WLO, 0, bff + l * 1024 + 512,
            bK, 0, nullptr, nullptr, 0, 0, rows, 512, 512, 1, 1.0f, 0);
        ln_kernel<<<rows, 256>>>(X, bK, ln + l * 2048 + 1024, ln + l * 2048 + 1536,
                                 X, Px, LO);
    }
}

extern "C" void kernel_launch(void* const* d_in, const int* in_sizes, int n_in,
                              void* d_out, int out_size)
{
    const float* raw_emb   = (const float*)d_in[0];
    const float* pos_w     = (const float*)d_in[1];
    const float* post_dec  = (const float*)d_in[2];
    const float* pos_r     = (const float*)d_in[3];
    const float* questions = (const float*)d_in[4];
    const float* W_k       = (const float*)d_in[5];
    const float* W_ig      = (const float*)d_in[6];
    const float* b_ig      = (const float*)d_in[7];
    const float* W_u1      = (const float*)d_in[8];
    const float* b_u1      = (const float*)d_in[9];
    const float* W_u2      = (const float*)d_in[10];
    const float* b_u2      = (const float*)d_in[11];
    const float* b1        = (const float*)d_in[12];
    const float* W_ok      = (const float*)d_in[13];
    const float* b_ok      = (const float*)d_in[14];
    const float* encw_Wqkv = (const float*)d_in[15];
    const float* encw_bqkv = (const float*)d_in[16];
    const float* encw_Wo   = (const float*)d_in[17];
    const float* encw_bo   = (const float*)d_in[18];
    const float* encw_ln   = (const float*)d_in[19];
    const float* encw_Wff  = (const float*)d_in[20];
    const float* encw_bff  = (const float*)d_in[21];
    const float* encr_Wqkv = (const float*)d_in[22];
    const float* encr_bqkv = (const float*)d_in[23];
    const float* encr_Wo   = (const float*)d_in[24];
    const float* encr_bo   = (const float*)d_in[25];
    const float* encr_ln   = (const float*)d_in[26];
    const float* encr_Wff  = (const float*)d_in[27];
    const float* encr_bff  = (const float*)d_in[28];
    const int*   lookup    = (const int*)d_in[29];

    float* out  = (float*)d_out;
    float* gate = out + (size_t)NBB * SS * DD;

    float *pX, *pV, *pK, *pS, *pKd, *pVd, *pA1, *pA2s, *pA2, *pBW, *pBR;
    __nv_bfloat16 *pPW, *pPraw, *pPpd, *pPx, *pPq, *pPk, *pPvt, *pPp, *pPbq, *pPh,
                  *pPa2, *pPsel, *pPqst;
    cudaGetSymbolAddress((void**)&pX,    g_X);
    cudaGetSymbolAddress((void**)&pV,    g_V);
    cudaGetSymbolAddress((void**)&pK,    g_Kb);
    cudaGetSymbolAddress((void**)&pS,    g_S);
    cudaGetSymbolAddress((void**)&pKd,   g_Kdoc);
    cudaGetSymbolAddress((void**)&pVd,   g_Vdoc);
    cudaGetSymbolAddress((void**)&pA1,   g_A1S);
    cudaGetSymbolAddress((void**)&pA2s,  g_A2SC);
    cudaGetSymbolAddress((void**)&pA2,   g_A2);
    cudaGetSymbolAddress((void**)&pBW,   g_BIASW);
    cudaGetSymbolAddress((void**)&pBR,   g_BIASR);
    cudaGetSymbolAddress((void**)&pPW,   g_PW);
    cudaGetSymbolAddress((void**)&pPraw, g_Praw);
    cudaGetSymbolAddress((void**)&pPpd,  g_Ppd);
    cudaGetSymbolAddress((void**)&pPx,   g_Px);
    cudaGetSymbolAddress((void**)&pPq,   g_Pq);
    cudaGetSymbolAddress((void**)&pPk,   g_Pk);
    cudaGetSymbolAddress((void**)&pPvt,  g_Pvt);
    cudaGetSymbolAddress((void**)&pPp,   g_Pp);
    cudaGetSymbolAddress((void**)&pPbq,  g_Pbq);
    cudaGetSymbolAddress((void**)&pPh,   g_Ph);
    cudaGetSymbolAddress((void**)&pPa2,  g_Pa2);
    cudaGetSymbolAddress((void**)&pPsel, g_Psel);
    cudaGetSymbolAddress((void**)&pPqst, g_Pqst);

    cudaFuncSetAttribute(tgemm3,    cudaFuncAttributeMaxDynamicSharedMemorySize, TG_SMEM);
    cudaFuncSetAttribute(tgemm3n64, cudaFuncAttributeMaxDynamicSharedMemorySize, TGN_SMEM);

    const float scD = 1.0f / sqrtf((float)DD);

    // prep ordered so launch idx 5 = first big tgemm3 (for ncu -s 5)
    trans_conv<<<dim3(16, 16, 6), dim3(32, 8)>>>(encw_Wqkv, pPW + 0LL  * 262144, WLO, 512, 512, 262144, 262144, nullptr);
    conv_planes<<<NDOC * SS, 256>>>(raw_emb, pPraw, 4194304LL);
    rope_table_kernel<<<1024, 256>>>();
    trans_conv<<<dim3(16, 16, 2), dim3(32, 8)>>>(encw_Wo,   pPW + 6LL  * 262144, WLO, 512, 512, 262144, 262144, nullptr);
    trans_conv<<<dim3(16, 16, 4), dim3(32, 8)>>>(encw_Wff,  pPW + 8LL  * 262144, WLO, 512, 512, 262144, 262144, nullptr);

    // write-side encoder (first QKV = launch idx 5)
    tg3(pPraw, 4194304LL, 0, pPW, WLO, 0, encw_bqkv, pV, 0, pPq, pPk, LO, 0,
        NDOC * SS, 1536, 512, 1, 1.0f, 2);
    bias_prep<<<NDOC, 256>>>(pos_w, pBW, 1);
    run_encoder(raw_emb, pX, NDOC, pPraw, 4194304LL, pBW,
                pPW, encw_bqkv, encw_bo, encw_ln, encw_bff,
                pV, pK, pS, pPq, pPk, pPvt, pPp, pPbq, pPh, pPx, 1);

    vgate_kernel<<<NDOC * SS, 256>>>(pX, raw_emb, W_ig, b_ig, pVd);
    trans_conv<<<dim3(16, 16, 1), dim3(32, 8)>>>(W_k, pPW + 24LL * 262144, WLO, 512, 512, 262144, 262144, nullptr);
    tg3(pPraw, 4194304LL, 0, pPW + 24LL * 262144, WLO, 0, nullptr, pKd, 0,
        nullptr, nullptr, 0, 0, NDOC * SS, 512, 512, 1, 1.0f, 0);
    sgemm_launch(questions, pKd, nullptr, pS, QQ, SS, DD, NDOC, 0, 524288, 65536, scD, 1);
    softmax_f32<<<NDOC * QQ, 256>>>(pS, pBW, SS, QQ);
    sgemm_launch(pS, pVd, nullptr, pA1, QQ, DD, SS, NDOC, 65536, 524288, 32768, 1.0f, 0);

    // read-side encoder
    trans_conv<<<dim3(16, 16, 6), dim3(32, 8)>>>(encr_Wqkv, pPW + 12LL * 262144, WLO, 512, 512, 262144, 262144, nullptr);
    trans_conv<<<dim3(16, 16, 2), dim3(32, 8)>>>(encr_Wo,   pPW + 18LL * 262144, WLO, 512, 512, 262144, 262144, nullptr);
    trans_conv<<<dim3(16, 16, 4), dim3(32, 8)>>>(encr_Wff,  pPW + 20LL * 262144, WLO, 512, 512, 262144, 262144, nullptr);
    conv_planes<<<NBB * SS, 256>>>(post_dec, pPpd, 8388608LL);
    bias_prep<<<NBB, 256>>>(pos_r, pBR, 2);
    run_encoder(post_dec, pX, NBB, pPpd, 8388608LL, pBR,
                pPW + 12LL * 262144, encr_bqkv, encr_bo, encr_ln, encr_bff,
                pV, pK, pS, pPq, pPk, pPvt, pPp, pPbq, pPh, pPx, 0);

    // k2 / a2 / A2 / out
    trans_conv<<<dim3(16, 16, 1), dim3(32, 8)>>>(W_ok, pPW + 25LL * 262144, WLO, 512, 512, 262144, 262144, nullptr);
    conv_planes<<<QQ, 256>>>(questions, pPqst, 32768LL);
    tg3(pPpd, 8388608LL, 0, pPW + 25LL * 262144, WLO, 0, b_ok, nullptr, 0,
        pPq, nullptr, LO, 0, NBB * SS, 512, 512, 1, 1.0f, 0);
    {
        dim3 grid(1, (NBB * SS) / 128, 1);
        tgemm3n64<<<grid, 256, TGN_SMEM>>>(pPq, pPqst, nullptr, pA2s,
                                           NBB * SS, QQ, DD, LO, 32768LL,
                                           0, 0, 0, 0.125f);
    }
    softmax64_planes<<<NBB * SS / 8, 256>>>(pA2s, pPa2, 1048576LL);
    trans_conv<<<dim3(16, 2, 16), dim3(32, 8)>>>(pA1, pPsel, 524288, 64, 512, 32768, 32768, lookup);
    tg3(pPa2, 1048576LL, 65536, pPsel, 524288LL, 32768, nullptr, pA2, 524288,
        nullptr, nullptr, 0, 0, 1024, 512, 64, NBB, 1.0f, 0);

    out_kernel<<<NBB * SS, 256>>>(pX, pA2, post_dec,
                                  W_u1, b_u1, W_u2, b_u2, b1,
                                  out, gate);

    (void)in_sizes; (void)n_in; (void)out_size;
}

// round 8
// speedup vs baseline: 2.1395x; 1.0080x over previous
#include <cuda_runtime.h>
#include <cuda_bf16.h>
#include <math.h>
#include <stdint.h>

#define DD     512
#define SS     1024
#define NBB    16
#define QQ     64
#define NDOC   8

__device__ float g_X   [16384 * 512];
__device__ float g_V   [16384 * 512];
__device__ float g_Kb  [16384 * 512];
__device__ float g_S   [16 * 1024 * 1024];
__device__ float g_Kdoc[8192 * 512];
__device__ float g_Vdoc[8192 * 512];
__device__ float g_A1S [8 * 64 * 512];
__device__ float g_A2SC[16384 * 64];
__device__ float g_A2  [16384 * 512];
__device__ float g_sin [1024 * 256];
__device__ float g_cos [1024 * 256];
__device__ float g_BIASW[8 * 1024];
__device__ float g_BIASR[16 * 1024];

#define WLO 6815744LL
#define LO  8388608LL
__device__ __align__(16) __nv_bfloat16 g_PW  [2 * 26 * 262144];
__device__ __align__(16) __nv_bfloat16 g_Praw[2 * 4194304];
__device__ __align__(16) __nv_bfloat16 g_Ppd [2 * 8388608];
__device__ __align__(16) __nv_bfloat16 g_Px  [2 * 8388608];
__device__ __align__(16) __nv_bfloat16 g_Pq  [2 * 8388608];
__device__ __align__(16) __nv_bfloat16 g_Pk  [2 * 8388608];
__device__ __align__(16) __nv_bfloat16 g_Pvt [2 * 8388608];
__device__ __align__(16) __nv_bfloat16 g_Pp  [2 * 16777216];
__device__ __align__(16) __nv_bfloat16 g_Pbq [2 * 8388608];
__device__ __align__(16) __nv_bfloat16 g_Ph  [2 * 8388608];
__device__ __align__(16) __nv_bfloat16 g_Pa2 [2 * 1048576];
__device__ __align__(16) __nv_bfloat16 g_Psel[2 * 524288];
__device__ __align__(16) __nv_bfloat16 g_Pqst[2 * 32768];

__device__ __forceinline__ uint32_t smem_u32(const void* p) {
    uint32_t a;
    asm("{ .reg .u64 t; cvta.to.shared.u64 t, %1; cvt.u32.u64 %0, t; }"
        : "=r"(a) : "l"(p));
    return a;
}

__device__ __forceinline__ void ldsm4(uint32_t* r, uint32_t addr) {
    asm volatile("ldmatrix.sync.aligned.m8n8.x4.shared.b16 {%0,%1,%2,%3}, [%4];"
                 : "=r"(r[0]), "=r"(r[1]), "=r"(r[2]), "=r"(r[3]) : "r"(addr));
}

__device__ __forceinline__ void mma_bf16(float* c, const uint32_t* a,
                                         uint32_t b0, uint32_t b1) {
    asm volatile(
        "mma.sync.aligned.m16n8k16.row.col.f32.bf16.bf16.f32 "
        "{%0,%1,%2,%3}, {%4,%5,%6,%7}, {%8,%9}, {%0,%1,%2,%3};"
        : "+f"(c[0]), "+f"(c[1]), "+f"(c[2]), "+f"(c[3])
        : "r"(a[0]), "r"(a[1]), "r"(a[2]), "r"(a[3]), "r"(b0), "r"(b1));
}

__device__ __forceinline__ void cpasync16(uint32_t dst, const void* src) {
    asm volatile("cp.async.cg.shared.global [%0], [%1], 16;" :: "r"(dst), "l"(src));
}
#define CP_COMMIT() asm volatile("cp.async.commit_group;" ::: "memory")
#define CP_WAIT(n)  asm volatile("cp.async.wait_group %0;" :: "n"(n) : "memory")

__device__ __forceinline__ void split_pair(float x0, float x1,
                                           __nv_bfloat162& h, __nv_bfloat162& l) {
    h = __floats2bfloat162_rn(x0, x1);
    l = __floats2bfloat162_rn(x0 - __bfloat162float(h.x),
                              x1 - __bfloat162float(h.y));
}

#define PLANE  10240
#define TSTAGE 40960
#define TG_SMEM (4 * 40960)

__global__ void __launch_bounds__(512)
tgemm3(const __nv_bfloat16* __restrict__ Ah0,
       const __nv_bfloat16* __restrict__ Bh0,
       const float* __restrict__ bias, float* __restrict__ Cf,
       __nv_bfloat16* __restrict__ Ch0, __nv_bfloat16* __restrict__ Ch2,
       int M, int N, int K,
       long long loA, long long loB, long long loC,
       long long sA, long long sB, long long sC, long long sCp,
       float alpha, int epi)
{
    extern __shared__ char smem[];
    const uint32_t sbu = smem_u32(smem);
    const int t = threadIdx.x, w = t >> 5, lane = t & 31;
    const int wm = w & 3, wn = w >> 2;
    const int z = blockIdx.z;
    const int m0 = blockIdx.y * 128, n0 = blockIdx.x * 128;

    const __nv_bfloat16* Ah = Ah0 + (size_t)z * sA;
    const __nv_bfloat16* Bh = Bh0 + (size_t)z * sB;

    const int lrow = t >> 2, seg = t & 3;
    const __nv_bfloat16* pr[4];
    pr[0] = Ah + (size_t)(m0 + lrow) * K + seg * 8;
    pr[1] = pr[0] + loA;
    pr[2] = Bh + (size_t)(n0 + lrow) * K + seg * 8;
    pr[3] = pr[2] + loB;

    float acc[2][4][4];
#pragma unroll
    for (int i = 0; i < 2; i++)
#pragma unroll
        for (int j = 0; j < 4; j++)
#pragma unroll
            for (int e = 0; e < 4; e++) acc[i][j][e] = 0.0f;

    const int nch = K >> 5;
    const uint32_t sdbase = sbu + (uint32_t)(lrow * 80 + seg * 16);

#define ISSUE(ch) do {                                                      \
    uint32_t _sd = sdbase + (uint32_t)((ch) & 3) * TSTAGE;                  \
    const int _cb = (ch) * 32;                                              \
    _Pragma("unroll")                                                       \
    for (int _p = 0; _p < 4; _p++)                                          \
        cpasync16(_sd + _p * PLANE, pr[_p] + _cb);                          \
    CP_COMMIT();                                                            \
} while (0)

    ISSUE(0);
    ISSUE(1);
    if (nch > 2) ISSUE(2);

    const uint32_t lmoff = (uint32_t)((lane & 15) * 80 + (lane >> 4) * 16);

    for (int ch = 0; ch < nch; ch++) {
        const int rem = nch - 1 - ch;
        if (rem >= 2)      { CP_WAIT(2); }
        else if (rem == 1) { CP_WAIT(1); }
        else               { CP_WAIT(0); }
        __syncthreads();
        if (ch + 3 < nch) ISSUE(ch + 3);

        const uint32_t sAh = sbu + (uint32_t)(ch & 3) * TSTAGE;
        const uint32_t sBh = sAh + 2 * PLANE;
#pragma unroll
        for (int kk = 0; kk < 2; kk++) {
            uint32_t ah[2][4], al[2][4], bh[2][4], bl[2][4];
#pragma unroll
            for (int mt = 0; mt < 2; mt++) {
                uint32_t aaddr = sAh + (uint32_t)((wm * 32 + mt * 16) * 80 + kk * 32) + lmoff;
                ldsm4(ah[mt], aaddr);
                ldsm4(al[mt], aaddr + PLANE);
            }
#pragma unroll
            for (int ng = 0; ng < 2; ng++) {
                uint32_t baddr = sBh + (uint32_t)((wn * 32 + ng * 16) * 80 + kk * 32) + lmoff;
                ldsm4(bh[ng], baddr);
                ldsm4(bl[ng], baddr + PLANE);
            }
            // term-major: 8 independent accumulators between dependent reuses
#pragma unroll
            for (int ng = 0; ng < 2; ng++)
#pragma unroll
                for (int mt = 0; mt < 2; mt++)
#pragma unroll
                    for (int h2 = 0; h2 < 2; h2++)
                        mma_bf16(acc[mt][ng * 2 + h2], ah[mt], bh[ng][h2], bh[ng][h2 + 2]);
#pragma unroll
            for (int ng = 0; ng < 2; ng++)
#pragma unroll
                for (int mt = 0; mt < 2; mt++)
#pragma unroll
                    for (int h2 = 0; h2 < 2; h2++)
                        mma_bf16(acc[mt][ng * 2 + h2], ah[mt], bl[ng][h2], bl[ng][h2 + 2]);
#pragma unroll
            for (int ng = 0; ng < 2; ng++)
#pragma unroll
                for (int mt = 0; mt < 2; mt++)
#pragma unroll
                    for (int h2 = 0; h2 < 2; h2++)
                        mma_bf16(acc[mt][ng * 2 + h2], al[mt], bh[ng][h2], bh[ng][h2 + 2]);
        }
    }
#undef ISSUE

    const float GC = 0.7978845608028654f;
    const int crow = m0 + wm * 32 + (lane >> 2);
    const int ccol = n0 + wn * 32 + (lane & 3) * 2;

    if (epi == 2) {
#pragma unroll
        for (int mt = 0; mt < 2; mt++) {
#pragma unroll
            for (int n8 = 0; n8 < 4; n8++) {
                const float* c = acc[mt][n8];
                const int col = ccol + n8 * 8;
                float b0 = bias[col], b1 = bias[col + 1];
#pragma unroll
                for (int h = 0; h < 2; h++) {
                    const int row = crow + mt * 16 + h * 8;
                    float x0 = c[h * 2 + 0] + b0;
                    float x1 = c[h * 2 + 1] + b1;
                    if (col < 1024) {
                        const int s = row & (SS - 1);
                        const int i = (col & 511) >> 1;
                        float sn = g_sin[s * 256 + i];
                        float cs = g_cos[s * 256 + i];
                        float y0 = x0 * cs - x1 * sn;
                        float y1 = x0 * sn + x1 * cs;
                        __nv_bfloat162 hh, ll;
                        split_pair(y0, y1, hh, ll);
                        __nv_bfloat16* dst = (col < 512) ? Ch0 : Ch2;
                        size_t off = (size_t)row * 512 + (col & 511);
                        *(__nv_bfloat162*)&dst[off] = hh;
                        *(__nv_bfloat162*)&(dst + loC)[off] = ll;
                    } else {
                        *(float2*)&Cf[(size_t)row * 512 + (col - 1024)] =
                            make_float2(x0, x1);
                    }
                }
            }
        }
        return;
    }

    float* Cfz = Cf ? Cf + (size_t)z * sC : (float*)0;
    __nv_bfloat16* Chz = Ch0 ? Ch0 + (size_t)z * sCp : (__nv_bfloat16*)0;
    __nv_bfloat16* Clz = Chz ? Chz + loC : (__nv_bfloat16*)0;
#pragma unroll
    for (int mt = 0; mt < 2; mt++) {
#pragma unroll
        for (int n8 = 0; n8 < 4; n8++) {
            const float* c = acc[mt][n8];
            const int col = ccol + n8 * 8;
            float b0 = bias ? bias[col]     : 0.0f;
            float b1 = bias ? bias[col + 1] : 0.0f;
#pragma unroll
            for (int h = 0; h < 2; h++) {
                const int row = crow + mt * 16 + h * 8;
                float x0 = c[h * 2 + 0] * alpha + b0;
                float x1 = c[h * 2 + 1] * alpha + b1;
                if (epi == 1) {
                    x0 = 0.5f * x0 * (1.0f + tanhf(GC * (x0 + 0.044715f * x0 * x0 * x0)));
                    x1 = 0.5f * x1 * (1.0f + tanhf(GC * (x1 + 0.044715f * x1 * x1 * x1)));
                }
                if (Cfz)
                    *(float2*)&Cfz[(size_t)row * N + col] = make_float2(x0, x1);
                if (Chz) {
                    __nv_bfloat162 hh, ll;
                    split_pair(x0, x1, hh, ll);
                    *(__nv_bfloat162*)&Chz[(size_t)row * N + col] = hh;
                    *(__nv_bfloat162*)&Clz[(size_t)row * N + col] = ll;
                }
            }
        }
    }
}

static void tg3(const __nv_bfloat16* Ah, long long loA, long long sA,
                const __nv_bfloat16* Bh, long long loB, long long sB,
                const float* bias, float* Cf, long long sC,
                __nv_bfloat16* Ch, __nv_bfloat16* Ch2, long long loC, long long sCp,
                int M, int N, int K, int batch, float alpha, int epi)
{
    dim3 grid(N / 128, M / 128, batch);
    tgemm3<<<grid, 512, TG_SMEM>>>(Ah, Bh, bias, Cf, Ch, Ch2, M, N, K,
                                   loA, loB, loC, sA, sB, sC, sCp, alpha, epi);
}

// N-tile 64 variant: 256 threads, 8 warps (4x2), tile 128x64
#define BPLANE  5120
#define BSTAGE  30720
#define TGN_SMEM (4 * 30720)

__global__ void __launch_bounds__(256)
tgemm3n64(const __nv_bfloat16* __restrict__ Ah0,
          const __nv_bfloat16* __restrict__ Bh0,
          const float* __restrict__ bias, float* __restrict__ Cf,
          int M, int N, int K,
          long long loA, long long loB,
          long long sA, long long sB, long long sC,
          float alpha)
{
    extern __shared__ char smem[];
    const uint32_t sbu = smem_u32(smem);
    const int t = threadIdx.x, w = t >> 5, lane = t & 31;
    const int wm = w & 3, wn = w >> 2;
    const int z = blockIdx.z;
    const int m0 = blockIdx.y * 128, n0 = blockIdx.x * 64;

    const __nv_bfloat16* Ah = Ah0 + (size_t)z * sA;
    const __nv_bfloat16* Bh = Bh0 + (size_t)z * sB;

    const int arow = t >> 1, aseg = (t & 1) * 2;
    const int brow = t >> 2, bseg = t & 3;
    const __nv_bfloat16* pa0 = Ah + (size_t)(m0 + arow) * K + aseg * 8;
    const __nv_bfloat16* pa1 = pa0 + loA;
    const __nv_bfloat16* pb0 = Bh + (size_t)(n0 + brow) * K + bseg * 8;
    const __nv_bfloat16* pb1 = pb0 + loB;

    const uint32_t adst = sbu + (uint32_t)(arow * 80 + aseg * 16);
    const uint32_t bdst = sbu + 20480u + (uint32_t)(brow * 80 + bseg * 16);

    float acc[2][4][4];
#pragma unroll
    for (int i = 0; i < 2; i++)
#pragma unroll
        for (int j = 0; j < 4; j++)
#pragma unroll
            for (int e = 0; e < 4; e++) acc[i][j][e] = 0.0f;

    const int nch = K >> 5;

#define ISSUEN(ch) do {                                                     \
    uint32_t _st = (uint32_t)((ch) & 3) * BSTAGE;                           \
    const int _cb = (ch) * 32;                                              \
    cpasync16(adst + _st,              pa0 + _cb);                          \
    cpasync16(adst + _st + 32,         pa0 + _cb + 16);                     \
    cpasync16(adst + _st + PLANE,      pa1 + _cb);                          \
    cpasync16(adst + _st + PLANE + 32, pa1 + _cb + 16);                     \
    cpasync16(bdst + _st,              pb0 + _cb);                          \
    cpasync16(bdst + _st + BPLANE,     pb1 + _cb);                          \
    CP_COMMIT();                                                            \
} while (0)

    ISSUEN(0);
    ISSUEN(1);
    if (nch > 2) ISSUEN(2);

    const uint32_t lmoff = (uint32_t)((lane & 15) * 80 + (lane >> 4) * 16);

    for (int ch = 0; ch < nch; ch++) {
        const int rem = nch - 1 - ch;
        if (rem >= 2)      { CP_WAIT(2); }
        else if (rem == 1) { CP_WAIT(1); }
        else               { CP_WAIT(0); }
        __syncthreads();
        if (ch + 3 < nch) ISSUEN(ch + 3);

        const uint32_t sAh = sbu + (uint32_t)(ch & 3) * BSTAGE;
        const uint32_t sBh = sAh + 20480u;
#pragma unroll
        for (int kk = 0; kk < 2; kk++) {
            uint32_t ah[2][4], al[2][4], bh[2][4], bl[2][4];
#pragma unroll
            for (int mt = 0; mt < 2; mt++) {
                uint32_t aaddr = sAh + (uint32_t)((wm * 32 + mt * 16) * 80 + kk * 32) + lmoff;
                ldsm4(ah[mt], aaddr);
                ldsm4(al[mt], aaddr + PLANE);
            }
#pragma unroll
            for (int ng = 0; ng < 2; ng++) {
                uint32_t baddr = sBh + (uint32_t)((wn * 32 + ng * 16) * 80 + kk * 32) + lmoff;
                ldsm4(bh[ng], baddr);
                ldsm4(bl[ng], baddr + BPLANE);
            }
#pragma unroll
            for (int ng = 0; ng < 2; ng++)
#pragma unroll
                for (int mt = 0; mt < 2; mt++)
#pragma unroll
                    for (int h2 = 0; h2 < 2; h2++)
                        mma_bf16(acc[mt][ng * 2 + h2], ah[mt], bh[ng][h2], bh[ng][h2 + 2]);
#pragma unroll
            for (int ng = 0; ng < 2; ng++)
#pragma unroll
                for (int mt = 0; mt < 2; mt++)
#pragma unroll
                    for (int h2 = 0; h2 < 2; h2++)
                        mma_bf16(acc[mt][ng * 2 + h2], ah[mt], bl[ng][h2], bl[ng][h2 + 2]);
#pragma unroll
            for (int ng = 0; ng < 2; ng++)
#pragma unroll
                for (int mt = 0; mt < 2; mt++)
#pragma unroll
                    for (int h2 = 0; h2 < 2; h2++)
                        mma_bf16(acc[mt][ng * 2 + h2], al[mt], bh[ng][h2], bh[ng][h2 + 2]);
        }
    }
#undef ISSUEN

    const int crow = m0 + wm * 32 + (lane >> 2);
    const int ccol = n0 + wn * 32 + (lane & 3) * 2;
    float* Cfz = Cf + (size_t)z * sC;
#pragma unroll
    for (int mt = 0; mt < 2; mt++)
#pragma unroll
        for (int n8 = 0; n8 < 4; n8++) {
            const float* c = acc[mt][n8];
            const int col = ccol + n8 * 8;
            float b0 = bias ? bias[col]     : 0.0f;
            float b1 = bias ? bias[col + 1] : 0.0f;
#pragma unroll
            for (int h = 0; h < 2; h++) {
                const int row = crow + mt * 16 + h * 8;
                float x0 = c[h * 2 + 0] * alpha + b0;
                float x1 = c[h * 2 + 1] * alpha + b1;
                *(float2*)&Cfz[(size_t)row * N + col] = make_float2(x0, x1);
            }
        }
}

__global__ void trans_conv(const float* __restrict__ in, __nv_bfloat16* __restrict__ oh,
                           long long loOff, int R, int C,
                           long long sI, long long sO, const int* __restrict__ ids)
{
    __shared__ float tile[32][33];
    const int z = blockIdx.z;
    size_t ib = ids ? (size_t)ids[z] * sI : (size_t)z * sI;
    const float* ip = in + ib;
    __nv_bfloat16* ohz = oh + (size_t)z * sO;
    __nv_bfloat16* olz = ohz + loOff;
    const int c0 = blockIdx.x * 32, r0 = blockIdx.y * 32;
    const int tx = threadIdx.x, ty = threadIdx.y;
#pragma unroll
    for (int k = 0; k < 32; k += 8)
        tile[ty + k][tx] = ip[(size_t)(r0 + ty + k) * C + c0 + tx];
    __syncthreads();
    const int rr = (tx & 15) * 2, chf = tx >> 4;
#pragma unroll
    for (int k = 0; k < 2; k++) {
        int cc = ty + chf * 8 + k * 16;
        __nv_bfloat162 h, l;
        split_pair(tile[rr][cc], tile[rr + 1][cc], h, l);
        *(__nv_bfloat162*)&ohz[(size_t)(c0 + cc) * R + r0 + rr] = h;
        *(__nv_bfloat162*)&olz[(size_t)(c0 + cc) * R + r0 + rr] = l;
    }
}

__global__ void conv_planes(const float* __restrict__ in, __nv_bfloat16* __restrict__ oh,
                            long long lo)
{
    size_t idx = (size_t)blockIdx.x * 512 + (size_t)threadIdx.x * 2;
    float2 v = *(const float2*)&in[idx];
    __nv_bfloat162 h, l;
    split_pair(v.x, v.y, h, l);
    *(__nv_bfloat162*)&oh[idx] = h;
    *(__nv_bfloat162*)&(oh + lo)[idx] = l;
}

__global__ void rope_table_kernel()
{
    int s = blockIdx.x;
    int i = threadIdx.x;
    float invf = 1.0f / powf(10000.0f, (float)i / 256.0f);
    float angf = (float)s * invf;
    double ang = (double)angf;
    g_sin[s * 256 + i] = (float)sin(ang);
    g_cos[s * 256 + i] = (float)cos(ang);
}

__global__ void bias_prep(const float* __restrict__ pos, float* __restrict__ out, int mode)
{
    int n = blockIdx.x, t = threadIdx.x;
    for (int c = t; c < 1024; c += 256) {
        float p = pos[n * 1024 + c];
        out[n * 1024 + c] = (mode == 1) ? logf(p) : (logf(p) - log1pf(-p));
    }
}

__global__ void softmax1024_planes(const float* __restrict__ S, const float* __restrict__ bias,
                                   __nv_bfloat16* __restrict__ oh, long long lo)
{
    const int row = blockIdx.x, t = threadIdx.x;
    const float* sr = S + (size_t)row * 1024;
    const float* pb = bias + (size_t)(row >> 10) * 1024;
    float2 a  = *(const float2*)&sr[2 * t];
    float2 b2 = *(const float2*)&sr[512 + 2 * t];
    float2 ba = *(const float2*)&pb[2 * t];
    float2 bb = *(const float2*)&pb[512 + 2 * t];
    float v0 = a.x + ba.x, v1 = a.y + ba.y, v2 = b2.x + bb.x, v3 = b2.y + bb.y;

    __shared__ float red[256];
    float mx = fmaxf(fmaxf(v0, v1), fmaxf(v2, v3));
    red[t] = mx; __syncthreads();
    for (int s = 128; s > 0; s >>= 1) { if (t < s) red[t] = fmaxf(red[t], red[t + s]); __syncthreads(); }
    mx = red[0]; __syncthreads();

    float e0 = expf(v0 - mx), e1 = expf(v1 - mx), e2 = expf(v2 - mx), e3 = expf(v3 - mx);
    red[t] = e0 + e1 + e2 + e3; __syncthreads();
    for (int s = 128; s > 0; s >>= 1) { if (t < s) red[t] += red[t + s]; __syncthreads(); }
    float inv = 1.0f / red[0];

    __nv_bfloat162 h, l;
    size_t o = (size_t)row * 1024 + 2 * t;
    split_pair(e0 * inv, e1 * inv, h, l);
    *(__nv_bfloat162*)&oh[o] = h;
    *(__nv_bfloat162*)&(oh + lo)[o] = l;
    split_pair(e2 * inv, e3 * inv, h, l);
    *(__nv_bfloat162*)&oh[o + 512] = h;
    *(__nv_bfloat162*)&(oh + lo)[o + 512] = l;
}

__global__ void softmax64_planes(const float* __restrict__ S, __nv_bfloat16* __restrict__ oh,
                                 long long lo)
{
    const int row = blockIdx.x * 8 + (threadIdx.x >> 5);
    const int lane = threadIdx.x & 31;
    const float* sr = S + (size_t)row * 64;
    float2 v = *(const float2*)&sr[lane * 2];
    float mx = fmaxf(v.x, v.y);
#pragma unroll
    for (int o = 16; o > 0; o >>= 1)
        mx = fmaxf(mx, __shfl_xor_sync(0xFFFFFFFF, mx, o));
    float e0 = expf(v.x - mx), e1 = expf(v.y - mx);
    float s = e0 + e1;
#pragma unroll
    for (int o = 16; o > 0; o >>= 1)
        s += __shfl_xor_sync(0xFFFFFFFF, s, o);
    float inv = 1.0f / s;
    __nv_bfloat162 h, l;
    split_pair(e0 * inv, e1 * inv, h, l);
    size_t o2 = (size_t)row * 64 + lane * 2;
    *(__nv_bfloat162*)&oh[o2] = h;
    *(__nv_bfloat162*)&(oh + lo)[o2] = l;
}

__global__ void softmax_f32(float* __restrict__ S, const float* __restrict__ bias,
                            int cols, int rpb)
{
    int row = blockIdx.x;
    float* sr = S + (size_t)row * cols;
    const float* pb = bias + (size_t)(row / rpb) * cols;
    int t = threadIdx.x;
    __shared__ float red[256];

    float mx = -1e30f;
    for (int c = t; c < cols; c += 256) {
        float v = sr[c] + pb[c];
        sr[c] = v;
        mx = fmaxf(mx, v);
    }
    red[t] = mx; __syncthreads();
    for (int s = 128; s > 0; s >>= 1) { if (t < s) red[t] = fmaxf(red[t], red[t + s]); __syncthreads(); }
    mx = red[0]; __syncthreads();

    float sum = 0.0f;
    for (int c = t; c < cols; c += 256) {
        float e = expf(sr[c] - mx);
        sr[c] = e;
        sum += e;
    }
    red[t] = sum; __syncthreads();
    for (int s = 128; s > 0; s >>= 1) { if (t < s) red[t] += red[t + s]; __syncthreads(); }
    float inv = 1.0f / red[0];
    for (int c = t; c < cols; c += 256) sr[c] *= inv;
}

__global__ void ln_kernel(const float* __restrict__ Xin, const float* __restrict__ R,
                          const float* __restrict__ g, const float* __restrict__ b,
                          float* __restrict__ Xout,
                          __nv_bfloat16* __restrict__ oh, long long lo)
{
    int row = blockIdx.x;
    int t   = threadIdx.x;
    const float* xr = Xin + (size_t)row * DD;
    const float* rr = R + (size_t)row * DD;

    float v0 = xr[2 * t] + rr[2 * t];
    float v1 = xr[2 * t + 1] + rr[2 * t + 1];

    __shared__ float red[256];
    red[t] = v0 + v1; __syncthreads();
    for (int s = 128; s > 0; s >>= 1) { if (t < s) red[t] += red[t + s]; __syncthreads(); }
    float m = red[0] * (1.0f / 512.0f);
    __syncthreads();

    float d0 = v0 - m, d1 = v1 - m;
    red[t] = d0 * d0 + d1 * d1; __syncthreads();
    for (int s = 128; s > 0; s >>= 1) { if (t < s) red[t] += red[t + s]; __syncthreads(); }
    float var = red[0] * (1.0f / 512.0f);
    float inv = rsqrtf(var + 1e-5f);

    float o0 = d0 * inv * g[2 * t]     + b[2 * t];
    float o1 = d1 * inv * g[2 * t + 1] + b[2 * t + 1];
    float* xo = Xout + (size_t)row * DD;
    xo[2 * t]     = o0;
    xo[2 * t + 1] = o1;

    __nv_bfloat162 h, l;
    split_pair(o0, o1, h, l);
    size_t o = (size_t)row * DD + 2 * t;
    *(__nv_bfloat162*)&oh[o] = h;
    *(__nv_bfloat162*)&(oh + lo)[o] = l;
}

__global__ void vgate_kernel(const float* __restrict__ F, const float* __restrict__ raw,
                             const float* __restrict__ Wig, const float* __restrict__ big,
                             float* __restrict__ V)
{
    int row = blockIdx.x;
    int t   = threadIdx.x;
    const float* fr = F + (size_t)row * DD;
    __shared__ float red[256];
    float s = fr[t] * Wig[t] + fr[t + 256] * Wig[t + 256];
    red[t] = s; __syncthreads();
    for (int k = 128; k > 0; k >>= 1) { if (t < k) red[t] += red[t + k]; __syncthreads(); }
    float gte = 1.0f / (1.0f + expf(-(red[0] + big[0])));
    const float* rr = raw + (size_t)row * DD;
    float* vr = V + (size_t)row * DD;
    vr[t]       = rr[t]       * gte;
    vr[t + 256] = rr[t + 256] * gte;
}

__global__ void out_kernel(const float* __restrict__ FU, const float* __restrict__ A2,
                           const float* __restrict__ PD,
                           const float* __restrict__ Wu1, const float* __restrict__ bu1,
                           const float* __restrict__ Wu2, const float* __restrict__ bu2,
                           const float* __restrict__ b1,
                           float* __restrict__ out, float* __restrict__ gate)
{
    int row = blockIdx.x;
    int t   = threadIdx.x;
    const float* fu = FU + (size_t)row * DD;
    const float* a2 = A2 + (size_t)row * DD;
    const float* pd = PD + (size_t)row * DD;

    __shared__ float red[256];
    float s = fu[t] * Wu1[t] + fu[t + 256] * Wu1[t + 256]
            + a2[t] * Wu2[t] + a2[t + 256] * Wu2[t + 256];
    red[t] = s; __syncthreads();
    for (int k = 128; k > 0; k >>= 1) { if (t < k) red[t] += red[t + k]; __syncthreads(); }
    float z = red[0] + bu1[0] + bu2[0] + b1[0] - 4.0f;
    float g = 1.0f / (1.0f + expf(-z));

    float* orow = out + (size_t)row * DD;
    orow[t]       = pd[t]       * (1.0f - g) + a2[t]       * g;
    orow[t + 256] = pd[t + 256] * (1.0f - g) + a2[t + 256] * g;
    if (t == 0) gate[row] = g;
}

#define BM 64
#define BN 64
#define BK 16

__global__ void gemm_kernel(const float* __restrict__ A,
                            const float* __restrict__ Bm,
                            const float* __restrict__ bias,
                            float* __restrict__ C,
                            int M, int N, int K,
                            long long sA, long long sB, long long sC,
                            float alpha, int transB, int epi)
{
    const int bz = blockIdx.z;
    A  += (size_t)bz * sA;
    Bm += (size_t)bz * sB;
    C  += (size_t)bz * sC;

    const int m0 = blockIdx.y * BM;
    const int n0 = blockIdx.x * BN;

    __shared__ float As[BK][BM + 4];
    __shared__ float Bs[BK][BN + 4];

    const int t  = threadIdx.x;
    const int tx = t & 15;
    const int ty = t >> 4;

    float acc[4][4] = {};

    const int arow = t >> 2;
    const int akc  = (t & 3) * 4;
    const int kb   = t >> 4;
    const int nb   = (t & 15) * 4;

    for (int k0 = 0; k0 < K; k0 += BK) {
        float4 av = *(const float4*)&A[(size_t)(m0 + arow) * K + k0 + akc];
        As[akc + 0][arow] = av.x;
        As[akc + 1][arow] = av.y;
        As[akc + 2][arow] = av.z;
        As[akc + 3][arow] = av.w;

        if (!transB) {
            float4 bv = *(const float4*)&Bm[(size_t)(k0 + kb) * N + n0 + nb];
            *(float4*)&Bs[kb][nb] = bv;
        } else {
            float4 bv = *(const float4*)&Bm[(size_t)(n0 + arow) * K + k0 + akc];
            Bs[akc + 0][arow] = bv.x;
            Bs[akc + 1][arow] = bv.y;
            Bs[akc + 2][arow] = bv.z;
            Bs[akc + 3][arow] = bv.w;
        }
        __syncthreads();

#pragma unroll
        for (int k = 0; k < BK; k++) {
            float4 a = *(const float4*)&As[k][ty * 4];
            float4 b = *(const float4*)&Bs[k][tx * 4];
            acc[0][0] += a.x * b.x; acc[0][1] += a.x * b.y;
            acc[0][2] += a.x * b.z; acc[0][3] += a.x * b.w;
            acc[1][0] += a.y * b.x; acc[1][1] += a.y * b.y;
            acc[1][2] += a.y * b.z; acc[1][3] += a.y * b.w;
            acc[2][0] += a.z * b.x; acc[2][1] += a.z * b.y;
            acc[2][2] += a.z * b.z; acc[2][3] += a.z * b.w;
            acc[3][0] += a.w * b.x; acc[3][1] += a.w * b.y;
            acc[3][2] += a.w * b.z; acc[3][3] += a.w * b.w;
        }
        __syncthreads();
    }

#pragma unroll
    for (int i = 0; i < 4; i++) {
        const int row = m0 + ty * 4 + i;
        float v[4];
#pragma unroll
        for (int j = 0; j < 4; j++) {
            float x = acc[i][j] * alpha;
            if (bias) x += bias[n0 + tx * 4 + j];
            v[j] = x;
        }
        *(float4*)&C[(size_t)row * N + n0 + tx * 4] = make_float4(v[0], v[1], v[2], v[3]);
    }
}

static void sgemm_launch(const float* A, const float* B, const float* bias, float* C,
                         int M, int N, int K, int batch,
                         long long sA, long long sB, long long sC,
                         float alpha, int transB)
{
    dim3 grid(N / BN, M / BM, batch);
    gemm_kernel<<<grid, 256>>>(A, B, bias, C, M, N, K, sA, sB, sC, alpha, transB, 0);
}

static void run_encoder(const float* Xin0, float* X, int nb,
                        const __nv_bfloat16* initP, long long initLo,
                        const float* biasRows,
                        const __nv_bfloat16* PW,
                        const float* bqkv, const float* bo,
                        const float* ln, const float* bff,
                        float* bV, float* bK, float* bS,
                        __nv_bfloat16* Pq, __nv_bfloat16* Pk, __nv_bfloat16* Pvt,
                        __nv_bfloat16* Pp, __nv_bfloat16* Pbq, __nv_bfloat16* Ph,
                        __nv_bfloat16* Px, int skip_first_qkv)
{
    const int rows = nb * SS;
    const float sc = 1.0f / sqrtf((float)DD);
    for (int l = 0; l < 2; l++) {
        const __nv_bfloat16* AP = (l == 0) ? initP : Px;
        const long long loAP = (l == 0) ? initLo : LO;
        if (!(l == 0 && skip_first_qkv))
            tg3(AP, loAP, 0, PW + (size_t)(l * 3) * 262144, WLO, 0,
                bqkv + (size_t)l * 1536, bV, 0, Pq, Pk, LO, 0,
                rows, 1536, 512, 1, 1.0f, 2);
        trans_conv<<<dim3(16, 32, nb), dim3(32, 8)>>>(bV, Pvt, LO, 1024, 512,
                                                      524288, 524288, nullptr);
        tg3(Pq, LO, 524288, Pk, LO, 524288, nullptr, bS, 1048576,
            nullptr, nullptr, 0, 0, 1024, 1024, 512, nb, sc, 0);
        softmax1024_planes<<<rows, 256>>>(bS, biasRows, Pp, 16777216LL);
        tg3(Pp, 16777216LL, 1048576, Pvt, LO, 524288, nullptr, nullptr, 0,
            Pbq, nullptr, LO, 524288, 1024, 512, 1024, nb, 1.0f, 0);
        tg3(Pbq, LO, 0, PW + (size_t)(6 + l) * 262144, WLO, 0, bo + l * 512,
            bK, 0, nullptr, nullptr, 0, 0, rows, 512, 512, 1, 1.0f, 0);
        ln_kernel<<<rows, 256>>>((l == 0) ? Xin0 : X, bK,
                                 ln + l * 2048, ln + l * 2048 + 512, X, Px, LO);
        tg3(Px, LO, 0, PW + (size_t)(8 + 2 * l) * 262144, WLO, 0, bff + l * 1024,
            nullptr, 0, Ph, nullptr, LO, 0, rows, 512, 512, 1, 1.0f, 1);
        tg3(Ph, LO, 0, PW + (size_t)(9 + 2 * l) * 262144, WLO, 0, bff + l * 1024 + 512,
            bK, 0, nullptr, nullptr, 0, 0, rows, 512, 512, 1, 1.0f, 0);
        ln_kernel<<<rows, 256>>>(X, bK, ln + l * 2048 + 1024, ln + l * 2048 + 1536,
                                 X, Px, LO);
    }
}

extern "C" void kernel_launch(void* const* d_in, const int* in_sizes, int n_in,
                              void* d_out, int out_size)
{
    const float* raw_emb   = (const float*)d_in[0];
    const float* pos_w     = (const float*)d_in[1];
    const float* post_dec  = (const float*)d_in[2];
    const float* pos_r     = (const float*)d_in[3];
    const float* questions = (const float*)d_in[4];
    const float* W_k       = (const float*)d_in[5];
    const float* W_ig      = (const float*)d_in[6];
    const float* b_ig      = (const float*)d_in[7];
    const float* W_u1      = (const float*)d_in[8];
    const float* b_u1      = (const float*)d_in[9];
    const float* W_u2      = (const float*)d_in[10];
    const float* b_u2      = (const float*)d_in[11];
    const float* b1        = (const float*)d_in[12];
    const float* W_ok      = (const float*)d_in[13];
    const float* b_ok      = (const float*)d_in[14];
    const float* encw_Wqkv = (const float*)d_in[15];
    const float* encw_bqkv = (const float*)d_in[16];
    const float* encw_Wo   = (const float*)d_in[17];
    const float* encw_bo   = (const float*)d_in[18];
    const float* encw_ln   = (const float*)d_in[19];
    const float* encw_Wff  = (const float*)d_in[20];
    const float* encw_bff  = (const float*)d_in[21];
    const float* encr_Wqkv = (const float*)d_in[22];
    const float* encr_bqkv = (const float*)d_in[23];
    const float* encr_Wo   = (const float*)d_in[24];
    const float* encr_bo   = (const float*)d_in[25];
    const float* encr_ln   = (const float*)d_in[26];
    const float* encr_Wff  = (const float*)d_in[27];
    const float* encr_bff  = (const float*)d_in[28];
    const int*   lookup    = (const int*)d_in[29];

    float* out  = (float*)d_out;
    float* gate = out + (size_t)NBB * SS * DD;

    float *pX, *pV, *pK, *pS, *pKd, *pVd, *pA1, *pA2s, *pA2, *pBW, *pBR;
    __nv_bfloat16 *pPW, *pPraw, *pPpd, *pPx, *pPq, *pPk, *pPvt, *pPp, *pPbq, *pPh,
                  *pPa2, *pPsel, *pPqst;
    cudaGetSymbolAddress((void**)&pX,    g_X);
    cudaGetSymbolAddress((void**)&pV,    g_V);
    cudaGetSymbolAddress((void**)&pK,    g_Kb);
    cudaGetSymbolAddress((void**)&pS,    g_S);
    cudaGetSymbolAddress((void**)&pKd,   g_Kdoc);
    cudaGetSymbolAddress((void**)&pVd,   g_Vdoc);
    cudaGetSymbolAddress((void**)&pA1,   g_A1S);
    cudaGetSymbolAddress((void**)&pA2s,  g_A2SC);
    cudaGetSymbolAddress((void**)&pA2,   g_A2);
    cudaGetSymbolAddress((void**)&pBW,   g_BIASW);
    cudaGetSymbolAddress((void**)&pBR,   g_BIASR);
    cudaGetSymbolAddress((void**)&pPW,   g_PW);
    cudaGetSymbolAddress((void**)&pPraw, g_Praw);
    cudaGetSymbolAddress((void**)&pPpd,  g_Ppd);
    cudaGetSymbolAddress((void**)&pPx,   g_Px);
    cudaGetSymbolAddress((void**)&pPq,   g_Pq);
    cudaGetSymbolAddress((void**)&pPk,   g_Pk);
    cudaGetSymbolAddress((void**)&pPvt,  g_Pvt);
    cudaGetSymbolAddress((void**)&pPp,   g_Pp);
    cudaGetSymbolAddress((void**)&pPbq,  g_Pbq);
    cudaGetSymbolAddress((void**)&pPh,   g_Ph);
    cudaGetSymbolAddress((void**)&pPa2,  g_Pa2);
    cudaGetSymbolAddress((void**)&pPsel, g_Psel);
    cudaGetSymbolAddress((void**)&pPqst, g_Pqst);

    cudaFuncSetAttribute(tgemm3,    cudaFuncAttributeMaxDynamicSharedMemorySize, TG_SMEM);
    cudaFuncSetAttribute(tgemm3n64, cudaFuncAttributeMaxDynamicSharedMemorySize, TGN_SMEM);

    const float scD = 1.0f / sqrtf((float)DD);

    trans_conv<<<dim3(16, 16, 6), dim3(32, 8)>>>(encw_Wqkv, pPW + 0LL  * 262144, WLO, 512, 512, 262144, 262144, nullptr);
    conv_planes<<<NDOC * SS, 256>>>(raw_emb, pPraw, 4194304LL);
    rope_table_kernel<<<1024, 256>>>();
    trans_conv<<<dim3(16, 16, 2), dim3(32, 8)>>>(encw_Wo,   pPW + 6LL  * 262144, WLO, 512, 512, 262144, 262144, nullptr);
    trans_conv<<<dim3(16, 16, 4), dim3(32, 8)>>>(encw_Wff,  pPW + 8LL  * 262144, WLO, 512, 512, 262144, 262144, nullptr);

    // write-side encoder
    tg3(pPraw, 4194304LL, 0, pPW, WLO, 0, encw_bqkv, pV, 0, pPq, pPk, LO, 0,
        NDOC * SS, 1536, 512, 1, 1.0f, 2);
    bias_prep<<<NDOC, 256>>>(pos_w, pBW, 1);
    run_encoder(raw_emb, pX, NDOC, pPraw, 4194304LL, pBW,
                pPW, encw_bqkv, encw_bo, encw_ln, encw_bff,
                pV, pK, pS, pPq, pPk, pPvt, pPp, pPbq, pPh, pPx, 1);

    vgate_kernel<<<NDOC * SS, 256>>>(pX, raw_emb, W_ig, b_ig, pVd);
    trans_conv<<<dim3(16, 16, 1), dim3(32, 8)>>>(W_k, pPW + 24LL * 262144, WLO, 512, 512, 262144, 262144, nullptr);
    tg3(pPraw, 4194304LL, 0, pPW + 24LL * 262144, WLO, 0, nullptr, pKd, 0,
        nullptr, nullptr, 0, 0, NDOC * SS, 512, 512, 1, 1.0f, 0);
    sgemm_launch(questions, pKd, nullptr, pS, QQ, SS, DD, NDOC, 0, 524288, 65536, scD, 1);
    softmax_f32<<<NDOC * QQ, 256>>>(pS, pBW, SS, QQ);
    sgemm_launch(pS, pVd, nullptr, pA1, QQ, DD, SS, NDOC, 65536, 524288, 32768, 1.0f, 0);

    // read-side encoder
    trans_conv<<<dim3(16, 16, 6), dim3(32, 8)>>>(encr_Wqkv, pPW + 12LL * 262144, WLO, 512, 512, 262144, 262144, nullptr);
    trans_conv<<<dim3(16, 16, 2), dim3(32, 8)>>>(encr_Wo,   pPW + 18LL * 262144, WLO, 512, 512, 262144, 262144, nullptr);
    trans_conv<<<dim3(16, 16, 4), dim3(32, 8)>>>(encr_Wff,  pPW + 20LL * 262144, WLO, 512, 512, 262144, 262144, nullptr);
    conv_planes<<<NBB * SS, 256>>>(post_dec, pPpd, 8388608LL);
    bias_prep<<<NBB, 256>>>(pos_r, pBR, 2);
    run_encoder(post_dec, pX, NBB, pPpd, 8388608LL, pBR,
                pPW + 12LL * 262144, encr_bqkv, encr_bo, encr_ln, encr_bff,
                pV, pK, pS, pPq, pPk, pPvt, pPp, pPbq, pPh, pPx, 0);

    // k2 / a2 / A2 / out
    trans_conv<<<dim3(16, 16, 1), dim3(32, 8)>>>(W_ok, pPW + 25LL * 262144, WLO, 512, 512, 262144, 262144, nullptr);
    conv_planes<<<QQ, 256>>>(questions, pPqst, 32768LL);
    tg3(pPpd, 8388608LL, 0, pPW + 25LL * 262144, WLO, 0, b_ok, nullptr, 0,
        pPq, nullptr, LO, 0, NBB * SS, 512, 512, 1, 1.0f, 0);
    {
        dim3 grid(1, (NBB * SS) / 128, 1);
        tgemm3n64<<<grid, 256, TGN_SMEM>>>(pPq, pPqst, nullptr, pA2s,
                                           NBB * SS, QQ, DD, LO, 32768LL,
                                           0, 0, 0, 0.125f);
    }
    softmax64_planes<<<NBB * SS / 8, 256>>>(pA2s, pPa2, 1048576LL);
    trans_conv<<<dim3(16, 2, 16), dim3(32, 8)>>>(pA1, pPsel, 524288, 64, 512, 32768, 32768, lookup);
    tg3(pPa2, 1048576LL, 65536, pPsel, 524288LL, 32768, nullptr, pA2, 524288,
        nullptr, nullptr, 0, 0, 1024, 512, 64, NBB, 1.0f, 0);

    out_kernel<<<NBB * SS, 256>>>(pX, pA2, post_dec,
                                  W_u1, b_u1, W_u2, b_u2, b1,
                                  out, gate);

    (void)in_sizes; (void)n_in; (void)out_size;
}

// round 9
// speedup vs baseline: 2.7364x; 1.2790x over previous
#include <cuda_runtime.h>
#include <cuda_fp16.h>
#include <math.h>
#include <stdint.h>

#define DD     512
#define SS     1024
#define NBB    16
#define QQ     64
#define NDOC   8

__device__ float g_X   [16384 * 512];
__device__ float g_V   [16384 * 512];
__device__ float g_Kb  [16384 * 512];
__device__ float g_S   [16 * 1024 * 1024];
__device__ float g_Kdoc[8192 * 512];
__device__ float g_Vdoc[8192 * 512];
__device__ float g_A1S [8 * 64 * 512];
__device__ float g_A2SC[16384 * 64];
__device__ float g_A2  [16384 * 512];
__device__ float g_sin [1024 * 256];
__device__ float g_cos [1024 * 256];
__device__ float g_BIASW[8 * 1024];
__device__ float g_BIASR[16 * 1024];

#define WLO 6815744LL
#define LO  8388608LL
__device__ __align__(16) __half g_PW  [2 * 26 * 262144];
__device__ __align__(16) __half g_Praw[2 * 4194304];
__device__ __align__(16) __half g_Ppd [2 * 8388608];
__device__ __align__(16) __half g_Px  [2 * 8388608];
__device__ __align__(16) __half g_Pq  [2 * 8388608];   // hi-only use
__device__ __align__(16) __half g_Pk  [8388608];       // hi only
__device__ __align__(16) __half g_Pvt [8388608];       // hi only
__device__ __align__(16) __half g_Pp  [16777216];      // hi only
__device__ __align__(16) __half g_Pbq [2 * 8388608];
__device__ __align__(16) __half g_Ph  [2 * 8388608];
__device__ __align__(16) __half g_Pa2 [1048576];       // hi only
__device__ __align__(16) __half g_Psel[524288];        // hi only
__device__ __align__(16) __half g_Pqst[32768];         // hi only

__device__ __forceinline__ uint32_t smem_u32(const void* p) {
    uint32_t a;
    asm("{ .reg .u64 t; cvta.to.shared.u64 t, %1; cvt.u32.u64 %0, t; }"
        : "=r"(a) : "l"(p));
    return a;
}

__device__ __forceinline__ void ldsm4(uint32_t* r, uint32_t addr) {
    asm volatile("ldmatrix.sync.aligned.m8n8.x4.shared.b16 {%0,%1,%2,%3}, [%4];"
                 : "=r"(r[0]), "=r"(r[1]), "=r"(r[2]), "=r"(r[3]) : "r"(addr));
}

__device__ __forceinline__ void mma_f16(float* c, const uint32_t* a,
                                        uint32_t b0, uint32_t b1) {
    asm volatile(
        "mma.sync.aligned.m16n8k16.row.col.f32.f16.f16.f32 "
        "{%0,%1,%2,%3}, {%4,%5,%6,%7}, {%8,%9}, {%0,%1,%2,%3};"
        : "+f"(c[0]), "+f"(c[1]), "+f"(c[2]), "+f"(c[3])
        : "r"(a[0]), "r"(a[1]), "r"(a[2]), "r"(a[3]), "r"(b0), "r"(b1));
}

__device__ __forceinline__ void cpasync16(uint32_t dst, const void* src) {
    asm volatile("cp.async.cg.shared.global [%0], [%1], 16;" :: "r"(dst), "l"(src));
}
#define CP_COMMIT() asm volatile("cp.async.commit_group;" ::: "memory")
#define CP_WAIT(n)  asm volatile("cp.async.wait_group %0;" :: "n"(n) : "memory")

__device__ __forceinline__ void split_pair(float x0, float x1,
                                           __half2& h, __half2& l) {
    h = __floats2half2_rn(x0, x1);
    l = __floats2half2_rn(x0 - __low2float(h), x1 - __high2float(h));
}

// ---------------------------------------------------------------------------
// 3-term split GEMM (fp16 planes): C = alpha*(Ah+Al)@(Bh+Bl)^T + bias
// epi: 0=none, 1=gelu, 2=QKV (rope -> hi-only q/k planes, V -> f32)
// ---------------------------------------------------------------------------
#define PLANE  10240
#define TSTAGE 40960
#define TG_SMEM (4 * 40960)

__global__ void __launch_bounds__(512)
tgemm3(const __half* __restrict__ Ah0, const __half* __restrict__ Bh0,
       const float* __restrict__ bias, float* __restrict__ Cf,
       __half* __restrict__ Ch0, __half* __restrict__ Ch2,
       int M, int N, int K,
       long long loA, long long loB, long long loC,
       long long sA, long long sB, long long sC, long long sCp,
       float alpha, int epi)
{
    extern __shared__ char smem[];
    const uint32_t sbu = smem_u32(smem);
    const int t = threadIdx.x, w = t >> 5, lane = t & 31;
    const int wm = w & 3, wn = w >> 2;
    const int z = blockIdx.z;
    const int m0 = blockIdx.y * 128, n0 = blockIdx.x * 128;

    const __half* Ah = Ah0 + (size_t)z * sA;
    const __half* Bh = Bh0 + (size_t)z * sB;

    const int lrow = t >> 2, seg = t & 3;
    const __half* pr[4];
    pr[0] = Ah + (size_t)(m0 + lrow) * K + seg * 8;
    pr[1] = pr[0] + loA;
    pr[2] = Bh + (size_t)(n0 + lrow) * K + seg * 8;
    pr[3] = pr[2] + loB;

    float acc[2][4][4];
#pragma unroll
    for (int i = 0; i < 2; i++)
#pragma unroll
        for (int j = 0; j < 4; j++)
#pragma unroll
            for (int e = 0; e < 4; e++) acc[i][j][e] = 0.0f;

    const int nch = K >> 5;
    const uint32_t sdbase = sbu + (uint32_t)(lrow * 80 + seg * 16);

#define ISSUE(ch) do {                                                      \
    uint32_t _sd = sdbase + (uint32_t)((ch) & 3) * TSTAGE;                  \
    const int _cb = (ch) * 32;                                              \
    _Pragma("unroll")                                                       \
    for (int _p = 0; _p < 4; _p++)                                          \
        cpasync16(_sd + _p * PLANE, pr[_p] + _cb);                          \
    CP_COMMIT();                                                            \
} while (0)

    ISSUE(0);
    ISSUE(1);
    if (nch > 2) ISSUE(2);

    const uint32_t lmoff = (uint32_t)((lane & 15) * 80 + (lane >> 4) * 16);

    for (int ch = 0; ch < nch; ch++) {
        const int rem = nch - 1 - ch;
        if (rem >= 2)      { CP_WAIT(2); }
        else if (rem == 1) { CP_WAIT(1); }
        else               { CP_WAIT(0); }
        __syncthreads();
        if (ch + 3 < nch) ISSUE(ch + 3);

        const uint32_t sAh = sbu + (uint32_t)(ch & 3) * TSTAGE;
        const uint32_t sBh = sAh + 2 * PLANE;
#pragma unroll
        for (int kk = 0; kk < 2; kk++) {
            uint32_t ah[2][4], al[2][4], bh[2][4], bl[2][4];
#pragma unroll
            for (int mt = 0; mt < 2; mt++) {
                uint32_t aaddr = sAh + (uint32_t)((wm * 32 + mt * 16) * 80 + kk * 32) + lmoff;
                ldsm4(ah[mt], aaddr);
                ldsm4(al[mt], aaddr + PLANE);
            }
#pragma unroll
            for (int ng = 0; ng < 2; ng++) {
                uint32_t baddr = sBh + (uint32_t)((wn * 32 + ng * 16) * 80 + kk * 32) + lmoff;
                ldsm4(bh[ng], baddr);
                ldsm4(bl[ng], baddr + PLANE);
            }
#pragma unroll
            for (int ng = 0; ng < 2; ng++)
#pragma unroll
                for (int mt = 0; mt < 2; mt++)
#pragma unroll
                    for (int h2 = 0; h2 < 2; h2++)
                        mma_f16(acc[mt][ng * 2 + h2], ah[mt], bh[ng][h2], bh[ng][h2 + 2]);
#pragma unroll
            for (int ng = 0; ng < 2; ng++)
#pragma unroll
                for (int mt = 0; mt < 2; mt++)
#pragma unroll
                    for (int h2 = 0; h2 < 2; h2++)
                        mma_f16(acc[mt][ng * 2 + h2], ah[mt], bl[ng][h2], bl[ng][h2 + 2]);
#pragma unroll
            for (int ng = 0; ng < 2; ng++)
#pragma unroll
                for (int mt = 0; mt < 2; mt++)
#pragma unroll
                    for (int h2 = 0; h2 < 2; h2++)
                        mma_f16(acc[mt][ng * 2 + h2], al[mt], bh[ng][h2], bh[ng][h2 + 2]);
        }
    }
#undef ISSUE

    const float GC = 0.7978845608028654f;
    const int crow = m0 + wm * 32 + (lane >> 2);
    const int ccol = n0 + wn * 32 + (lane & 3) * 2;

    if (epi == 2) {
        // QKV: cols [0,1024) -> rope -> hi-only planes; [1024,1536) -> V f32
#pragma unroll
        for (int mt = 0; mt < 2; mt++) {
#pragma unroll
            for (int n8 = 0; n8 < 4; n8++) {
                const float* c = acc[mt][n8];
                const int col = ccol + n8 * 8;
                float b0 = bias[col], b1 = bias[col + 1];
#pragma unroll
                for (int h = 0; h < 2; h++) {
                    const int row = crow + mt * 16 + h * 8;
                    float x0 = c[h * 2 + 0] + b0;
                    float x1 = c[h * 2 + 1] + b1;
                    if (col < 1024) {
                        const int s = row & (SS - 1);
                        const int i = (col & 511) >> 1;
                        float sn = g_sin[s * 256 + i];
                        float cs = g_cos[s * 256 + i];
                        float y0 = x0 * cs - x1 * sn;
                        float y1 = x0 * sn + x1 * cs;
                        __half* dst = (col < 512) ? Ch0 : Ch2;
                        size_t off = (size_t)row * 512 + (col & 511);
                        *(__half2*)&dst[off] = __floats2half2_rn(y0, y1);
                    } else {
                        *(float2*)&Cf[(size_t)row * 512 + (col - 1024)] =
                            make_float2(x0, x1);
                    }
                }
            }
        }
        return;
    }

    float* Cfz = Cf ? Cf + (size_t)z * sC : (float*)0;
    __half* Chz = Ch0 ? Ch0 + (size_t)z * sCp : (__half*)0;
    __half* Clz = Chz ? Chz + loC : (__half*)0;
#pragma unroll
    for (int mt = 0; mt < 2; mt++) {
#pragma unroll
        for (int n8 = 0; n8 < 4; n8++) {
            const float* c = acc[mt][n8];
            const int col = ccol + n8 * 8;
            float b0 = bias ? bias[col]     : 0.0f;
            float b1 = bias ? bias[col + 1] : 0.0f;
#pragma unroll
            for (int h = 0; h < 2; h++) {
                const int row = crow + mt * 16 + h * 8;
                float x0 = c[h * 2 + 0] * alpha + b0;
                float x1 = c[h * 2 + 1] * alpha + b1;
                if (epi == 1) {
                    x0 = 0.5f * x0 * (1.0f + tanhf(GC * (x0 + 0.044715f * x0 * x0 * x0)));
                    x1 = 0.5f * x1 * (1.0f + tanhf(GC * (x1 + 0.044715f * x1 * x1 * x1)));
                }
                if (Cfz)
                    *(float2*)&Cfz[(size_t)row * N + col] = make_float2(x0, x1);
                if (Chz) {
                    __half2 hh, ll;
                    split_pair(x0, x1, hh, ll);
                    *(__half2*)&Chz[(size_t)row * N + col] = hh;
                    *(__half2*)&Clz[(size_t)row * N + col] = ll;
                }
            }
        }
    }
}

static void tg3(const __half* Ah, long long loA, long long sA,
                const __half* Bh, long long loB, long long sB,
                const float* bias, float* Cf, long long sC,
                __half* Ch, __half* Ch2, long long loC, long long sCp,
                int M, int N, int K, int batch, float alpha, int epi)
{
    dim3 grid(N / 128, M / 128, batch);
    tgemm3<<<grid, 512, TG_SMEM>>>(Ah, Bh, bias, Cf, Ch, Ch2, M, N, K,
                                   loA, loB, loC, sA, sB, sC, sCp, alpha, epi);
}

// ---------------------------------------------------------------------------
// 1-term GEMM (hi planes only): C = alpha * Ah @ Bh^T + bias
// Cf optional f32; Ch optional planes out (lo iff loC != 0).
// ---------------------------------------------------------------------------
#define T1STAGE 20480
#define T1_SMEM (4 * 20480)

__global__ void __launch_bounds__(512)
tgemm1(const __half* __restrict__ Ah0, const __half* __restrict__ Bh0,
       const float* __restrict__ bias, float* __restrict__ Cf,
       __half* __restrict__ Ch0,
       int M, int N, int K, long long loC,
       long long sA, long long sB, long long sC, long long sCp,
       float alpha)
{
    extern __shared__ char smem[];
    const uint32_t sbu = smem_u32(smem);
    const int t = threadIdx.x, w = t >> 5, lane = t & 31;
    const int wm = w & 3, wn = w >> 2;
    const int z = blockIdx.z;
    const int m0 = blockIdx.y * 128, n0 = blockIdx.x * 128;

    const __half* Ap = Ah0 + (size_t)z * sA + (size_t)(m0 + (t >> 2)) * K + (t & 3) * 8;
    const __half* Bp = Bh0 + (size_t)z * sB + (size_t)(n0 + (t >> 2)) * K + (t & 3) * 8;

    float acc[2][4][4];
#pragma unroll
    for (int i = 0; i < 2; i++)
#pragma unroll
        for (int j = 0; j < 4; j++)
#pragma unroll
            for (int e = 0; e < 4; e++) acc[i][j][e] = 0.0f;

    const int nch = K >> 5;
    const uint32_t sdbase = sbu + (uint32_t)((t >> 2) * 80 + (t & 3) * 16);

#define ISSUE1(ch) do {                                                     \
    uint32_t _sd = sdbase + (uint32_t)((ch) & 3) * T1STAGE;                 \
    const int _cb = (ch) * 32;                                              \
    cpasync16(_sd,         Ap + _cb);                                       \
    cpasync16(_sd + PLANE, Bp + _cb);                                       \
    CP_COMMIT();                                                            \
} while (0)

    ISSUE1(0);
    ISSUE1(1);
    if (nch > 2) ISSUE1(2);

    const uint32_t lmoff = (uint32_t)((lane & 15) * 80 + (lane >> 4) * 16);

    for (int ch = 0; ch < nch; ch++) {
        const int rem = nch - 1 - ch;
        if (rem >= 2)      { CP_WAIT(2); }
        else if (rem == 1) { CP_WAIT(1); }
        else               { CP_WAIT(0); }
        __syncthreads();
        if (ch + 3 < nch) ISSUE1(ch + 3);

        const uint32_t sAh = sbu + (uint32_t)(ch & 3) * T1STAGE;
        const uint32_t sBh = sAh + PLANE;
#pragma unroll
        for (int kk = 0; kk < 2; kk++) {
            uint32_t ah[2][4], bh[2][4];
#pragma unroll
            for (int mt = 0; mt < 2; mt++)
                ldsm4(ah[mt], sAh + (uint32_t)((wm * 32 + mt * 16) * 80 + kk * 32) + lmoff);
#pragma unroll
            for (int ng = 0; ng < 2; ng++)
                ldsm4(bh[ng], sBh + (uint32_t)((wn * 32 + ng * 16) * 80 + kk * 32) + lmoff);
#pragma unroll
            for (int ng = 0; ng < 2; ng++)
#pragma unroll
                for (int mt = 0; mt < 2; mt++)
#pragma unroll
                    for (int h2 = 0; h2 < 2; h2++)
                        mma_f16(acc[mt][ng * 2 + h2], ah[mt], bh[ng][h2], bh[ng][h2 + 2]);
        }
    }
#undef ISSUE1

    const int crow = m0 + wm * 32 + (lane >> 2);
    const int ccol = n0 + wn * 32 + (lane & 3) * 2;
    float* Cfz = Cf ? Cf + (size_t)z * sC : (float*)0;
    __half* Chz = Ch0 ? Ch0 + (size_t)z * sCp : (__half*)0;
    __half* Clz = (Chz && loC) ? Chz + loC : (__half*)0;
#pragma unroll
    for (int mt = 0; mt < 2; mt++) {
#pragma unroll
        for (int n8 = 0; n8 < 4; n8++) {
            const float* c = acc[mt][n8];
            const int col = ccol + n8 * 8;
            float b0 = bias ? bias[col]     : 0.0f;
            float b1 = bias ? bias[col + 1] : 0.0f;
#pragma unroll
            for (int h = 0; h < 2; h++) {
                const int row = crow + mt * 16 + h * 8;
                float x0 = c[h * 2 + 0] * alpha + b0;
                float x1 = c[h * 2 + 1] * alpha + b1;
                if (Cfz)
                    *(float2*)&Cfz[(size_t)row * N + col] = make_float2(x0, x1);
                if (Chz) {
                    __half2 hh, ll;
                    split_pair(x0, x1, hh, ll);
                    *(__half2*)&Chz[(size_t)row * N + col] = hh;
                    if (Clz) *(__half2*)&Clz[(size_t)row * N + col] = ll;
                }
            }
        }
    }
}

static void tg1(const __half* Ah, long long sA, const __half* Bh, long long sB,
                const float* bias, float* Cf, long long sC,
                __half* Ch, long long loC, long long sCp,
                int M, int N, int K, int batch, float alpha)
{
    dim3 grid(N / 128, M / 128, batch);
    tgemm1<<<grid, 512, T1_SMEM>>>(Ah, Bh, bias, Cf, Ch, M, N, K, loC,
                                   sA, sB, sC, sCp, alpha);
}

// 1-term, N-tile 64 (for a2 = k2 @ questions^T): 256 threads, 8 warps 4x2
#define B1STAGE 15360
#define T1N_SMEM (4 * 15360)

__global__ void __launch_bounds__(256)
tgemm1n64(const __half* __restrict__ Ah0, const __half* __restrict__ Bh0,
          float* __restrict__ Cf, int M, int N, int K, float alpha)
{
    extern __shared__ char smem[];
    const uint32_t sbu = smem_u32(smem);
    const int t = threadIdx.x, w = t >> 5, lane = t & 31;
    const int wm = w & 3, wn = w >> 2;
    const int m0 = blockIdx.y * 128, n0 = blockIdx.x * 64;

    const int arow = t >> 1, aseg = (t & 1) * 2;
    const int brow = t >> 2, bseg = t & 3;
    const __half* pa = Ah0 + (size_t)(m0 + arow) * K + aseg * 8;
    const __half* pb = Bh0 + (size_t)(n0 + brow) * K + bseg * 8;
    const uint32_t adst = sbu + (uint32_t)(arow * 80 + aseg * 16);
    const uint32_t bdst = sbu + 10240u + (uint32_t)(brow * 80 + bseg * 16);

    float acc[2][4][4];
#pragma unroll
    for (int i = 0; i < 2; i++)
#pragma unroll
        for (int j = 0; j < 4; j++)
#pragma unroll
            for (int e = 0; e < 4; e++) acc[i][j][e] = 0.0f;

    const int nch = K >> 5;

#define ISSUEN(ch) do {                                                     \
    uint32_t _st = (uint32_t)((ch) & 3) * B1STAGE;                          \
    const int _cb = (ch) * 32;                                              \
    cpasync16(adst + _st,      pa + _cb);                                   \
    cpasync16(adst + _st + 16, pa + _cb + 8);                               \
    cpasync16(bdst + _st,      pb + _cb);                                   \
    CP_COMMIT();                                                            \
} while (0)

    ISSUEN(0);
    ISSUEN(1);
    if (nch > 2) ISSUEN(2);

    const uint32_t lmoff = (uint32_t)((lane & 15) * 80 + (lane >> 4) * 16);

    for (int ch = 0; ch < nch; ch++) {
        const int rem = nch - 1 - ch;
        if (rem >= 2)      { CP_WAIT(2); }
        else if (rem == 1) { CP_WAIT(1); }
        else               { CP_WAIT(0); }
        __syncthreads();
        if (ch + 3 < nch) ISSUEN(ch + 3);

        const uint32_t sAh = sbu + (uint32_t)(ch & 3) * B1STAGE;
        const uint32_t sBh = sAh + 10240u;
#pragma unroll
        for (int kk = 0; kk < 2; kk++) {
            uint32_t ah[2][4], bh[2][4];
#pragma unroll
            for (int mt = 0; mt < 2; mt++)
                ldsm4(ah[mt], sAh + (uint32_t)((wm * 32 + mt * 16) * 80 + kk * 32) + lmoff);
#pragma unroll
            for (int ng = 0; ng < 2; ng++)
                ldsm4(bh[ng], sBh + (uint32_t)((wn * 32 + ng * 16) * 80 + kk * 32) + lmoff);
#pragma unroll
            for (int ng = 0; ng < 2; ng++)
#pragma unroll
                for (int mt = 0; mt < 2; mt++)
#pragma unroll
                    for (int h2 = 0; h2 < 2; h2++)
                        mma_f16(acc[mt][ng * 2 + h2], ah[mt], bh[ng][h2], bh[ng][h2 + 2]);
        }
    }
#undef ISSUEN

    const int crow = m0 + wm * 32 + (lane >> 2);
    const int ccol = n0 + wn * 32 + (lane & 3) * 2;
#pragma unroll
    for (int mt = 0; mt < 2; mt++)
#pragma unroll
        for (int n8 = 0; n8 < 4; n8++) {
            const float* c = acc[mt][n8];
            const int col = ccol + n8 * 8;
#pragma unroll
            for (int h = 0; h < 2; h++) {
                const int row = crow + mt * 16 + h * 8;
                *(float2*)&Cf[(size_t)row * N + col] =
                    make_float2(c[h * 2] * alpha, c[h * 2 + 1] * alpha);
            }
        }
}

// ---------------------------------------------------------------------------
// Transpose + convert to planes (lo written iff loOff != 0)
// ---------------------------------------------------------------------------
__global__ void trans_conv(const float* __restrict__ in, __half* __restrict__ oh,
                           long long loOff, int R, int C,
                           long long sI, long long sO, const int* __restrict__ ids)
{
    __shared__ float tile[32][33];
    const int z = blockIdx.z;
    size_t ib = ids ? (size_t)ids[z] * sI : (size_t)z * sI;
    const float* ip = in + ib;
    __half* ohz = oh + (size_t)z * sO;
    __half* olz = loOff ? ohz + loOff : (__half*)0;
    const int c0 = blockIdx.x * 32, r0 = blockIdx.y * 32;
    const int tx = threadIdx.x, ty = threadIdx.y;
#pragma unroll
    for (int k = 0; k < 32; k += 8)
        tile[ty + k][tx] = ip[(size_t)(r0 + ty + k) * C + c0 + tx];
    __syncthreads();
    const int rr = (tx & 15) * 2, chf = tx >> 4;
#pragma unroll
    for (int k = 0; k < 2; k++) {
        int cc = ty + chf * 8 + k * 16;
        __half2 h, l;
        split_pair(tile[rr][cc], tile[rr + 1][cc], h, l);
        *(__half2*)&ohz[(size_t)(c0 + cc) * R + r0 + rr] = h;
        if (olz) *(__half2*)&olz[(size_t)(c0 + cc) * R + r0 + rr] = l;
    }
}

__global__ void conv_planes(const float* __restrict__ in, __half* __restrict__ oh,
                            long long lo)
{
    size_t idx = (size_t)blockIdx.x * 512 + (size_t)threadIdx.x * 2;
    float2 v = *(const float2*)&in[idx];
    __half2 h, l;
    split_pair(v.x, v.y, h, l);
    *(__half2*)&oh[idx] = h;
    if (lo) *(__half2*)&(oh + lo)[idx] = l;
}

__global__ void rope_table_kernel()
{
    int s = blockIdx.x;
    int i = threadIdx.x;
    float invf = 1.0f / powf(10000.0f, (float)i / 256.0f);
    float angf = (float)s * invf;
    double ang = (double)angf;
    g_sin[s * 256 + i] = (float)sin(ang);
    g_cos[s * 256 + i] = (float)cos(ang);
}

__global__ void bias_prep(const float* __restrict__ pos, float* __restrict__ out, int mode)
{
    int n = blockIdx.x, t = threadIdx.x;
    for (int c = t; c < 1024; c += 256) {
        float p = pos[n * 1024 + c];
        out[n * 1024 + c] = (mode == 1) ? logf(p) : (logf(p) - log1pf(-p));
    }
}

// Softmax 1024 cols + bias, emits hi plane only
__global__ void softmax1024_planes(const float* __restrict__ S, const float* __restrict__ bias,
                                   __half* __restrict__ oh)
{
    const int row = blockIdx.x, t = threadIdx.x;
    const float* sr = S + (size_t)row * 1024;
    const float* pb = bias + (size_t)(row >> 10) * 1024;
    float2 a  = *(const float2*)&sr[2 * t];
    float2 b2 = *(const float2*)&sr[512 + 2 * t];
    float2 ba = *(const float2*)&pb[2 * t];
    float2 bb = *(const float2*)&pb[512 + 2 * t];
    float v0 = a.x + ba.x, v1 = a.y + ba.y, v2 = b2.x + bb.x, v3 = b2.y + bb.y;

    __shared__ float red[256];
    float mx = fmaxf(fmaxf(v0, v1), fmaxf(v2, v3));
    red[t] = mx; __syncthreads();
    for (int s = 128; s > 0; s >>= 1) { if (t < s) red[t] = fmaxf(red[t], red[t + s]); __syncthreads(); }
    mx = red[0]; __syncthreads();

    float e0 = expf(v0 - mx), e1 = expf(v1 - mx), e2 = expf(v2 - mx), e3 = expf(v3 - mx);
    red[t] = e0 + e1 + e2 + e3; __syncthreads();
    for (int s = 128; s > 0; s >>= 1) { if (t < s) red[t] += red[t + s]; __syncthreads(); }
    float inv = 1.0f / red[0];

    size_t o = (size_t)row * 1024 + 2 * t;
    *(__half2*)&oh[o]       = __floats2half2_rn(e0 * inv, e1 * inv);
    *(__half2*)&oh[o + 512] = __floats2half2_rn(e2 * inv, e3 * inv);
}

// Softmax 64 cols, warp/row, emits hi plane only
__global__ void softmax64_planes(const float* __restrict__ S, __half* __restrict__ oh)
{
    const int row = blockIdx.x * 8 + (threadIdx.x >> 5);
    const int lane = threadIdx.x & 31;
    const float* sr = S + (size_t)row * 64;
    float2 v = *(const float2*)&sr[lane * 2];
    float mx = fmaxf(v.x, v.y);
#pragma unroll
    for (int o = 16; o > 0; o >>= 1)
        mx = fmaxf(mx, __shfl_xor_sync(0xFFFFFFFF, mx, o));
    float e0 = expf(v.x - mx), e1 = expf(v.y - mx);
    float s = e0 + e1;
#pragma unroll
    for (int o = 16; o > 0; o >>= 1)
        s += __shfl_xor_sync(0xFFFFFFFF, s, o);
    float inv = 1.0f / s;
    *(__half2*)&oh[(size_t)row * 64 + lane * 2] = __floats2half2_rn(e0 * inv, e1 * inv);
}

__global__ void softmax_f32(float* __restrict__ S, const float* __restrict__ bias,
                            int cols, int rpb)
{
    int row = blockIdx.x;
    float* sr = S + (size_t)row * cols;
    const float* pb = bias + (size_t)(row / rpb) * cols;
    int t = threadIdx.x;
    __shared__ float red[256];

    float mx = -1e30f;
    for (int c = t; c < cols; c += 256) {
        float v = sr[c] + pb[c];
        sr[c] = v;
        mx = fmaxf(mx, v);
    }
    red[t] = mx; __syncthreads();
    for (int s = 128; s > 0; s >>= 1) { if (t < s) red[t] = fmaxf(red[t], red[t + s]); __syncthreads(); }
    mx = red[0]; __syncthreads();

    float sum = 0.0f;
    for (int c = t; c < cols; c += 256) {
        float e = expf(sr[c] - mx);
        sr[c] = e;
        sum += e;
    }
    red[t] = sum; __syncthreads();
    for (int s = 128; s > 0; s >>= 1) { if (t < s) red[t] += red[t + s]; __syncthreads(); }
    float inv = 1.0f / red[0];
    for (int c = t; c < cols; c += 256) sr[c] *= inv;
}

__global__ void ln_kernel(const float* __restrict__ Xin, const float* __restrict__ R,
                          const float* __restrict__ g, const float* __restrict__ b,
                          float* __restrict__ Xout,
                          __half* __restrict__ oh, long long lo)
{
    int row = blockIdx.x;
    int t   = threadIdx.x;
    const float* xr = Xin + (size_t)row * DD;
    const float* rr = R + (size_t)row * DD;

    float v0 = xr[2 * t] + rr[2 * t];
    float v1 = xr[2 * t + 1] + rr[2 * t + 1];

    __shared__ float red[256];
    red[t] = v0 + v1; __syncthreads();
    for (int s = 128; s > 0; s >>= 1) { if (t < s) red[t] += red[t + s]; __syncthreads(); }
    float m = red[0] * (1.0f / 512.0f);
    __syncthreads();

    float d0 = v0 - m, d1 = v1 - m;
    red[t] = d0 * d0 + d1 * d1; __syncthreads();
    for (int s = 128; s > 0; s >>= 1) { if (t < s) red[t] += red[t + s]; __syncthreads(); }
    float var = red[0] * (1.0f / 512.0f);
    float inv = rsqrtf(var + 1e-5f);

    float o0 = d0 * inv * g[2 * t]     + b[2 * t];
    float o1 = d1 * inv * g[2 * t + 1] + b[2 * t + 1];
    float* xo = Xout + (size_t)row * DD;
    xo[2 * t]     = o0;
    xo[2 * t + 1] = o1;

    __half2 h, l;
    split_pair(o0, o1, h, l);
    size_t o = (size_t)row * DD + 2 * t;
    *(__half2*)&oh[o] = h;
    *(__half2*)&(oh + lo)[o] = l;
}

__global__ void vgate_kernel(const float* __restrict__ F, const float* __restrict__ raw,
                             const float* __restrict__ Wig, const float* __restrict__ big,
                             float* __restrict__ V)
{
    int row = blockIdx.x;
    int t   = threadIdx.x;
    const float* fr = F + (size_t)row * DD;
    __shared__ float red[256];
    float s = fr[t] * Wig[t] + fr[t + 256] * Wig[t + 256];
    red[t] = s; __syncthreads();
    for (int k = 128; k > 0; k >>= 1) { if (t < k) red[t] += red[t + k]; __syncthreads(); }
    float gte = 1.0f / (1.0f + expf(-(red[0] + big[0])));
    const float* rr = raw + (size_t)row * DD;
    float* vr = V + (size_t)row * DD;
    vr[t]       = rr[t]       * gte;
    vr[t + 256] = rr[t + 256] * gte;
}

__global__ void out_kernel(const float* __restrict__ FU, const float* __restrict__ A2,
                           const float* __restrict__ PD,
                           const float* __restrict__ Wu1, const float* __restrict__ bu1,
                           const float* __restrict__ Wu2, const float* __restrict__ bu2,
                           const float* __restrict__ b1,
                           float* __restrict__ out, float* __restrict__ gate)
{
    int row = blockIdx.x;
    int t   = threadIdx.x;
    const float* fu = FU + (size_t)row * DD;
    const float* a2 = A2 + (size_t)row * DD;
    const float* pd = PD + (size_t)row * DD;

    __shared__ float red[256];
    float s = fu[t] * Wu1[t] + fu[t + 256] * Wu1[t + 256]
            + a2[t] * Wu2[t] + a2[t + 256] * Wu2[t + 256];
    red[t] = s; __syncthreads();
    for (int k = 128; k > 0; k >>= 1) { if (t < k) red[t] += red[t + k]; __syncthreads(); }
    float z = red[0] + bu1[0] + bu2[0] + b1[0] - 4.0f;
    float g = 1.0f / (1.0f + expf(-z));

    float* orow = out + (size_t)row * DD;
    orow[t]       = pd[t]       * (1.0f - g) + a2[t]       * g;
    orow[t + 256] = pd[t + 256] * (1.0f - g) + a2[t + 256] * g;
    if (t == 0) gate[row] = g;
}

#define BM 64
#define BN 64
#define BK 16

__global__ void gemm_kernel(const float* __restrict__ A,
                            const float* __restrict__ Bm,
                            const float* __restrict__ bias,
                            float* __restrict__ C,
                            int M, int N, int K,
                            long long sA, long long sB, long long sC,
                            float alpha, int transB, int epi)
{
    const int bz = blockIdx.z;
    A  += (size_t)bz * sA;
    Bm += (size_t)bz * sB;
    C  += (size_t)bz * sC;

    const int m0 = blockIdx.y * BM;
    const int n0 = blockIdx.x * BN;

    __shared__ float As[BK][BM + 4];
    __shared__ float Bs[BK][BN + 4];

    const int t  = threadIdx.x;
    const int tx = t & 15;
    const int ty = t >> 4;

    float acc[4][4] = {};

    const int arow = t >> 2;
    const int akc  = (t & 3) * 4;
    const int kb   = t >> 4;
    const int nb   = (t & 15) * 4;

    for (int k0 = 0; k0 < K; k0 += BK) {
        float4 av = *(const float4*)&A[(size_t)(m0 + arow) * K + k0 + akc];
        As[akc + 0][arow] = av.x;
        As[akc + 1][arow] = av.y;
        As[akc + 2][arow] = av.z;
        As[akc + 3][arow] = av.w;

        if (!transB) {
            float4 bv = *(const float4*)&Bm[(size_t)(k0 + kb) * N + n0 + nb];
            *(float4*)&Bs[kb][nb] = bv;
        } else {
            float4 bv = *(const float4*)&Bm[(size_t)(n0 + arow) * K + k0 + akc];
            Bs[akc + 0][arow] = bv.x;
            Bs[akc + 1][arow] = bv.y;
            Bs[akc + 2][arow] = bv.z;
            Bs[akc + 3][arow] = bv.w;
        }
        __syncthreads();

#pragma unroll
        for (int k = 0; k < BK; k++) {
            float4 a = *(const float4*)&As[k][ty * 4];
            float4 b = *(const float4*)&Bs[k][tx * 4];
            acc[0][0] += a.x * b.x; acc[0][1] += a.x * b.y;
            acc[0][2] += a.x * b.z; acc[0][3] += a.x * b.w;
            acc[1][0] += a.y * b.x; acc[1][1] += a.y * b.y;
            acc[1][2] += a.y * b.z; acc[1][3] += a.y * b.w;
            acc[2][0] += a.z * b.x; acc[2][1] += a.z * b.y;
            acc[2][2] += a.z * b.z; acc[2][3] += a.z * b.w;
            acc[3][0] += a.w * b.x; acc[3][1] += a.w * b.y;
            acc[3][2] += a.w * b.z; acc[3][3] += a.w * b.w;
        }
        __syncthreads();
    }

#pragma unroll
    for (int i = 0; i < 4; i++) {
        const int row = m0 + ty * 4 + i;
        float v[4];
#pragma unroll
        for (int j = 0; j < 4; j++) {
            float x = acc[i][j] * alpha;
            if (bias) x += bias[n0 + tx * 4 + j];
            v[j] = x;
        }
        *(float4*)&C[(size_t)row * N + n0 + tx * 4] = make_float4(v[0], v[1], v[2], v[3]);
    }
}

static void sgemm_launch(const float* A, const float* B, const float* bias, float* C,
                         int M, int N, int K, int batch,
                         long long sA, long long sB, long long sC,
                         float alpha, int transB)
{
    dim3 grid(N / BN, M / BM, batch);
    gemm_kernel<<<grid, 256>>>(A, B, bias, C, M, N, K, sA, sB, sC, alpha, transB, 0);
}

static void run_encoder(const float* Xin0, float* X, int nb,
                        const __half* initP, long long initLo,
                        const float* biasRows,
                        const __half* PW,
                        const float* bqkv, const float* bo,
                        const float* ln, const float* bff,
                        float* bV, float* bK, float* bS,
                        __half* Pq, __half* Pk, __half* Pvt,
                        __half* Pp, __half* Pbq, __half* Ph,
                        __half* Px, int skip_first_qkv)
{
    const int rows = nb * SS;
    const float sc = 1.0f / sqrtf((float)DD);
    for (int l = 0; l < 2; l++) {
        const __half* AP = (l == 0) ? initP : Px;
        const long long loAP = (l == 0) ? initLo : LO;
        if (!(l == 0 && skip_first_qkv))
            tg3(AP, loAP, 0, PW + (size_t)(l * 3) * 262144, WLO, 0,
                bqkv + (size_t)l * 1536, bV, 0, Pq, Pk, 0, 0,
                rows, 1536, 512, 1, 1.0f, 2);
        trans_conv<<<dim3(16, 32, nb), dim3(32, 8)>>>(bV, Pvt, 0, 1024, 512,
                                                      524288, 524288, nullptr);
        // scores = Q @ K^T * sc  (1-term)
        tg1(Pq, 524288, Pk, 524288, nullptr, bS, 1048576, nullptr, 0, 0,
            1024, 1024, 512, nb, sc);
        softmax1024_planes<<<rows, 256>>>(bS, biasRows, Pp);
        // T = A @ V (1-term) -> Pbq hi+lo planes
        tg1(Pp, 1048576, Pvt, 524288, nullptr, nullptr, 0, Pbq, LO, 524288,
            1024, 512, 1024, nb, 1.0f);
        // O = T @ Wo + bo (3-term)
        tg3(Pbq, LO, 0, PW + (size_t)(6 + l) * 262144, WLO, 0, bo + l * 512,
            bK, 0, nullptr, nullptr, 0, 0, rows, 512, 512, 1, 1.0f, 0);
        ln_kernel<<<rows, 256>>>((l == 0) ? Xin0 : X, bK,
                                 ln + l * 2048, ln + l * 2048 + 512, X, Px, LO);
        tg3(Px, LO, 0, PW + (size_t)(8 + 2 * l) * 262144, WLO, 0, bff + l * 1024,
            nullptr, 0, Ph, nullptr, LO, 0, rows, 512, 512, 1, 1.0f, 1);
        tg3(Ph, LO, 0, PW + (size_t)(9 + 2 * l) * 262144, WLO, 0, bff + l * 1024 + 512,
            bK, 0, nullptr, nullptr, 0, 0, rows, 512, 512, 1, 1.0f, 0);
        ln_kernel<<<rows, 256>>>(X, bK, ln + l * 2048 + 1024, ln + l * 2048 + 1536,
                                 X, Px, LO);
    }
}

extern "C" void kernel_launch(void* const* d_in, const int* in_sizes, int n_in,
                              void* d_out, int out_size)
{
    const float* raw_emb   = (const float*)d_in[0];
    const float* pos_w     = (const float*)d_in[1];
    const float* post_dec  = (const float*)d_in[2];
    const float* pos_r     = (const float*)d_in[3];
    const float* questions = (const float*)d_in[4];
    const float* W_k       = (const float*)d_in[5];
    const float* W_ig      = (const float*)d_in[6];
    const float* b_ig      = (const float*)d_in[7];
    const float* W_u1      = (const float*)d_in[8];
    const float* b_u1      = (const float*)d_in[9];
    const float* W_u2      = (const float*)d_in[10];
    const float* b_u2      = (const float*)d_in[11];
    const float* b1        = (const float*)d_in[12];
    const float* W_ok      = (const float*)d_in[13];
    const float* b_ok      = (const float*)d_in[14];
    const float* encw_Wqkv = (const float*)d_in[15];
    const float* encw_bqkv = (const float*)d_in[16];
    const float* encw_Wo   = (const float*)d_in[17];
    const float* encw_bo   = (const float*)d_in[18];
    const float* encw_ln   = (const float*)d_in[19];
    const float* encw_Wff  = (const float*)d_in[20];
    const float* encw_bff  = (const float*)d_in[21];
    const float* encr_Wqkv = (const float*)d_in[22];
    const float* encr_bqkv = (const float*)d_in[23];
    const float* encr_Wo   = (const float*)d_in[24];
    const float* encr_bo   = (const float*)d_in[25];
    const float* encr_ln   = (const float*)d_in[26];
    const float* encr_Wff  = (const float*)d_in[27];
    const float* encr_bff  = (const float*)d_in[28];
    const int*   lookup    = (const int*)d_in[29];

    float* out  = (float*)d_out;
    float* gate = out + (size_t)NBB * SS * DD;

    float *pX, *pV, *pK, *pS, *pKd, *pVd, *pA1, *pA2s, *pA2, *pBW, *pBR;
    __half *pPW, *pPraw, *pPpd, *pPx, *pPq, *pPk, *pPvt, *pPp, *pPbq, *pPh,
           *pPa2, *pPsel, *pPqst;
    cudaGetSymbolAddress((void**)&pX,    g_X);
    cudaGetSymbolAddress((void**)&pV,    g_V);
    cudaGetSymbolAddress((void**)&pK,    g_Kb);
    cudaGetSymbolAddress((void**)&pS,    g_S);
    cudaGetSymbolAddress((void**)&pKd,   g_Kdoc);
    cudaGetSymbolAddress((void**)&pVd,   g_Vdoc);
    cudaGetSymbolAddress((void**)&pA1,   g_A1S);
    cudaGetSymbolAddress((void**)&pA2s,  g_A2SC);
    cudaGetSymbolAddress((void**)&pA2,   g_A2);
    cudaGetSymbolAddress((void**)&pBW,   g_BIASW);
    cudaGetSymbolAddress((void**)&pBR,   g_BIASR);
    cudaGetSymbolAddress((void**)&pPW,   g_PW);
    cudaGetSymbolAddress((void**)&pPraw, g_Praw);
    cudaGetSymbolAddress((void**)&pPpd,  g_Ppd);
    cudaGetSymbolAddress((void**)&pPx,   g_Px);
    cudaGetSymbolAddress((void**)&pPq,   g_Pq);
    cudaGetSymbolAddress((void**)&pPk,   g_Pk);
    cudaGetSymbolAddress((void**)&pPvt,  g_Pvt);
    cudaGetSymbolAddress((void**)&pPp,   g_Pp);
    cudaGetSymbolAddress((void**)&pPbq,  g_Pbq);
    cudaGetSymbolAddress((void**)&pPh,   g_Ph);
    cudaGetSymbolAddress((void**)&pPa2,  g_Pa2);
    cudaGetSymbolAddress((void**)&pPsel, g_Psel);
    cudaGetSymbolAddress((void**)&pPqst, g_Pqst);

    cudaFuncSetAttribute(tgemm3,    cudaFuncAttributeMaxDynamicSharedMemorySize, TG_SMEM);
    cudaFuncSetAttribute(tgemm1,    cudaFuncAttributeMaxDynamicSharedMemorySize, T1_SMEM);
    cudaFuncSetAttribute(tgemm1n64, cudaFuncAttributeMaxDynamicSharedMemorySize, T1N_SMEM);

    const float scD = 1.0f / sqrtf((float)DD);

    trans_conv<<<dim3(16, 16, 6), dim3(32, 8)>>>(encw_Wqkv, pPW + 0LL  * 262144, WLO, 512, 512, 262144, 262144, nullptr);
    conv_planes<<<NDOC * SS, 256>>>(raw_emb, pPraw, 4194304LL);
    rope_table_kernel<<<1024, 256>>>();
    trans_conv<<<dim3(16, 16, 2), dim3(32, 8)>>>(encw_Wo,   pPW + 6LL  * 262144, WLO, 512, 512, 262144, 262144, nullptr);
    trans_conv<<<dim3(16, 16, 4), dim3(32, 8)>>>(encw_Wff,  pPW + 8LL  * 262144, WLO, 512, 512, 262144, 262144, nullptr);

    // write-side encoder
    tg3(pPraw, 4194304LL, 0, pPW, WLO, 0, encw_bqkv, pV, 0, pPq, pPk, 0, 0,
        NDOC * SS, 1536, 512, 1, 1.0f, 2);
    bias_prep<<<NDOC, 256>>>(pos_w, pBW, 1);
    run_encoder(raw_emb, pX, NDOC, pPraw, 4194304LL, pBW,
                pPW, encw_bqkv, encw_bo, encw_ln, encw_bff,
                pV, pK, pS, pPq, pPk, pPvt, pPp, pPbq, pPh, pPx, 1);

    vgate_kernel<<<NDOC * SS, 256>>>(pX, raw_emb, W_ig, b_ig, pVd);
    trans_conv<<<dim3(16, 16, 1), dim3(32, 8)>>>(W_k, pPW + 24LL * 262144, WLO, 512, 512, 262144, 262144, nullptr);
    tg3(pPraw, 4194304LL, 0, pPW + 24LL * 262144, WLO, 0, nullptr, pKd, 0,
        nullptr, nullptr, 0, 0, NDOC * SS, 512, 512, 1, 1.0f, 0);
    sgemm_launch(questions, pKd, nullptr, pS, QQ, SS, DD, NDOC, 0, 524288, 65536, scD, 1);
    softmax_f32<<<NDOC * QQ, 256>>>(pS, pBW, SS, QQ);
    sgemm_launch(pS, pVd, nullptr, pA1, QQ, DD, SS, NDOC, 65536, 524288, 32768, 1.0f, 0);

    // read-side encoder
    trans_conv<<<dim3(16, 16, 6), dim3(32, 8)>>>(encr_Wqkv, pPW + 12LL * 262144, WLO, 512, 512, 262144, 262144, nullptr);
    trans_conv<<<dim3(16, 16, 2), dim3(32, 8)>>>(encr_Wo,   pPW + 18LL * 262144, WLO, 512, 512, 262144, 262144, nullptr);
    trans_conv<<<dim3(16, 16, 4), dim3(32, 8)>>>(encr_Wff,  pPW + 20LL * 262144, WLO, 512, 512, 262144, 262144, nullptr);
    conv_planes<<<NBB * SS, 256>>>(post_dec, pPpd, 8388608LL);
    bias_prep<<<NBB, 256>>>(pos_r, pBR, 2);
    run_encoder(post_dec, pX, NBB, pPpd, 8388608LL, pBR,
                pPW + 12LL * 262144, encr_bqkv, encr_bo, encr_ln, encr_bff,
                pV, pK, pS, pPq, pPk, pPvt, pPp, pPbq, pPh, pPx, 0);

    // k2 / a2 / A2 / out
    trans_conv<<<dim3(16, 16, 1), dim3(32, 8)>>>(W_ok, pPW + 25LL * 262144, WLO, 512, 512, 262144, 262144, nullptr);
    conv_planes<<<QQ, 256>>>(questions, pPqst, 0);
    // k2 = post_dec @ W_ok + b_ok (1-term, hi-only planes out -> Pq reuse)
    tg1(pPpd, 0, pPW + 25LL * 262144, 0, b_ok, nullptr, 0, pPq, 0, 0,
        NBB * SS, 512, 512, 1, 1.0f);
    // a2 = softmax(k2 @ questions^T / 8)
    {
        dim3 grid(1, (NBB * SS) / 128, 1);
        tgemm1n64<<<grid, 256, T1N_SMEM>>>(pPq, pPqst, pA2s, NBB * SS, QQ, DD, 0.125f);
    }
    softmax64_planes<<<NBB * SS / 8, 256>>>(pA2s, pPa2);
    trans_conv<<<dim3(16, 2, 16), dim3(32, 8)>>>(pA1, pPsel, 0, 64, 512, 32768, 32768, lookup);
    // A2 = a2 @ selA (1-term)
    tg1(pPa2, 65536, pPsel, 32768, nullptr, pA2, 524288, nullptr, 0, 0,
        1024, 512, 64, NBB, 1.0f);

    out_kernel<<<NBB * SS, 256>>>(pX, pA2, post_dec,
                                  W_u1, b_u1, W_u2, b_u2, b1,
                                  out, gate);

    (void)in_sizes; (void)n_in; (void)out_size;
}

// round 10
// speedup vs baseline: 3.0832x; 1.1268x over previous
#include <cuda_runtime.h>
#include <cuda_fp16.h>
#include <math.h>
#include <stdint.h>

#define DD     512
#define SS     1024
#define NBB    16
#define QQ     64
#define NDOC   8

// ---- read-side f32 scratch ----
__device__ float g_X   [16384 * 512];
__device__ float g_V   [16384 * 512];
__device__ float g_Kb  [16384 * 512];
// ---- write-side f32 scratch ----
__device__ float g_Xw  [8192 * 512];
__device__ float g_Vw  [8192 * 512];
__device__ float g_Kw  [8192 * 512];
__device__ float g_S1  [8 * 64 * 1024];
__device__ float g_Kdoc[8192 * 512];
__device__ float g_Vdoc[8192 * 512];
__device__ float g_A1S [8 * 64 * 512];
__device__ float g_A2SC[16384 * 64];
__device__ float g_A2  [16384 * 512];
__device__ float g_sin [1024 * 256];
__device__ float g_cos [1024 * 256];
__device__ float g_BIASW[8 * 1024];
__device__ float g_BIASR[16 * 1024];

#define WLO 6815744LL
#define LO  8388608LL
#define LOW 4194304LL
__device__ __align__(16) __half g_PW  [2 * 26 * 262144];
__device__ __align__(16) __half g_Praw[2 * 4194304];
__device__ __align__(16) __half g_Ppd [2 * 8388608];
// read-side planes
__device__ __align__(16) __half g_Px  [2 * 8388608];
__device__ __align__(16) __half g_Pq  [8388608];
__device__ __align__(16) __half g_Pk  [8388608];
__device__ __align__(16) __half g_Pvt [8388608];
__device__ __align__(16) __half g_Pp  [16777216];
__device__ __align__(16) __half g_Pbq [2 * 8388608];
__device__ __align__(16) __half g_Ph  [2 * 8388608];
__device__ __align__(16) __half g_Sh  [16 * 1048576];
// write-side planes
__device__ __align__(16) __half g_Pxw [2 * 4194304];
__device__ __align__(16) __half g_Pqw [4194304];
__device__ __align__(16) __half g_Pkw [4194304];
__device__ __align__(16) __half g_Pvtw[4194304];
__device__ __align__(16) __half g_Ppw [8388608];
__device__ __align__(16) __half g_Pbqw[2 * 4194304];
__device__ __align__(16) __half g_Phw [2 * 4194304];
__device__ __align__(16) __half g_Shw [8 * 1048576];
// misc planes
__device__ __align__(16) __half g_Pk2 [8388608];
__device__ __align__(16) __half g_Pa2 [1048576];
__device__ __align__(16) __half g_Psel[524288];
__device__ __align__(16) __half g_Pqst[32768];

__device__ __forceinline__ uint32_t smem_u32(const void* p) {
    uint32_t a;
    asm("{ .reg .u64 t; cvta.to.shared.u64 t, %1; cvt.u32.u64 %0, t; }"
        : "=r"(a) : "l"(p));
    return a;
}

__device__ __forceinline__ void ldsm4(uint32_t* r, uint32_t addr) {
    asm volatile("ldmatrix.sync.aligned.m8n8.x4.shared.b16 {%0,%1,%2,%3}, [%4];"
                 : "=r"(r[0]), "=r"(r[1]), "=r"(r[2]), "=r"(r[3]) : "r"(addr));
}

__device__ __forceinline__ void mma_f16(float* c, const uint32_t* a,
                                        uint32_t b0, uint32_t b1) {
    asm volatile(
        "mma.sync.aligned.m16n8k16.row.col.f32.f16.f16.f32 "
        "{%0,%1,%2,%3}, {%4,%5,%6,%7}, {%8,%9}, {%0,%1,%2,%3};"
        : "+f"(c[0]), "+f"(c[1]), "+f"(c[2]), "+f"(c[3])
        : "r"(a[0]), "r"(a[1]), "r"(a[2]), "r"(a[3]), "r"(b0), "r"(b1));
}

__device__ __forceinline__ void cpasync16(uint32_t dst, const void* src) {
    asm volatile("cp.async.cg.shared.global [%0], [%1], 16;" :: "r"(dst), "l"(src));
}
#define CP_COMMIT() asm volatile("cp.async.commit_group;" ::: "memory")
#define CP_WAIT(n)  asm volatile("cp.async.wait_group %0;" :: "n"(n) : "memory")

__device__ __forceinline__ void split_pair(float x0, float x1,
                                           __half2& h, __half2& l) {
    h = __floats2half2_rn(x0, x1);
    l = __floats2half2_rn(x0 - __low2float(h), x1 - __high2float(h));
}

// ---------------------------------------------------------------------------
// 3-term split GEMM (fp16 planes)
// ---------------------------------------------------------------------------
#define PLANE  10240
#define TSTAGE 40960
#define TG_SMEM (4 * 40960)

__global__ void __launch_bounds__(512)
tgemm3(const __half* __restrict__ Ah0, const __half* __restrict__ Bh0,
       const float* __restrict__ bias, float* __restrict__ Cf,
       __half* __restrict__ Ch0, __half* __restrict__ Ch2,
       int M, int N, int K,
       long long loA, long long loB, long long loC,
       long long sA, long long sB, long long sC, long long sCp,
       float alpha, int epi)
{
    extern __shared__ char smem[];
    const uint32_t sbu = smem_u32(smem);
    const int t = threadIdx.x, w = t >> 5, lane = t & 31;
    const int wm = w & 3, wn = w >> 2;
    const int z = blockIdx.z;
    const int m0 = blockIdx.y * 128, n0 = blockIdx.x * 128;

    const __half* Ah = Ah0 + (size_t)z * sA;
    const __half* Bh = Bh0 + (size_t)z * sB;

    const int lrow = t >> 2, seg = t & 3;
    const __half* pr[4];
    pr[0] = Ah + (size_t)(m0 + lrow) * K + seg * 8;
    pr[1] = pr[0] + loA;
    pr[2] = Bh + (size_t)(n0 + lrow) * K + seg * 8;
    pr[3] = pr[2] + loB;

    float acc[2][4][4];
#pragma unroll
    for (int i = 0; i < 2; i++)
#pragma unroll
        for (int j = 0; j < 4; j++)
#pragma unroll
            for (int e = 0; e < 4; e++) acc[i][j][e] = 0.0f;

    const int nch = K >> 5;
    const uint32_t sdbase = sbu + (uint32_t)(lrow * 80 + seg * 16);

#define ISSUE(ch) do {                                                      \
    uint32_t _sd = sdbase + (uint32_t)((ch) & 3) * TSTAGE;                  \
    const int _cb = (ch) * 32;                                              \
    _Pragma("unroll")                                                       \
    for (int _p = 0; _p < 4; _p++)                                          \
        cpasync16(_sd + _p * PLANE, pr[_p] + _cb);                          \
    CP_COMMIT();                                                            \
} while (0)

    ISSUE(0);
    ISSUE(1);
    if (nch > 2) ISSUE(2);

    const uint32_t lmoff = (uint32_t)((lane & 15) * 80 + (lane >> 4) * 16);

    for (int ch = 0; ch < nch; ch++) {
        const int rem = nch - 1 - ch;
        if (rem >= 2)      { CP_WAIT(2); }
        else if (rem == 1) { CP_WAIT(1); }
        else               { CP_WAIT(0); }
        __syncthreads();
        if (ch + 3 < nch) ISSUE(ch + 3);

        const uint32_t sAh = sbu + (uint32_t)(ch & 3) * TSTAGE;
        const uint32_t sBh = sAh + 2 * PLANE;
#pragma unroll
        for (int kk = 0; kk < 2; kk++) {
            uint32_t ah[2][4], al[2][4], bh[2][4], bl[2][4];
#pragma unroll
            for (int mt = 0; mt < 2; mt++) {
                uint32_t aaddr = sAh + (uint32_t)((wm * 32 + mt * 16) * 80 + kk * 32) + lmoff;
                ldsm4(ah[mt], aaddr);
                ldsm4(al[mt], aaddr + PLANE);
            }
#pragma unroll
            for (int ng = 0; ng < 2; ng++) {
                uint32_t baddr = sBh + (uint32_t)((wn * 32 + ng * 16) * 80 + kk * 32) + lmoff;
                ldsm4(bh[ng], baddr);
                ldsm4(bl[ng], baddr + PLANE);
            }
#pragma unroll
            for (int ng = 0; ng < 2; ng++)
#pragma unroll
                for (int mt = 0; mt < 2; mt++)
#pragma unroll
                    for (int h2 = 0; h2 < 2; h2++)
                        mma_f16(acc[mt][ng * 2 + h2], ah[mt], bh[ng][h2], bh[ng][h2 + 2]);
#pragma unroll
            for (int ng = 0; ng < 2; ng++)
#pragma unroll
                for (int mt = 0; mt < 2; mt++)
#pragma unroll
                    for (int h2 = 0; h2 < 2; h2++)
                        mma_f16(acc[mt][ng * 2 + h2], ah[mt], bl[ng][h2], bl[ng][h2 + 2]);
#pragma unroll
            for (int ng = 0; ng < 2; ng++)
#pragma unroll
                for (int mt = 0; mt < 2; mt++)
#pragma unroll
                    for (int h2 = 0; h2 < 2; h2++)
                        mma_f16(acc[mt][ng * 2 + h2], al[mt], bh[ng][h2], bh[ng][h2 + 2]);
        }
    }
#undef ISSUE

    const float GC = 0.7978845608028654f;
    const int crow = m0 + wm * 32 + (lane >> 2);
    const int ccol = n0 + wn * 32 + (lane & 3) * 2;

    if (epi == 2) {
#pragma unroll
        for (int mt = 0; mt < 2; mt++) {
#pragma unroll
            for (int n8 = 0; n8 < 4; n8++) {
                const float* c = acc[mt][n8];
                const int col = ccol + n8 * 8;
                float b0 = bias[col], b1 = bias[col + 1];
#pragma unroll
                for (int h = 0; h < 2; h++) {
                    const int row = crow + mt * 16 + h * 8;
                    float x0 = c[h * 2 + 0] + b0;
                    float x1 = c[h * 2 + 1] + b1;
                    if (col < 1024) {
                        const int s = row & (SS - 1);
                        const int i = (col & 511) >> 1;
                        float sn = g_sin[s * 256 + i];
                        float cs = g_cos[s * 256 + i];
                        float y0 = x0 * cs - x1 * sn;
                        float y1 = x0 * sn + x1 * cs;
                        __half* dst = (col < 512) ? Ch0 : Ch2;
                        size_t off = (size_t)row * 512 + (col & 511);
                        *(__half2*)&dst[off] = __floats2half2_rn(y0, y1);
                    } else {
                        *(float2*)&Cf[(size_t)row * 512 + (col - 1024)] =
                            make_float2(x0, x1);
                    }
                }
            }
        }
        return;
    }

    float* Cfz = Cf ? Cf + (size_t)z * sC : (float*)0;
    __half* Chz = Ch0 ? Ch0 + (size_t)z * sCp : (__half*)0;
    __half* Clz = Chz ? Chz + loC : (__half*)0;
#pragma unroll
    for (int mt = 0; mt < 2; mt++) {
#pragma unroll
        for (int n8 = 0; n8 < 4; n8++) {
            const float* c = acc[mt][n8];
            const int col = ccol + n8 * 8;
            float b0 = bias ? bias[col]     : 0.0f;
            float b1 = bias ? bias[col + 1] : 0.0f;
#pragma unroll
            for (int h = 0; h < 2; h++) {
                const int row = crow + mt * 16 + h * 8;
                float x0 = c[h * 2 + 0] * alpha + b0;
                float x1 = c[h * 2 + 1] * alpha + b1;
                if (epi == 1) {
                    x0 = 0.5f * x0 * (1.0f + tanhf(GC * (x0 + 0.044715f * x0 * x0 * x0)));
                    x1 = 0.5f * x1 * (1.0f + tanhf(GC * (x1 + 0.044715f * x1 * x1 * x1)));
                }
                if (Cfz)
                    *(float2*)&Cfz[(size_t)row * N + col] = make_float2(x0, x1);
                if (Chz) {
                    __half2 hh, ll;
                    split_pair(x0, x1, hh, ll);
                    *(__half2*)&Chz[(size_t)row * N + col] = hh;
                    *(__half2*)&Clz[(size_t)row * N + col] = ll;
                }
            }
        }
    }
}

static void tg3(const __half* Ah, long long loA, long long sA,
                const __half* Bh, long long loB, long long sB,
                const float* bias, float* Cf, long long sC,
                __half* Ch, __half* Ch2, long long loC, long long sCp,
                int M, int N, int K, int batch, float alpha, int epi,
                cudaStream_t st)
{
    dim3 grid(N / 128, M / 128, batch);
    tgemm3<<<grid, 512, TG_SMEM, st>>>(Ah, Bh, bias, Cf, Ch, Ch2, M, N, K,
                                       loA, loB, loC, sA, sB, sC, sCp, alpha, epi);
}

// ---------------------------------------------------------------------------
// 1-term GEMM (hi planes only)
// ---------------------------------------------------------------------------
#define T1STAGE 20480
#define T1_SMEM (4 * 20480)

__global__ void __launch_bounds__(512)
tgemm1(const __half* __restrict__ Ah0, const __half* __restrict__ Bh0,
       const float* __restrict__ bias, float* __restrict__ Cf,
       __half* __restrict__ Ch0,
       int M, int N, int K, long long loC,
       long long sA, long long sB, long long sC, long long sCp,
       float alpha)
{
    extern __shared__ char smem[];
    const uint32_t sbu = smem_u32(smem);
    const int t = threadIdx.x, w = t >> 5, lane = t & 31;
    const int wm = w & 3, wn = w >> 2;
    const int z = blockIdx.z;
    const int m0 = blockIdx.y * 128, n0 = blockIdx.x * 128;

    const __half* Ap = Ah0 + (size_t)z * sA + (size_t)(m0 + (t >> 2)) * K + (t & 3) * 8;
    const __half* Bp = Bh0 + (size_t)z * sB + (size_t)(n0 + (t >> 2)) * K + (t & 3) * 8;

    float acc[2][4][4];
#pragma unroll
    for (int i = 0; i < 2; i++)
#pragma unroll
        for (int j = 0; j < 4; j++)
#pragma unroll
            for (int e = 0; e < 4; e++) acc[i][j][e] = 0.0f;

    const int nch = K >> 5;
    const uint32_t sdbase = sbu + (uint32_t)((t >> 2) * 80 + (t & 3) * 16);

#define ISSUE1(ch) do {                                                     \
    uint32_t _sd = sdbase + (uint32_t)((ch) & 3) * T1STAGE;                 \
    const int _cb = (ch) * 32;                                              \
    cpasync16(_sd,         Ap + _cb);                                       \
    cpasync16(_sd + PLANE, Bp + _cb);                                       \
    CP_COMMIT();                                                            \
} while (0)

    ISSUE1(0);
    ISSUE1(1);
    if (nch > 2) ISSUE1(2);

    const uint32_t lmoff = (uint32_t)((lane & 15) * 80 + (lane >> 4) * 16);

    for (int ch = 0; ch < nch; ch++) {
        const int rem = nch - 1 - ch;
        if (rem >= 2)      { CP_WAIT(2); }
        else if (rem == 1) { CP_WAIT(1); }
        else               { CP_WAIT(0); }
        __syncthreads();
        if (ch + 3 < nch) ISSUE1(ch + 3);

        const uint32_t sAh = sbu + (uint32_t)(ch & 3) * T1STAGE;
        const uint32_t sBh = sAh + PLANE;
#pragma unroll
        for (int kk = 0; kk < 2; kk++) {
            uint32_t ah[2][4], bh[2][4];
#pragma unroll
            for (int mt = 0; mt < 2; mt++)
                ldsm4(ah[mt], sAh + (uint32_t)((wm * 32 + mt * 16) * 80 + kk * 32) + lmoff);
#pragma unroll
            for (int ng = 0; ng < 2; ng++)
                ldsm4(bh[ng], sBh + (uint32_t)((wn * 32 + ng * 16) * 80 + kk * 32) + lmoff);
#pragma unroll
            for (int ng = 0; ng < 2; ng++)
#pragma unroll
                for (int mt = 0; mt < 2; mt++)
#pragma unroll
                    for (int h2 = 0; h2 < 2; h2++)
                        mma_f16(acc[mt][ng * 2 + h2], ah[mt], bh[ng][h2], bh[ng][h2 + 2]);
        }
    }
#undef ISSUE1

    const int crow = m0 + wm * 32 + (lane >> 2);
    const int ccol = n0 + wn * 32 + (lane & 3) * 2;
    float* Cfz = Cf ? Cf + (size_t)z * sC : (float*)0;
    __half* Chz = Ch0 ? Ch0 + (size_t)z * sCp : (__half*)0;
    __half* Clz = (Chz && loC) ? Chz + loC : (__half*)0;
#pragma unroll
    for (int mt = 0; mt < 2; mt++) {
#pragma unroll
        for (int n8 = 0; n8 < 4; n8++) {
            const float* c = acc[mt][n8];
            const int col = ccol + n8 * 8;
            float b0 = bias ? bias[col]     : 0.0f;
            float b1 = bias ? bias[col + 1] : 0.0f;
#pragma unroll
            for (int h = 0; h < 2; h++) {
                const int row = crow + mt * 16 + h * 8;
                float x0 = c[h * 2 + 0] * alpha + b0;
                float x1 = c[h * 2 + 1] * alpha + b1;
                if (Cfz)
                    *(float2*)&Cfz[(size_t)row * N + col] = make_float2(x0, x1);
                if (Chz) {
                    __half2 hh, ll;
                    split_pair(x0, x1, hh, ll);
                    *(__half2*)&Chz[(size_t)row * N + col] = hh;
                    if (Clz) *(__half2*)&Clz[(size_t)row * N + col] = ll;
                }
            }
        }
    }
}

static void tg1(const __half* Ah, long long sA, const __half* Bh, long long sB,
                const float* bias, float* Cf, long long sC,
                __half* Ch, long long loC, long long sCp,
                int M, int N, int K, int batch, float alpha, cudaStream_t st)
{
    dim3 grid(N / 128, M / 128, batch);
    tgemm1<<<grid, 512, T1_SMEM, st>>>(Ah, Bh, bias, Cf, Ch, M, N, K, loC,
                                       sA, sB, sC, sCp, alpha);
}

// 1-term, N-tile 64
#define B1STAGE 15360
#define T1N_SMEM (4 * 15360)

__global__ void __launch_bounds__(256)
tgemm1n64(const __half* __restrict__ Ah0, const __half* __restrict__ Bh0,
          float* __restrict__ Cf, int M, int N, int K, float alpha)
{
    extern __shared__ char smem[];
    const uint32_t sbu = smem_u32(smem);
    const int t = threadIdx.x, w = t >> 5, lane = t & 31;
    const int wm = w & 3, wn = w >> 2;
    const int m0 = blockIdx.y * 128, n0 = blockIdx.x * 64;

    const int arow = t >> 1, aseg = (t & 1) * 2;
    const int brow = t >> 2, bseg = t & 3;
    const __half* pa = Ah0 + (size_t)(m0 + arow) * K + aseg * 8;
    const __half* pb = Bh0 + (size_t)(n0 + brow) * K + bseg * 8;
    const uint32_t adst = sbu + (uint32_t)(arow * 80 + aseg * 16);
    const uint32_t bdst = sbu + 10240u + (uint32_t)(brow * 80 + bseg * 16);

    float acc[2][4][4];
#pragma unroll
    for (int i = 0; i < 2; i++)
#pragma unroll
        for (int j = 0; j < 4; j++)
#pragma unroll
            for (int e = 0; e < 4; e++) acc[i][j][e] = 0.0f;

    const int nch = K >> 5;

#define ISSUEN(ch) do {                                                     \
    uint32_t _st = (uint32_t)((ch) & 3) * B1STAGE;                          \
    const int _cb = (ch) * 32;                                              \
    cpasync16(adst + _st,      pa + _cb);                                   \
    cpasync16(adst + _st + 16, pa + _cb + 8);                               \
    cpasync16(bdst + _st,      pb + _cb);                                   \
    CP_COMMIT();                                                            \
} while (0)

    ISSUEN(0);
    ISSUEN(1);
    if (nch > 2) ISSUEN(2);

    const uint32_t lmoff = (uint32_t)((lane & 15) * 80 + (lane >> 4) * 16);

    for (int ch = 0; ch < nch; ch++) {
        const int rem = nch - 1 - ch;
        if (rem >= 2)      { CP_WAIT(2); }
        else if (rem == 1) { CP_WAIT(1); }
        else               { CP_WAIT(0); }
        __syncthreads();
        if (ch + 3 < nch) ISSUEN(ch + 3);

        const uint32_t sAh = sbu + (uint32_t)(ch & 3) * B1STAGE;
        const uint32_t sBh = sAh + 10240u;
#pragma unroll
        for (int kk = 0; kk < 2; kk++) {
            uint32_t ah[2][4], bh[2][4];
#pragma unroll
            for (int mt = 0; mt < 2; mt++)
                ldsm4(ah[mt], sAh + (uint32_t)((wm * 32 + mt * 16) * 80 + kk * 32) + lmoff);
#pragma unroll
            for (int ng = 0; ng < 2; ng++)
                ldsm4(bh[ng], sBh + (uint32_t)((wn * 32 + ng * 16) * 80 + kk * 32) + lmoff);
#pragma unroll
            for (int ng = 0; ng < 2; ng++)
#pragma unroll
                for (int mt = 0; mt < 2; mt++)
#pragma unroll
                    for (int h2 = 0; h2 < 2; h2++)
                        mma_f16(acc[mt][ng * 2 + h2], ah[mt], bh[ng][h2], bh[ng][h2 + 2]);
        }
    }
#undef ISSUEN

    const int crow = m0 + wm * 32 + (lane >> 2);
    const int ccol = n0 + wn * 32 + (lane & 3) * 2;
#pragma unroll
    for (int mt = 0; mt < 2; mt++)
#pragma unroll
        for (int n8 = 0; n8 < 4; n8++) {
            const float* c = acc[mt][n8];
            const int col = ccol + n8 * 8;
#pragma unroll
            for (int h = 0; h < 2; h++) {
                const int row = crow + mt * 16 + h * 8;
                *(float2*)&Cf[(size_t)row * N + col] =
                    make_float2(c[h * 2] * alpha, c[h * 2 + 1] * alpha);
            }
        }
}

// ---------------------------------------------------------------------------
__global__ void trans_conv(const float* __restrict__ in, __half* __restrict__ oh,
                           long long loOff, int R, int C,
                           long long sI, long long sO, const int* __restrict__ ids)
{
    __shared__ float tile[32][33];
    const int z = blockIdx.z;
    size_t ib = ids ? (size_t)ids[z] * sI : (size_t)z * sI;
    const float* ip = in + ib;
    __half* ohz = oh + (size_t)z * sO;
    __half* olz = loOff ? ohz + loOff : (__half*)0;
    const int c0 = blockIdx.x * 32, r0 = blockIdx.y * 32;
    const int tx = threadIdx.x, ty = threadIdx.y;
#pragma unroll
    for (int k = 0; k < 32; k += 8)
        tile[ty + k][tx] = ip[(size_t)(r0 + ty + k) * C + c0 + tx];
    __syncthreads();
    const int rr = (tx & 15) * 2, chf = tx >> 4;
#pragma unroll
    for (int k = 0; k < 2; k++) {
        int cc = ty + chf * 8 + k * 16;
        __half2 h, l;
        split_pair(tile[rr][cc], tile[rr + 1][cc], h, l);
        *(__half2*)&ohz[(size_t)(c0 + cc) * R + r0 + rr] = h;
        if (olz) *(__half2*)&olz[(size_t)(c0 + cc) * R + r0 + rr] = l;
    }
}

__global__ void conv_planes(const float* __restrict__ in, __half* __restrict__ oh,
                            long long lo)
{
    size_t idx = (size_t)blockIdx.x * 512 + (size_t)threadIdx.x * 2;
    float2 v = *(const float2*)&in[idx];
    __half2 h, l;
    split_pair(v.x, v.y, h, l);
    *(__half2*)&oh[idx] = h;
    if (lo) *(__half2*)&(oh + lo)[idx] = l;
}

__global__ void rope_table_kernel()
{
    int s = blockIdx.x;
    int i = threadIdx.x;
    float invf = 1.0f / powf(10000.0f, (float)i / 256.0f);
    float angf = (float)s * invf;
    double ang = (double)angf;
    g_sin[s * 256 + i] = (float)sin(ang);
    g_cos[s * 256 + i] = (float)cos(ang);
}

__global__ void bias_prep(const float* __restrict__ pos, float* __restrict__ out, int mode)
{
    int n = blockIdx.x, t = threadIdx.x;
    for (int c = t; c < 1024; c += 256) {
        float p = pos[n * 1024 + c];
        out[n * 1024 + c] = (mode == 1) ? logf(p) : (logf(p) - log1pf(-p));
    }
}

// Softmax 1024 cols (fp16 scores) + bias, emits hi plane only
__global__ void softmax1024_planes(const __half* __restrict__ S, const float* __restrict__ bias,
                                   __half* __restrict__ oh)
{
    const int row = blockIdx.x, t = threadIdx.x;
    const __half* sr = S + (size_t)row * 1024;
    const float* pb = bias + (size_t)(row >> 10) * 1024;
    __half2 a  = *(const __half2*)&sr[2 * t];
    __half2 b2 = *(const __half2*)&sr[512 + 2 * t];
    float2 ba = *(const float2*)&pb[2 * t];
    float2 bb = *(const float2*)&pb[512 + 2 * t];
    float v0 = __low2float(a) + ba.x,  v1 = __high2float(a) + ba.y;
    float v2 = __low2float(b2) + bb.x, v3 = __high2float(b2) + bb.y;

    __shared__ float red[256];
    float mx = fmaxf(fmaxf(v0, v1), fmaxf(v2, v3));
    red[t] = mx; __syncthreads();
    for (int s = 128; s > 0; s >>= 1) { if (t < s) red[t] = fmaxf(red[t], red[t + s]); __syncthreads(); }
    mx = red[0]; __syncthreads();

    float e0 = expf(v0 - mx), e1 = expf(v1 - mx), e2 = expf(v2 - mx), e3 = expf(v3 - mx);
    red[t] = e0 + e1 + e2 + e3; __syncthreads();
    for (int s = 128; s > 0; s >>= 1) { if (t < s) red[t] += red[t + s]; __syncthreads(); }
    float inv = 1.0f / red[0];

    size_t o = (size_t)row * 1024 + 2 * t;
    *(__half2*)&oh[o]       = __floats2half2_rn(e0 * inv, e1 * inv);
    *(__half2*)&oh[o + 512] = __floats2half2_rn(e2 * inv, e3 * inv);
}

__global__ void softmax64_planes(const float* __restrict__ S, __half* __restrict__ oh)
{
    const int row = blockIdx.x * 8 + (threadIdx.x >> 5);
    const int lane = threadIdx.x & 31;
    const float* sr = S + (size_t)row * 64;
    float2 v = *(const float2*)&sr[lane * 2];
    float mx = fmaxf(v.x, v.y);
#pragma unroll
    for (int o = 16; o > 0; o >>= 1)
        mx = fmaxf(mx, __shfl_xor_sync(0xFFFFFFFF, mx, o));
    float e0 = expf(v.x - mx), e1 = expf(v.y - mx);
    float s = e0 + e1;
#pragma unroll
    for (int o = 16; o > 0; o >>= 1)
        s += __shfl_xor_sync(0xFFFFFFFF, s, o);
    float inv = 1.0f / s;
    *(__half2*)&oh[(size_t)row * 64 + lane * 2] = __floats2half2_rn(e0 * inv, e1 * inv);
}

__global__ void softmax_f32(float* __restrict__ S, const float* __restrict__ bias,
                            int cols, int rpb)
{
    int row = blockIdx.x;
    float* sr = S + (size_t)row * cols;
    const float* pb = bias + (size_t)(row / rpb) * cols;
    int t = threadIdx.x;
    __shared__ float red[256];

    float mx = -1e30f;
    for (int c = t; c < cols; c += 256) {
        float v = sr[c] + pb[c];
        sr[c] = v;
        mx = fmaxf(mx, v);
    }
    red[t] = mx; __syncthreads();
    for (int s = 128; s > 0; s >>= 1) { if (t < s) red[t] = fmaxf(red[t], red[t + s]); __syncthreads(); }
    mx = red[0]; __syncthreads();

    float sum = 0.0f;
    for (int c = t; c < cols; c += 256) {
        float e = expf(sr[c] - mx);
        sr[c] = e;
        sum += e;
    }
    red[t] = sum; __syncthreads();
    for (int s = 128; s > 0; s >>= 1) { if (t < s) red[t] += red[t + s]; __syncthreads(); }
    float inv = 1.0f / red[0];
    for (int c = t; c < cols; c += 256) sr[c] *= inv;
}

__global__ void ln_kernel(const float* __restrict__ Xin, const float* __restrict__ R,
                          const float* __restrict__ g, const float* __restrict__ b,
                          float* __restrict__ Xout,
                          __half* __restrict__ oh, long long lo)
{
    int row = blockIdx.x;
    int t   = threadIdx.x;
    const float* xr = Xin + (size_t)row * DD;
    const float* rr = R + (size_t)row * DD;

    float v0 = xr[2 * t] + rr[2 * t];
    float v1 = xr[2 * t + 1] + rr[2 * t + 1];

    __shared__ float red[256];
    red[t] = v0 + v1; __syncthreads();
    for (int s = 128; s > 0; s >>= 1) { if (t < s) red[t] += red[t + s]; __syncthreads(); }
    float m = red[0] * (1.0f / 512.0f);
    __syncthreads();

    float d0 = v0 - m, d1 = v1 - m;
    red[t] = d0 * d0 + d1 * d1; __syncthreads();
    for (int s = 128; s > 0; s >>= 1) { if (t < s) red[t] += red[t + s]; __syncthreads(); }
    float var = red[0] * (1.0f / 512.0f);
    float inv = rsqrtf(var + 1e-5f);

    float o0 = d0 * inv * g[2 * t]     + b[2 * t];
    float o1 = d1 * inv * g[2 * t + 1] + b[2 * t + 1];
    float* xo = Xout + (size_t)row * DD;
    xo[2 * t]     = o0;
    xo[2 * t + 1] = o1;

    __half2 h, l;
    split_pair(o0, o1, h, l);
    size_t o = (size_t)row * DD + 2 * t;
    *(__half2*)&oh[o] = h;
    *(__half2*)&(oh + lo)[o] = l;
}

__global__ void vgate_kernel(const float* __restrict__ F, const float* __restrict__ raw,
                             const float* __restrict__ Wig, const float* __restrict__ big,
                             float* __restrict__ V)
{
    int row = blockIdx.x;
    int t   = threadIdx.x;
    const float* fr = F + (size_t)row * DD;
    __shared__ float red[256];
    float s = fr[t] * Wig[t] + fr[t + 256] * Wig[t + 256];
    red[t] = s; __syncthreads();
    for (int k = 128; k > 0; k >>= 1) { if (t < k) red[t] += red[t + k]; __syncthreads(); }
    float gte = 1.0f / (1.0f + expf(-(red[0] + big[0])));
    const float* rr = raw + (size_t)row * DD;
    float* vr = V + (size_t)row * DD;
    vr[t]       = rr[t]       * gte;
    vr[t + 256] = rr[t + 256] * gte;
}

__global__ void out_kernel(const float* __restrict__ FU, const float* __restrict__ A2,
                           const float* __restrict__ PD,
                           const float* __restrict__ Wu1, const float* __restrict__ bu1,
                           const float* __restrict__ Wu2, const float* __restrict__ bu2,
                           const float* __restrict__ b1,
                           float* __restrict__ out, float* __restrict__ gate)
{
    int row = blockIdx.x;
    int t   = threadIdx.x;
    const float* fu = FU + (size_t)row * DD;
    const float* a2 = A2 + (size_t)row * DD;
    const float* pd = PD + (size_t)row * DD;

    __shared__ float red[256];
    float s = fu[t] * Wu1[t] + fu[t + 256] * Wu1[t + 256]
            + a2[t] * Wu2[t] + a2[t + 256] * Wu2[t + 256];
    red[t] = s; __syncthreads();
    for (int k = 128; k > 0; k >>= 1) { if (t < k) red[t] += red[t + k]; __syncthreads(); }
    float z = red[0] + bu1[0] + bu2[0] + b1[0] - 4.0f;
    float g = 1.0f / (1.0f + expf(-z));

    float* orow = out + (size_t)row * DD;
    orow[t]       = pd[t]       * (1.0f - g) + a2[t]       * g;
    orow[t + 256] = pd[t + 256] * (1.0f - g) + a2[t + 256] * g;
    if (t == 0) gate[row] = g;
}

#define BM 64
#define BN 64
#define BK 16

__global__ void gemm_kernel(const float* __restrict__ A,
                            const float* __restrict__ Bm,
                            const float* __restrict__ bias,
                            float* __restrict__ C,
                            int M, int N, int K,
                            long long sA, long long sB, long long sC,
                            float alpha, int transB, int epi)
{
    const int bz = blockIdx.z;
    A  += (size_t)bz * sA;
    Bm += (size_t)bz * sB;
    C  += (size_t)bz * sC;

    const int m0 = blockIdx.y * BM;
    const int n0 = blockIdx.x * BN;

    __shared__ float As[BK][BM + 4];
    __shared__ float Bs[BK][BN + 4];

    const int t  = threadIdx.x;
    const int tx = t & 15;
    const int ty = t >> 4;

    float acc[4][4] = {};

    const int arow = t >> 2;
    const int akc  = (t & 3) * 4;
    const int kb   = t >> 4;
    const int nb   = (t & 15) * 4;

    for (int k0 = 0; k0 < K; k0 += BK) {
        float4 av = *(const float4*)&A[(size_t)(m0 + arow) * K + k0 + akc];
        As[akc + 0][arow] = av.x;
        As[akc + 1][arow] = av.y;
        As[akc + 2][arow] = av.z;
        As[akc + 3][arow] = av.w;

        if (!transB) {
            float4 bv = *(const float4*)&Bm[(size_t)(k0 + kb) * N + n0 + nb];
            *(float4*)&Bs[kb][nb] = bv;
        } else {
            float4 bv = *(const float4*)&Bm[(size_t)(n0 + arow) * K + k0 + akc];
            Bs[akc + 0][arow] = bv.x;
            Bs[akc + 1][arow] = bv.y;
            Bs[akc + 2][arow] = bv.z;
            Bs[akc + 3][arow] = bv.w;
        }
        __syncthreads();

#pragma unroll
        for (int k = 0; k < BK; k++) {
            float4 a = *(const float4*)&As[k][ty * 4];
            float4 b = *(const float4*)&Bs[k][tx * 4];
            acc[0][0] += a.x * b.x; acc[0][1] += a.x * b.y;
            acc[0][2] += a.x * b.z; acc[0][3] += a.x * b.w;
            acc[1][0] += a.y * b.x; acc[1][1] += a.y * b.y;
            acc[1][2] += a.y * b.z; acc[1][3] += a.y * b.w;
            acc[2][0] += a.z * b.x; acc[2][1] += a.z * b.y;
            acc[2][2] += a.z * b.z; acc[2][3] += a.z * b.w;
            acc[3][0] += a.w * b.x; acc[3][1] += a.w * b.y;
            acc[3][2] += a.w * b.z; acc[3][3] += a.w * b.w;
        }
        __syncthreads();
    }

#pragma unroll
    for (int i = 0; i < 4; i++) {
        const int row = m0 + ty * 4 + i;
        float v[4];
#pragma unroll
        for (int j = 0; j < 4; j++) {
            float x = acc[i][j] * alpha;
            if (bias) x += bias[n0 + tx * 4 + j];
            v[j] = x;
        }
        *(float4*)&C[(size_t)row * N + n0 + tx * 4] = make_float4(v[0], v[1], v[2], v[3]);
    }
}

static void sgemm_launch(const float* A, const float* B, const float* bias, float* C,
                         int M, int N, int K, int batch,
                         long long sA, long long sB, long long sC,
                         float alpha, int transB, cudaStream_t st)
{
    dim3 grid(N / BN, M / BM, batch);
    gemm_kernel<<<grid, 256, 0, st>>>(A, B, bias, C, M, N, K, sA, sB, sC, alpha, transB, 0);
}

// ---------------------------------------------------------------------------
// Encoder (stream + private buffers). lo = plane lo-offset for this side.
// ---------------------------------------------------------------------------
static void run_encoder(const float* Xin0, float* X, int nb,
                        const __half* initP, long long initLo,
                        const float* biasRows, const __half* PW,
                        const float* bqkv, const float* bo,
                        const float* ln, const float* bff,
                        float* bV, float* bK, __half* Sh,
                        __half* Pq, __half* Pk, __half* Pvt,
                        __half* Pp, __half* Pbq, __half* Ph,
                        __half* Px, long long lo, cudaStream_t st)
{
    const int rows = nb * SS;
    const float sc = 1.0f / sqrtf((float)DD);
    for (int l = 0; l < 2; l++) {
        const __half* AP = (l == 0) ? initP : Px;
        const long long loAP = (l == 0) ? initLo : lo;
        tg3(AP, loAP, 0, PW + (size_t)(l * 3) * 262144, WLO, 0,
            bqkv + (size_t)l * 1536, bV, 0, Pq, Pk, 0, 0,
            rows, 1536, 512, 1, 1.0f, 2, st);
        trans_conv<<<dim3(16, 32, nb), dim3(32, 8), 0, st>>>(bV, Pvt, 0, 1024, 512,
                                                             524288, 524288, nullptr);
        // scores = Q @ K^T * sc -> fp16 raw
        tg1(Pq, 524288, Pk, 524288, nullptr, nullptr, 0, Sh, 0, 1048576,
            1024, 1024, 512, nb, sc, st);
        softmax1024_planes<<<rows, 256, 0, st>>>(Sh, biasRows, Pp);
        // T = A @ V (1-term) -> hi+lo planes
        tg1(Pp, 1048576, Pvt, 524288, nullptr, nullptr, 0, Pbq, lo, 524288,
            1024, 512, 1024, nb, 1.0f, st);
        // O = T @ Wo + bo (3-term)
        tg3(Pbq, lo, 0, PW + (size_t)(6 + l) * 262144, WLO, 0, bo + l * 512,
            bK, 0, nullptr, nullptr, 0, 0, rows, 512, 512, 1, 1.0f, 0, st);
        ln_kernel<<<rows, 256, 0, st>>>((l == 0) ? Xin0 : X, bK,
                                        ln + l * 2048, ln + l * 2048 + 512, X, Px, lo);
        tg3(Px, lo, 0, PW + (size_t)(8 + 2 * l) * 262144, WLO, 0, bff + l * 1024,
            nullptr, 0, Ph, nullptr, lo, 0, rows, 512, 512, 1, 1.0f, 1, st);
        tg3(Ph, lo, 0, PW + (size_t)(9 + 2 * l) * 262144, WLO, 0, bff + l * 1024 + 512,
            bK, 0, nullptr, nullptr, 0, 0, rows, 512, 512, 1, 1.0f, 0, st);
        ln_kernel<<<rows, 256, 0, st>>>(X, bK, ln + l * 2048 + 1024, ln + l * 2048 + 1536,
                                        X, Px, lo);
    }
}

extern "C" void kernel_launch(void* const* d_in, const int* in_sizes, int n_in,
                              void* d_out, int out_size)
{
    const float* raw_emb   = (const float*)d_in[0];
    const float* pos_w     = (const float*)d_in[1];
    const float* post_dec  = (const float*)d_in[2];
    const float* pos_r     = (const float*)d_in[3];
    const float* questions = (const float*)d_in[4];
    const float* W_k       = (const float*)d_in[5];
    const float* W_ig      = (const float*)d_in[6];
    const float* b_ig      = (const float*)d_in[7];
    const float* W_u1      = (const float*)d_in[8];
    const float* b_u1      = (const float*)d_in[9];
    const float* W_u2      = (const float*)d_in[10];
    const float* b_u2      = (const float*)d_in[11];
    const float* b1        = (const float*)d_in[12];
    const float* W_ok      = (const float*)d_in[13];
    const float* b_ok      = (const float*)d_in[14];
    const float* encw_Wqkv = (const float*)d_in[15];
    const float* encw_bqkv = (const float*)d_in[16];
    const float* encw_Wo   = (const float*)d_in[17];
    const float* encw_bo   = (const float*)d_in[18];
    const float* encw_ln   = (const float*)d_in[19];
    const float* encw_Wff  = (const float*)d_in[20];
    const float* encw_bff  = (const float*)d_in[21];
    const float* encr_Wqkv = (const float*)d_in[22];
    const float* encr_bqkv = (const float*)d_in[23];
    const float* encr_Wo   = (const float*)d_in[24];
    const float* encr_bo   = (const float*)d_in[25];
    const float* encr_ln   = (const float*)d_in[26];
    const float* encr_Wff  = (const float*)d_in[27];
    const float* encr_bff  = (const float*)d_in[28];
    const int*   lookup    = (const int*)d_in[29];

    float* out  = (float*)d_out;
    float* gate = out + (size_t)NBB * SS * DD;

    float *pX, *pV, *pK, *pXw, *pVw, *pKw, *pS1, *pKd, *pVd, *pA1, *pA2s, *pA2, *pBW, *pBR;
    __half *pPW, *pPraw, *pPpd, *pPx, *pPq, *pPk, *pPvt, *pPp, *pPbq, *pPh, *pSh;
    __half *pPxw, *pPqw, *pPkw, *pPvtw, *pPpw, *pPbqw, *pPhw, *pShw;
    __half *pPk2, *pPa2, *pPsel, *pPqst;
    cudaGetSymbolAddress((void**)&pX,    g_X);
    cudaGetSymbolAddress((void**)&pV,    g_V);
    cudaGetSymbolAddress((void**)&pK,    g_Kb);
    cudaGetSymbolAddress((void**)&pXw,   g_Xw);
    cudaGetSymbolAddress((void**)&pVw,   g_Vw);
    cudaGetSymbolAddress((void**)&pKw,   g_Kw);
    cudaGetSymbolAddress((void**)&pS1,   g_S1);
    cudaGetSymbolAddress((void**)&pKd,   g_Kdoc);
    cudaGetSymbolAddress((void**)&pVd,   g_Vdoc);
    cudaGetSymbolAddress((void**)&pA1,   g_A1S);
    cudaGetSymbolAddress((void**)&pA2s,  g_A2SC);
    cudaGetSymbolAddress((void**)&pA2,   g_A2);
    cudaGetSymbolAddress((void**)&pBW,   g_BIASW);
    cudaGetSymbolAddress((void**)&pBR,   g_BIASR);
    cudaGetSymbolAddress((void**)&pPW,   g_PW);
    cudaGetSymbolAddress((void**)&pPraw, g_Praw);
    cudaGetSymbolAddress((void**)&pPpd,  g_Ppd);
    cudaGetSymbolAddress((void**)&pPx,   g_Px);
    cudaGetSymbolAddress((void**)&pPq,   g_Pq);
    cudaGetSymbolAddress((void**)&pPk,   g_Pk);
    cudaGetSymbolAddress((void**)&pPvt,  g_Pvt);
    cudaGetSymbolAddress((void**)&pPp,   g_Pp);
    cudaGetSymbolAddress((void**)&pPbq,  g_Pbq);
    cudaGetSymbolAddress((void**)&pPh,   g_Ph);
    cudaGetSymbolAddress((void**)&pSh,   g_Sh);
    cudaGetSymbolAddress((void**)&pPxw,  g_Pxw);
    cudaGetSymbolAddress((void**)&pPqw,  g_Pqw);
    cudaGetSymbolAddress((void**)&pPkw,  g_Pkw);
    cudaGetSymbolAddress((void**)&pPvtw, g_Pvtw);
    cudaGetSymbolAddress((void**)&pPpw,  g_Ppw);
    cudaGetSymbolAddress((void**)&pPbqw, g_Pbqw);
    cudaGetSymbolAddress((void**)&pPhw,  g_Phw);
    cudaGetSymbolAddress((void**)&pShw,  g_Shw);
    cudaGetSymbolAddress((void**)&pPk2,  g_Pk2);
    cudaGetSymbolAddress((void**)&pPa2,  g_Pa2);
    cudaGetSymbolAddress((void**)&pPsel, g_Psel);
    cudaGetSymbolAddress((void**)&pPqst, g_Pqst);

    cudaFuncSetAttribute(tgemm3,    cudaFuncAttributeMaxDynamicSharedMemorySize, TG_SMEM);
    cudaFuncSetAttribute(tgemm1,    cudaFuncAttributeMaxDynamicSharedMemorySize, T1_SMEM);
    cudaFuncSetAttribute(tgemm1n64, cudaFuncAttributeMaxDynamicSharedMemorySize, T1N_SMEM);

    const float scD = 1.0f / sqrtf((float)DD);

    // fork infrastructure (leaked intentionally: destroying a capture-
    // participating stream before EndCapture would invalidate the capture)
    cudaStream_t s2;
    cudaStreamCreateWithFlags(&s2, cudaStreamNonBlocking);
    cudaEvent_t evF, evJ;
    cudaEventCreateWithFlags(&evF, cudaEventDisableTiming);
    cudaEventCreateWithFlags(&evJ, cudaEventDisableTiming);
    cudaStream_t s0 = 0;

    // ---- common prep on s0 (needed by both sides) ----
    rope_table_kernel<<<1024, 256, 0, s0>>>();
    conv_planes<<<NBB * SS, 256, 0, s0>>>(post_dec, pPpd, 8388608LL);

    cudaEventRecord(evF, s0);
    cudaStreamWaitEvent(s2, evF, 0);

    // ================= s2: write side + independent k2/a2 path =============
    trans_conv<<<dim3(16, 16, 6), dim3(32, 8), 0, s2>>>(encw_Wqkv, pPW + 0LL * 262144, WLO, 512, 512, 262144, 262144, nullptr);
    trans_conv<<<dim3(16, 16, 2), dim3(32, 8), 0, s2>>>(encw_Wo,   pPW + 6LL * 262144, WLO, 512, 512, 262144, 262144, nullptr);
    trans_conv<<<dim3(16, 16, 4), dim3(32, 8), 0, s2>>>(encw_Wff,  pPW + 8LL * 262144, WLO, 512, 512, 262144, 262144, nullptr);
    conv_planes<<<NDOC * SS, 256, 0, s2>>>(raw_emb, pPraw, 4194304LL);
    bias_prep<<<NDOC, 256, 0, s2>>>(pos_w, pBW, 1);

    run_encoder(raw_emb, pXw, NDOC, pPraw, 4194304LL, pBW,
                pPW, encw_bqkv, encw_bo, encw_ln, encw_bff,
                pVw, pKw, pShw, pPqw, pPkw, pPvtw, pPpw, pPbqw, pPhw, pPxw,
                LOW, s2);

    vgate_kernel<<<NDOC * SS, 256, 0, s2>>>(pXw, raw_emb, W_ig, b_ig, pVd);
    trans_conv<<<dim3(16, 16, 1), dim3(32, 8), 0, s2>>>(W_k, pPW + 24LL * 262144, WLO, 512, 512, 262144, 262144, nullptr);
    tg3(pPraw, 4194304LL, 0, pPW + 24LL * 262144, WLO, 0, nullptr, pKd, 0,
        nullptr, nullptr, 0, 0, NDOC * SS, 512, 512, 1, 1.0f, 0, s2);
    sgemm_launch(questions, pKd, nullptr, pS1, QQ, SS, DD, NDOC, 0, 524288, 65536, scD, 1, s2);
    softmax_f32<<<NDOC * QQ, 256, 0, s2>>>(pS1, pBW, SS, QQ);
    sgemm_launch(pS1, pVd, nullptr, pA1, QQ, DD, SS, NDOC, 65536, 524288, 32768, 1.0f, 0, s2);
    trans_conv<<<dim3(16, 2, 16), dim3(32, 8), 0, s2>>>(pA1, pPsel, 0, 64, 512, 32768, 32768, lookup);

    // independent k2/a2/A2 chain (uses pPpd from pre-fork prep)
    trans_conv<<<dim3(16, 16, 1), dim3(32, 8), 0, s2>>>(W_ok, pPW + 25LL * 262144, WLO, 512, 512, 262144, 262144, nullptr);
    conv_planes<<<QQ, 256, 0, s2>>>(questions, pPqst, 0);
    tg1(pPpd, 0, pPW + 25LL * 262144, 0, b_ok, nullptr, 0, pPk2, 0, 0,
        NBB * SS, 512, 512, 1, 1.0f, s2);
    {
        dim3 grid(1, (NBB * SS) / 128, 1);
        tgemm1n64<<<grid, 256, T1N_SMEM, s2>>>(pPk2, pPqst, pA2s, NBB * SS, QQ, DD, 0.125f);
    }
    softmax64_planes<<<NBB * SS / 8, 256, 0, s2>>>(pA2s, pPa2);
    tg1(pPa2, 65536, pPsel, 32768, nullptr, pA2, 524288, nullptr, 0, 0,
        1024, 512, 64, NBB, 1.0f, s2);

    cudaEventRecord(evJ, s2);

    // ================= s0: read-side encoder (long pole) ====================
    trans_conv<<<dim3(16, 16, 6), dim3(32, 8), 0, s0>>>(encr_Wqkv, pPW + 12LL * 262144, WLO, 512, 512, 262144, 262144, nullptr);
    trans_conv<<<dim3(16, 16, 2), dim3(32, 8), 0, s0>>>(encr_Wo,   pPW + 18LL * 262144, WLO, 512, 512, 262144, 262144, nullptr);
    trans_conv<<<dim3(16, 16, 4), dim3(32, 8), 0, s0>>>(encr_Wff,  pPW + 20LL * 262144, WLO, 512, 512, 262144, 262144, nullptr);
    bias_prep<<<NBB, 256, 0, s0>>>(pos_r, pBR, 2);

    run_encoder(post_dec, pX, NBB, pPpd, 8388608LL, pBR,
                pPW + 12LL * 262144, encr_bqkv, encr_bo, encr_ln, encr_bff,
                pV, pK, pSh, pPq, pPk, pPvt, pPp, pPbq, pPh, pPx,
                LO, s0);

    // join + final
    cudaStreamWaitEvent(s0, evJ, 0);
    out_kernel<<<NBB * SS, 256, 0, s0>>>(pX, pA2, post_dec,
                                         W_u1, b_u1, W_u2, b_u2, b1,
                                         out, gate);

    (void)in_sizes; (void)n_in; (void)out_size;
}

// round 11
// speedup vs baseline: 3.8800x; 1.2584x over previous
#include <cuda_runtime.h>
#include <cuda_fp16.h>
#include <math.h>
#include <stdint.h>

#define DD     512
#define SS     1024
#define NBB    16
#define QQ     64
#define NDOC   8

// ---- read-side f32 scratch ----
__device__ float g_X   [16384 * 512];
__device__ float g_V   [16384 * 512];
__device__ float g_Kb  [16384 * 512];
// ---- write-side f32 scratch ----
__device__ float g_Xw  [8192 * 512];
__device__ float g_Vw  [8192 * 512];
__device__ float g_Kw  [8192 * 512];
__device__ float g_S1  [8 * 64 * 1024];
__device__ float g_Kdoc[8192 * 512];
__device__ float g_Vdoc[8192 * 512];
__device__ float g_A1S [8 * 64 * 512];
__device__ float g_A2SC[16384 * 64];
__device__ float g_A2  [16384 * 512];
__device__ float g_sin [1024 * 256];
__device__ float g_cos [1024 * 256];
__device__ float g_BIASW[8 * 1024];
__device__ float g_BIASR[16 * 1024];

#define WLO 6815744LL
#define LO  8388608LL
#define LOW 4194304LL
__device__ __align__(16) __half g_PW  [2 * 26 * 262144];
__device__ __align__(16) __half g_Praw[4194304];
__device__ __align__(16) __half g_Ppd [8388608];
// read-side planes
__device__ __align__(16) __half g_Px  [2 * 8388608];
__device__ __align__(16) __half g_Pq  [8388608];
__device__ __align__(16) __half g_Pk  [8388608];
__device__ __align__(16) __half g_Pvt [8388608];
__device__ __align__(16) __half g_Pp  [16777216];
__device__ __align__(16) __half g_Pbq [2 * 8388608];
__device__ __align__(16) __half g_Ph  [2 * 8388608];
__device__ __align__(16) __half g_Sh  [16 * 1048576];
// write-side planes
__device__ __align__(16) __half g_Pxw [2 * 4194304];
__device__ __align__(16) __half g_Pqw [4194304];
__device__ __align__(16) __half g_Pkw [4194304];
__device__ __align__(16) __half g_Pvtw[4194304];
__device__ __align__(16) __half g_Ppw [8388608];
__device__ __align__(16) __half g_Pbqw[2 * 4194304];
__device__ __align__(16) __half g_Phw [2 * 4194304];
__device__ __align__(16) __half g_Shw [8 * 1048576];
// misc planes
__device__ __align__(16) __half g_Pk2 [8388608];
__device__ __align__(16) __half g_Pa2 [1048576];
__device__ __align__(16) __half g_Psel[524288];
__device__ __align__(16) __half g_Pqst[32768];

__device__ __forceinline__ uint32_t smem_u32(const void* p) {
    uint32_t a;
    asm("{ .reg .u64 t; cvta.to.shared.u64 t, %1; cvt.u32.u64 %0, t; }"
        : "=r"(a) : "l"(p));
    return a;
}

__device__ __forceinline__ void ldsm4(uint32_t* r, uint32_t addr) {
    asm volatile("ldmatrix.sync.aligned.m8n8.x4.shared.b16 {%0,%1,%2,%3}, [%4];"
                 : "=r"(r[0]), "=r"(r[1]), "=r"(r[2]), "=r"(r[3]) : "r"(addr));
}

__device__ __forceinline__ void mma_f16(float* c, const uint32_t* a,
                                        uint32_t b0, uint32_t b1) {
    asm volatile(
        "mma.sync.aligned.m16n8k16.row.col.f32.f16.f16.f32 "
        "{%0,%1,%2,%3}, {%4,%5,%6,%7}, {%8,%9}, {%0,%1,%2,%3};"
        : "+f"(c[0]), "+f"(c[1]), "+f"(c[2]), "+f"(c[3])
        : "r"(a[0]), "r"(a[1]), "r"(a[2]), "r"(a[3]), "r"(b0), "r"(b1));
}

__device__ __forceinline__ void cpasync16(uint32_t dst, const void* src) {
    asm volatile("cp.async.cg.shared.global [%0], [%1], 16;" :: "r"(dst), "l"(src));
}
#define CP_COMMIT() asm volatile("cp.async.commit_group;" ::: "memory")
#define CP_WAIT(n)  asm volatile("cp.async.wait_group %0;" :: "n"(n) : "memory")

__device__ __forceinline__ void split_pair(float x0, float x1,
                                           __half2& h, __half2& l) {
    h = __floats2half2_rn(x0, x1);
    l = __floats2half2_rn(x0 - __low2float(h), x1 - __high2float(h));
}

// ---------------------------------------------------------------------------
// 3-term split GEMM (fp16 planes): residual-path GEMMs (Wo, FF)
// epi: 0=none, 1=gelu
// ---------------------------------------------------------------------------
#define PLANE  10240
#define TSTAGE 40960
#define TG_SMEM (4 * 40960)

__global__ void __launch_bounds__(512)
tgemm3(const __half* __restrict__ Ah0, const __half* __restrict__ Bh0,
       const float* __restrict__ bias, float* __restrict__ Cf,
       __half* __restrict__ Ch0,
       int M, int N, int K,
       long long loA, long long loB, long long loC,
       long long sA, long long sB, long long sC, long long sCp,
       float alpha, int epi)
{
    extern __shared__ char smem[];
    const uint32_t sbu = smem_u32(smem);
    const int t = threadIdx.x, w = t >> 5, lane = t & 31;
    const int wm = w & 3, wn = w >> 2;
    const int z = blockIdx.z;
    const int m0 = blockIdx.y * 128, n0 = blockIdx.x * 128;

    const __half* Ah = Ah0 + (size_t)z * sA;
    const __half* Bh = Bh0 + (size_t)z * sB;

    const int lrow = t >> 2, seg = t & 3;
    const __half* pr[4];
    pr[0] = Ah + (size_t)(m0 + lrow) * K + seg * 8;
    pr[1] = pr[0] + loA;
    pr[2] = Bh + (size_t)(n0 + lrow) * K + seg * 8;
    pr[3] = pr[2] + loB;

    float acc[2][4][4];
#pragma unroll
    for (int i = 0; i < 2; i++)
#pragma unroll
        for (int j = 0; j < 4; j++)
#pragma unroll
            for (int e = 0; e < 4; e++) acc[i][j][e] = 0.0f;

    const int nch = K >> 5;
    const uint32_t sdbase = sbu + (uint32_t)(lrow * 80 + seg * 16);

#define ISSUE(ch) do {                                                      \
    uint32_t _sd = sdbase + (uint32_t)((ch) & 3) * TSTAGE;                  \
    const int _cb = (ch) * 32;                                              \
    _Pragma("unroll")                                                       \
    for (int _p = 0; _p < 4; _p++)                                          \
        cpasync16(_sd + _p * PLANE, pr[_p] + _cb);                          \
    CP_COMMIT();                                                            \
} while (0)

    ISSUE(0);
    ISSUE(1);
    if (nch > 2) ISSUE(2);

    const uint32_t lmoff = (uint32_t)((lane & 15) * 80 + (lane >> 4) * 16);

    for (int ch = 0; ch < nch; ch++) {
        const int rem = nch - 1 - ch;
        if (rem >= 2)      { CP_WAIT(2); }
        else if (rem == 1) { CP_WAIT(1); }
        else               { CP_WAIT(0); }
        __syncthreads();
        if (ch + 3 < nch) ISSUE(ch + 3);

        const uint32_t sAh = sbu + (uint32_t)(ch & 3) * TSTAGE;
        const uint32_t sBh = sAh + 2 * PLANE;
#pragma unroll
        for (int kk = 0; kk < 2; kk++) {
            uint32_t ah[2][4], al[2][4], bh[2][4], bl[2][4];
#pragma unroll
            for (int mt = 0; mt < 2; mt++) {
                uint32_t aaddr = sAh + (uint32_t)((wm * 32 + mt * 16) * 80 + kk * 32) + lmoff;
                ldsm4(ah[mt], aaddr);
                ldsm4(al[mt], aaddr + PLANE);
            }
#pragma unroll
            for (int ng = 0; ng < 2; ng++) {
                uint32_t baddr = sBh + (uint32_t)((wn * 32 + ng * 16) * 80 + kk * 32) + lmoff;
                ldsm4(bh[ng], baddr);
                ldsm4(bl[ng], baddr + PLANE);
            }
#pragma unroll
            for (int ng = 0; ng < 2; ng++)
#pragma unroll
                for (int mt = 0; mt < 2; mt++)
#pragma unroll
                    for (int h2 = 0; h2 < 2; h2++)
                        mma_f16(acc[mt][ng * 2 + h2], ah[mt], bh[ng][h2], bh[ng][h2 + 2]);
#pragma unroll
            for (int ng = 0; ng < 2; ng++)
#pragma unroll
                for (int mt = 0; mt < 2; mt++)
#pragma unroll
                    for (int h2 = 0; h2 < 2; h2++)
                        mma_f16(acc[mt][ng * 2 + h2], ah[mt], bl[ng][h2], bl[ng][h2 + 2]);
#pragma unroll
            for (int ng = 0; ng < 2; ng++)
#pragma unroll
                for (int mt = 0; mt < 2; mt++)
#pragma unroll
                    for (int h2 = 0; h2 < 2; h2++)
                        mma_f16(acc[mt][ng * 2 + h2], al[mt], bh[ng][h2], bh[ng][h2 + 2]);
        }
    }
#undef ISSUE

    const float GC = 0.7978845608028654f;
    const int crow = m0 + wm * 32 + (lane >> 2);
    const int ccol = n0 + wn * 32 + (lane & 3) * 2;

    float* Cfz = Cf ? Cf + (size_t)z * sC : (float*)0;
    __half* Chz = Ch0 ? Ch0 + (size_t)z * sCp : (__half*)0;
    __half* Clz = Chz ? Chz + loC : (__half*)0;
#pragma unroll
    for (int mt = 0; mt < 2; mt++) {
#pragma unroll
        for (int n8 = 0; n8 < 4; n8++) {
            const float* c = acc[mt][n8];
            const int col = ccol + n8 * 8;
            float b0 = bias ? bias[col]     : 0.0f;
            float b1 = bias ? bias[col + 1] : 0.0f;
#pragma unroll
            for (int h = 0; h < 2; h++) {
                const int row = crow + mt * 16 + h * 8;
                float x0 = c[h * 2 + 0] * alpha + b0;
                float x1 = c[h * 2 + 1] * alpha + b1;
                if (epi == 1) {
                    x0 = 0.5f * x0 * (1.0f + tanhf(GC * (x0 + 0.044715f * x0 * x0 * x0)));
                    x1 = 0.5f * x1 * (1.0f + tanhf(GC * (x1 + 0.044715f * x1 * x1 * x1)));
                }
                if (Cfz)
                    *(float2*)&Cfz[(size_t)row * N + col] = make_float2(x0, x1);
                if (Chz) {
                    __half2 hh, ll;
                    split_pair(x0, x1, hh, ll);
                    *(__half2*)&Chz[(size_t)row * N + col] = hh;
                    *(__half2*)&Clz[(size_t)row * N + col] = ll;
                }
            }
        }
    }
}

static void tg3(const __half* Ah, long long loA, long long sA,
                const __half* Bh, long long loB, long long sB,
                const float* bias, float* Cf, long long sC,
                __half* Ch, long long loC, long long sCp,
                int M, int N, int K, int batch, float alpha, int epi,
                cudaStream_t st)
{
    dim3 grid(N / 128, M / 128, batch);
    tgemm3<<<grid, 512, TG_SMEM, st>>>(Ah, Bh, bias, Cf, Ch, M, N, K,
                                       loA, loB, loC, sA, sB, sC, sCp, alpha, epi);
}

// ---------------------------------------------------------------------------
// 1-term GEMM (hi planes only). epi: 0 = plain (Cf f32 / Ch planes),
// 2 = QKV epilogue (cols<1024 rope -> Ch0/Ch2 hi planes, cols>=1024 -> Cf f32)
// ---------------------------------------------------------------------------
#define T1STAGE 20480
#define T1_SMEM (4 * 20480)

__global__ void __launch_bounds__(512)
tgemm1(const __half* __restrict__ Ah0, const __half* __restrict__ Bh0,
       const float* __restrict__ bias, float* __restrict__ Cf,
       __half* __restrict__ Ch0, __half* __restrict__ Ch2,
       int M, int N, int K, long long loC,
       long long sA, long long sB, long long sC, long long sCp,
       float alpha, int epi)
{
    extern __shared__ char smem[];
    const uint32_t sbu = smem_u32(smem);
    const int t = threadIdx.x, w = t >> 5, lane = t & 31;
    const int wm = w & 3, wn = w >> 2;
    const int z = blockIdx.z;
    const int m0 = blockIdx.y * 128, n0 = blockIdx.x * 128;

    const __half* Ap = Ah0 + (size_t)z * sA + (size_t)(m0 + (t >> 2)) * K + (t & 3) * 8;
    const __half* Bp = Bh0 + (size_t)z * sB + (size_t)(n0 + (t >> 2)) * K + (t & 3) * 8;

    float acc[2][4][4];
#pragma unroll
    for (int i = 0; i < 2; i++)
#pragma unroll
        for (int j = 0; j < 4; j++)
#pragma unroll
            for (int e = 0; e < 4; e++) acc[i][j][e] = 0.0f;

    const int nch = K >> 5;
    const uint32_t sdbase = sbu + (uint32_t)((t >> 2) * 80 + (t & 3) * 16);

#define ISSUE1(ch) do {                                                     \
    uint32_t _sd = sdbase + (uint32_t)((ch) & 3) * T1STAGE;                 \
    const int _cb = (ch) * 32;                                              \
    cpasync16(_sd,         Ap + _cb);                                       \
    cpasync16(_sd + PLANE, Bp + _cb);                                       \
    CP_COMMIT();                                                            \
} while (0)

    ISSUE1(0);
    ISSUE1(1);
    if (nch > 2) ISSUE1(2);

    const uint32_t lmoff = (uint32_t)((lane & 15) * 80 + (lane >> 4) * 16);

    for (int ch = 0; ch < nch; ch++) {
        const int rem = nch - 1 - ch;
        if (rem >= 2)      { CP_WAIT(2); }
        else if (rem == 1) { CP_WAIT(1); }
        else               { CP_WAIT(0); }
        __syncthreads();
        if (ch + 3 < nch) ISSUE1(ch + 3);

        const uint32_t sAh = sbu + (uint32_t)(ch & 3) * T1STAGE;
        const uint32_t sBh = sAh + PLANE;
#pragma unroll
        for (int kk = 0; kk < 2; kk++) {
            uint32_t ah[2][4], bh[2][4];
#pragma unroll
            for (int mt = 0; mt < 2; mt++)
                ldsm4(ah[mt], sAh + (uint32_t)((wm * 32 + mt * 16) * 80 + kk * 32) + lmoff);
#pragma unroll
            for (int ng = 0; ng < 2; ng++)
                ldsm4(bh[ng], sBh + (uint32_t)((wn * 32 + ng * 16) * 80 + kk * 32) + lmoff);
#pragma unroll
            for (int ng = 0; ng < 2; ng++)
#pragma unroll
                for (int mt = 0; mt < 2; mt++)
#pragma unroll
                    for (int h2 = 0; h2 < 2; h2++)
                        mma_f16(acc[mt][ng * 2 + h2], ah[mt], bh[ng][h2], bh[ng][h2 + 2]);
        }
    }
#undef ISSUE1

    const int crow = m0 + wm * 32 + (lane >> 2);
    const int ccol = n0 + wn * 32 + (lane & 3) * 2;

    if (epi == 2) {
#pragma unroll
        for (int mt = 0; mt < 2; mt++) {
#pragma unroll
            for (int n8 = 0; n8 < 4; n8++) {
                const float* c = acc[mt][n8];
                const int col = ccol + n8 * 8;
                float b0 = bias[col], b1 = bias[col + 1];
#pragma unroll
                for (int h = 0; h < 2; h++) {
                    const int row = crow + mt * 16 + h * 8;
                    float x0 = c[h * 2 + 0] + b0;
                    float x1 = c[h * 2 + 1] + b1;
                    if (col < 1024) {
                        const int s = row & (SS - 1);
                        const int i = (col & 511) >> 1;
                        float sn = g_sin[s * 256 + i];
                        float cs = g_cos[s * 256 + i];
                        float y0 = x0 * cs - x1 * sn;
                        float y1 = x0 * sn + x1 * cs;
                        __half* dst = (col < 512) ? Ch0 : Ch2;
                        size_t off = (size_t)row * 512 + (col & 511);
                        *(__half2*)&dst[off] = __floats2half2_rn(y0, y1);
                    } else {
                        *(float2*)&Cf[(size_t)row * 512 + (col - 1024)] =
                            make_float2(x0, x1);
                    }
                }
            }
        }
        return;
    }

    float* Cfz = Cf ? Cf + (size_t)z * sC : (float*)0;
    __half* Chz = Ch0 ? Ch0 + (size_t)z * sCp : (__half*)0;
    __half* Clz = (Chz && loC) ? Chz + loC : (__half*)0;
#pragma unroll
    for (int mt = 0; mt < 2; mt++) {
#pragma unroll
        for (int n8 = 0; n8 < 4; n8++) {
            const float* c = acc[mt][n8];
            const int col = ccol + n8 * 8;
            float b0 = bias ? bias[col]     : 0.0f;
            float b1 = bias ? bias[col + 1] : 0.0f;
#pragma unroll
            for (int h = 0; h < 2; h++) {
                const int row = crow + mt * 16 + h * 8;
                float x0 = c[h * 2 + 0] * alpha + b0;
                float x1 = c[h * 2 + 1] * alpha + b1;
                if (Cfz)
                    *(float2*)&Cfz[(size_t)row * N + col] = make_float2(x0, x1);
                if (Chz) {
                    __half2 hh, ll;
                    split_pair(x0, x1, hh, ll);
                    *(__half2*)&Chz[(size_t)row * N + col] = hh;
                    if (Clz) *(__half2*)&Clz[(size_t)row * N + col] = ll;
                }
            }
        }
    }
}

static void tg1(const __half* Ah, long long sA, const __half* Bh, long long sB,
                const float* bias, float* Cf, long long sC,
                __half* Ch, __half* Ch2, long long loC, long long sCp,
                int M, int N, int K, int batch, float alpha, int epi,
                cudaStream_t st)
{
    dim3 grid(N / 128, M / 128, batch);
    tgemm1<<<grid, 512, T1_SMEM, st>>>(Ah, Bh, bias, Cf, Ch, Ch2, M, N, K, loC,
                                       sA, sB, sC, sCp, alpha, epi);
}

// 1-term, N-tile 64
#define B1STAGE 15360
#define T1N_SMEM (4 * 15360)

__global__ void __launch_bounds__(256)
tgemm1n64(const __half* __restrict__ Ah0, const __half* __restrict__ Bh0,
          float* __restrict__ Cf, int M, int N, int K, float alpha)
{
    extern __shared__ char smem[];
    const uint32_t sbu = smem_u32(smem);
    const int t = threadIdx.x, w = t >> 5, lane = t & 31;
    const int wm = w & 3, wn = w >> 2;
    const int m0 = blockIdx.y * 128, n0 = blockIdx.x * 64;

    const int arow = t >> 1, aseg = (t & 1) * 2;
    const int brow = t >> 2, bseg = t & 3;
    const __half* pa = Ah0 + (size_t)(m0 + arow) * K + aseg * 8;
    const __half* pb = Bh0 + (size_t)(n0 + brow) * K + bseg * 8;
    const uint32_t adst = sbu + (uint32_t)(arow * 80 + aseg * 16);
    const uint32_t bdst = sbu + 10240u + (uint32_t)(brow * 80 + bseg * 16);

    float acc[2][4][4];
#pragma unroll
    for (int i = 0; i < 2; i++)
#pragma unroll
        for (int j = 0; j < 4; j++)
#pragma unroll
            for (int e = 0; e < 4; e++) acc[i][j][e] = 0.0f;

    const int nch = K >> 5;

#define ISSUEN(ch) do {                                                     \
    uint32_t _st = (uint32_t)((ch) & 3) * B1STAGE;                          \
    const int _cb = (ch) * 32;                                              \
    cpasync16(adst + _st,      pa + _cb);                                   \
    cpasync16(adst + _st + 16, pa + _cb + 8);                               \
    cpasync16(bdst + _st,      pb + _cb);                                   \
    CP_COMMIT();                                                            \
} while (0)

    ISSUEN(0);
    ISSUEN(1);
    if (nch > 2) ISSUEN(2);

    const uint32_t lmoff = (uint32_t)((lane & 15) * 80 + (lane >> 4) * 16);

    for (int ch = 0; ch < nch; ch++) {
        const int rem = nch - 1 - ch;
        if (rem >= 2)      { CP_WAIT(2); }
        else if (rem == 1) { CP_WAIT(1); }
        else               { CP_WAIT(0); }
        __syncthreads();
        if (ch + 3 < nch) ISSUEN(ch + 3);

        const uint32_t sAh = sbu + (uint32_t)(ch & 3) * B1STAGE;
        const uint32_t sBh = sAh + 10240u;
#pragma unroll
        for (int kk = 0; kk < 2; kk++) {
            uint32_t ah[2][4], bh[2][4];
#pragma unroll
            for (int mt = 0; mt < 2; mt++)
                ldsm4(ah[mt], sAh + (uint32_t)((wm * 32 + mt * 16) * 80 + kk * 32) + lmoff);
#pragma unroll
            for (int ng = 0; ng < 2; ng++)
                ldsm4(bh[ng], sBh + (uint32_t)((wn * 32 + ng * 16) * 80 + kk * 32) + lmoff);
#pragma unroll
            for (int ng = 0; ng < 2; ng++)
#pragma unroll
                for (int mt = 0; mt < 2; mt++)
#pragma unroll
                    for (int h2 = 0; h2 < 2; h2++)
                        mma_f16(acc[mt][ng * 2 + h2], ah[mt], bh[ng][h2], bh[ng][h2 + 2]);
        }
    }
#undef ISSUEN

    const int crow = m0 + wm * 32 + (lane >> 2);
    const int ccol = n0 + wn * 32 + (lane & 3) * 2;
#pragma unroll
    for (int mt = 0; mt < 2; mt++)
#pragma unroll
        for (int n8 = 0; n8 < 4; n8++) {
            const float* c = acc[mt][n8];
            const int col = ccol + n8 * 8;
#pragma unroll
            for (int h = 0; h < 2; h++) {
                const int row = crow + mt * 16 + h * 8;
                *(float2*)&Cf[(size_t)row * N + col] =
                    make_float2(c[h * 2] * alpha, c[h * 2 + 1] * alpha);
            }
        }
}

// ---------------------------------------------------------------------------
__global__ void trans_conv(const float* __restrict__ in, __half* __restrict__ oh,
                           long long loOff, int R, int C,
                           long long sI, long long sO, const int* __restrict__ ids)
{
    __shared__ float tile[32][33];
    const int z = blockIdx.z;
    size_t ib = ids ? (size_t)ids[z] * sI : (size_t)z * sI;
    const float* ip = in + ib;
    __half* ohz = oh + (size_t)z * sO;
    __half* olz = loOff ? ohz + loOff : (__half*)0;
    const int c0 = blockIdx.x * 32, r0 = blockIdx.y * 32;
    const int tx = threadIdx.x, ty = threadIdx.y;
#pragma unroll
    for (int k = 0; k < 32; k += 8)
        tile[ty + k][tx] = ip[(size_t)(r0 + ty + k) * C + c0 + tx];
    __syncthreads();
    const int rr = (tx & 15) * 2, chf = tx >> 4;
#pragma unroll
    for (int k = 0; k < 2; k++) {
        int cc = ty + chf * 8 + k * 16;
        __half2 h, l;
        split_pair(tile[rr][cc], tile[rr + 1][cc], h, l);
        *(__half2*)&ohz[(size_t)(c0 + cc) * R + r0 + rr] = h;
        if (olz) *(__half2*)&olz[(size_t)(c0 + cc) * R + r0 + rr] = l;
    }
}

__global__ void conv_planes(const float* __restrict__ in, __half* __restrict__ oh,
                            long long lo)
{
    size_t idx = (size_t)blockIdx.x * 512 + (size_t)threadIdx.x * 2;
    float2 v = *(const float2*)&in[idx];
    __half2 h, l;
    split_pair(v.x, v.y, h, l);
    *(__half2*)&oh[idx] = h;
    if (lo) *(__half2*)&(oh + lo)[idx] = l;
}

__global__ void rope_table_kernel()
{
    int s = blockIdx.x;
    int i = threadIdx.x;
    float invf = 1.0f / powf(10000.0f, (float)i / 256.0f);
    float angf = (float)s * invf;
    double ang = (double)angf;
    g_sin[s * 256 + i] = (float)sin(ang);
    g_cos[s * 256 + i] = (float)cos(ang);
}

__global__ void bias_prep(const float* __restrict__ pos, float* __restrict__ out, int mode)
{
    int n = blockIdx.x, t = threadIdx.x;
    for (int c = t; c < 1024; c += 256) {
        float p = pos[n * 1024 + c];
        out[n * 1024 + c] = (mode == 1) ? logf(p) : (logf(p) - log1pf(-p));
    }
}

__global__ void softmax1024_planes(const __half* __restrict__ S, const float* __restrict__ bias,
                                   __half* __restrict__ oh)
{
    const int row = blockIdx.x, t = threadIdx.x;
    const __half* sr = S + (size_t)row * 1024;
    const float* pb = bias + (size_t)(row >> 10) * 1024;
    __half2 a  = *(const __half2*)&sr[2 * t];
    __half2 b2 = *(const __half2*)&sr[512 + 2 * t];
    float2 ba = *(const float2*)&pb[2 * t];
    float2 bb = *(const float2*)&pb[512 + 2 * t];
    float v0 = __low2float(a) + ba.x,  v1 = __high2float(a) + ba.y;
    float v2 = __low2float(b2) + bb.x, v3 = __high2float(b2) + bb.y;

    __shared__ float red[256];
    float mx = fmaxf(fmaxf(v0, v1), fmaxf(v2, v3));
    red[t] = mx; __syncthreads();
    for (int s = 128; s > 0; s >>= 1) { if (t < s) red[t] = fmaxf(red[t], red[t + s]); __syncthreads(); }
    mx = red[0]; __syncthreads();

    float e0 = expf(v0 - mx), e1 = expf(v1 - mx), e2 = expf(v2 - mx), e3 = expf(v3 - mx);
    red[t] = e0 + e1 + e2 + e3; __syncthreads();
    for (int s = 128; s > 0; s >>= 1) { if (t < s) red[t] += red[t + s]; __syncthreads(); }
    float inv = 1.0f / red[0];

    size_t o = (size_t)row * 1024 + 2 * t;
    *(__half2*)&oh[o]       = __floats2half2_rn(e0 * inv, e1 * inv);
    *(__half2*)&oh[o + 512] = __floats2half2_rn(e2 * inv, e3 * inv);
}

__global__ void softmax64_planes(const float* __restrict__ S, __half* __restrict__ oh)
{
    const int row = blockIdx.x * 8 + (threadIdx.x >> 5);
    const int lane = threadIdx.x & 31;
    const float* sr = S + (size_t)row * 64;
    float2 v = *(const float2*)&sr[lane * 2];
    float mx = fmaxf(v.x, v.y);
#pragma unroll
    for (int o = 16; o > 0; o >>= 1)
        mx = fmaxf(mx, __shfl_xor_sync(0xFFFFFFFF, mx, o));
    float e0 = expf(v.x - mx), e1 = expf(v.y - mx);
    float s = e0 + e1;
#pragma unroll
    for (int o = 16; o > 0; o >>= 1)
        s += __shfl_xor_sync(0xFFFFFFFF, s, o);
    float inv = 1.0f / s;
    *(__half2*)&oh[(size_t)row * 64 + lane * 2] = __floats2half2_rn(e0 * inv, e1 * inv);
}

__global__ void softmax_f32(float* __restrict__ S, const float* __restrict__ bias,
                            int cols, int rpb)
{
    int row = blockIdx.x;
    float* sr = S + (size_t)row * cols;
    const float* pb = bias + (size_t)(row / rpb) * cols;
    int t = threadIdx.x;
    __shared__ float red[256];

    float mx = -1e30f;
    for (int c = t; c < cols; c += 256) {
        float v = sr[c] + pb[c];
        sr[c] = v;
        mx = fmaxf(mx, v);
    }
    red[t] = mx; __syncthreads();
    for (int s = 128; s > 0; s >>= 1) { if (t < s) red[t] = fmaxf(red[t], red[t + s]); __syncthreads(); }
    mx = red[0]; __syncthreads();

    float sum = 0.0f;
    for (int c = t; c < cols; c += 256) {
        float e = expf(sr[c] - mx);
        sr[c] = e;
        sum += e;
    }
    red[t] = sum; __syncthreads();
    for (int s = 128; s > 0; s >>= 1) { if (t < s) red[t] += red[t + s]; __syncthreads(); }
    float inv = 1.0f / red[0];
    for (int c = t; c < cols; c += 256) sr[c] *= inv;
}

__global__ void ln_kernel(const float* __restrict__ Xin, const float* __restrict__ R,
                          const float* __restrict__ g, const float* __restrict__ b,
                          float* __restrict__ Xout,
                          __half* __restrict__ oh, long long lo)
{
    int row = blockIdx.x;
    int t   = threadIdx.x;
    const float* xr = Xin + (size_t)row * DD;
    const float* rr = R + (size_t)row * DD;

    float v0 = xr[2 * t] + rr[2 * t];
    float v1 = xr[2 * t + 1] + rr[2 * t + 1];

    __shared__ float red[256];
    red[t] = v0 + v1; __syncthreads();
    for (int s = 128; s > 0; s >>= 1) { if (t < s) red[t] += red[t + s]; __syncthreads(); }
    float m = red[0] * (1.0f / 512.0f);
    __syncthreads();

    float d0 = v0 - m, d1 = v1 - m;
    red[t] = d0 * d0 + d1 * d1; __syncthreads();
    for (int s = 128; s > 0; s >>= 1) { if (t < s) red[t] += red[t + s]; __syncthreads(); }
    float var = red[0] * (1.0f / 512.0f);
    float inv = rsqrtf(var + 1e-5f);

    float o0 = d0 * inv * g[2 * t]     + b[2 * t];
    float o1 = d1 * inv * g[2 * t + 1] + b[2 * t + 1];
    float* xo = Xout + (size_t)row * DD;
    xo[2 * t]     = o0;
    xo[2 * t + 1] = o1;

    __half2 h, l;
    split_pair(o0, o1, h, l);
    size_t o = (size_t)row * DD + 2 * t;
    *(__half2*)&oh[o] = h;
    *(__half2*)&(oh + lo)[o] = l;
}

__global__ void vgate_kernel(const float* __restrict__ F, const float* __restrict__ raw,
                             const float* __restrict__ Wig, const float* __restrict__ big,
                             float* __restrict__ V)
{
    int row = blockIdx.x;
    int t   = threadIdx.x;
    const float* fr = F + (size_t)row * DD;
    __shared__ float red[256];
    float s = fr[t] * Wig[t] + fr[t + 256] * Wig[t + 256];
    red[t] = s; __syncthreads();
    for (int k = 128; k > 0; k >>= 1) { if (t < k) red[t] += red[t + k]; __syncthreads(); }
    float gte = 1.0f / (1.0f + expf(-(red[0] + big[0])));
    const float* rr = raw + (size_t)row * DD;
    float* vr = V + (size_t)row * DD;
    vr[t]       = rr[t]       * gte;
    vr[t + 256] = rr[t + 256] * gte;
}

__global__ void out_kernel(const float* __restrict__ FU, const float* __restrict__ A2,
                           const float* __restrict__ PD,
                           const float* __restrict__ Wu1, const float* __restrict__ bu1,
                           const float* __restrict__ Wu2, const float* __restrict__ bu2,
                           const float* __restrict__ b1,
                           float* __restrict__ out, float* __restrict__ gate)
{
    int row = blockIdx.x;
    int t   = threadIdx.x;
    const float* fu = FU + (size_t)row * DD;
    const float* a2 = A2 + (size_t)row * DD;
    const float* pd = PD + (size_t)row * DD;

    __shared__ float red[256];
    float s = fu[t] * Wu1[t] + fu[t + 256] * Wu1[t + 256]
            + a2[t] * Wu2[t] + a2[t + 256] * Wu2[t + 256];
    red[t] = s; __syncthreads();
    for (int k = 128; k > 0; k >>= 1) { if (t < k) red[t] += red[t + k]; __syncthreads(); }
    float z = red[0] + bu1[0] + bu2[0] + b1[0] - 4.0f;
    float g = 1.0f / (1.0f + expf(-z));

    float* orow = out + (size_t)row * DD;
    orow[t]       = pd[t]       * (1.0f - g) + a2[t]       * g;
    orow[t + 256] = pd[t + 256] * (1.0f - g) + a2[t + 256] * g;
    if (t == 0) gate[row] = g;
}

#define BM 64
#define BN 64
#define BK 16

__global__ void gemm_kernel(const float* __restrict__ A,
                            const float* __restrict__ Bm,
                            const float* __restrict__ bias,
                            float* __restrict__ C,
                            int M, int N, int K,
                            long long sA, long long sB, long long sC,
                            float alpha, int transB, int epi)
{
    const int bz = blockIdx.z;
    A  += (size_t)bz * sA;
    Bm += (size_t)bz * sB;
    C  += (size_t)bz * sC;

    const int m0 = blockIdx.y * BM;
    const int n0 = blockIdx.x * BN;

    __shared__ float As[BK][BM + 4];
    __shared__ float Bs[BK][BN + 4];

    const int t  = threadIdx.x;
    const int tx = t & 15;
    const int ty = t >> 4;

    float acc[4][4] = {};

    const int arow = t >> 2;
    const int akc  = (t & 3) * 4;
    const int kb   = t >> 4;
    const int nb   = (t & 15) * 4;

    for (int k0 = 0; k0 < K; k0 += BK) {
        float4 av = *(const float4*)&A[(size_t)(m0 + arow) * K + k0 + akc];
        As[akc + 0][arow] = av.x;
        As[akc + 1][arow] = av.y;
        As[akc + 2][arow] = av.z;
        As[akc + 3][arow] = av.w;

        if (!transB) {
            float4 bv = *(const float4*)&Bm[(size_t)(k0 + kb) * N + n0 + nb];
            *(float4*)&Bs[kb][nb] = bv;
        } else {
            float4 bv = *(const float4*)&Bm[(size_t)(n0 + arow) * K + k0 + akc];
            Bs[akc + 0][arow] = bv.x;
            Bs[akc + 1][arow] = bv.y;
            Bs[akc + 2][arow] = bv.z;
            Bs[akc + 3][arow] = bv.w;
        }
        __syncthreads();

#pragma unroll
        for (int k = 0; k < BK; k++) {
            float4 a = *(const float4*)&As[k][ty * 4];
            float4 b = *(const float4*)&Bs[k][tx * 4];
            acc[0][0] += a.x * b.x; acc[0][1] += a.x * b.y;
            acc[0][2] += a.x * b.z; acc[0][3] += a.x * b.w;
            acc[1][0] += a.y * b.x; acc[1][1] += a.y * b.y;
            acc[1][2] += a.y * b.z; acc[1][3] += a.y * b.w;
            acc[2][0] += a.z * b.x; acc[2][1] += a.z * b.y;
            acc[2][2] += a.z * b.z; acc[2][3] += a.z * b.w;
            acc[3][0] += a.w * b.x; acc[3][1] += a.w * b.y;
            acc[3][2] += a.w * b.z; acc[3][3] += a.w * b.w;
        }
        __syncthreads();
    }

#pragma unroll
    for (int i = 0; i < 4; i++) {
        const int row = m0 + ty * 4 + i;
        float v[4];
#pragma unroll
        for (int j = 0; j < 4; j++) {
            float x = acc[i][j] * alpha;
            if (bias) x += bias[n0 + tx * 4 + j];
            v[j] = x;
        }
        *(float4*)&C[(size_t)row * N + n0 + tx * 4] = make_float4(v[0], v[1], v[2], v[3]);
    }
}

static void sgemm_launch(const float* A, const float* B, const float* bias, float* C,
                         int M, int N, int K, int batch,
                         long long sA, long long sB, long long sC,
                         float alpha, int transB, cudaStream_t st)
{
    dim3 grid(N / BN, M / BM, batch);
    gemm_kernel<<<grid, 256, 0, st>>>(A, B, bias, C, M, N, K, sA, sB, sC, alpha, transB, 0);
}

// ---------------------------------------------------------------------------
// Encoder (stream + private buffers). QKV is 1-term (hi planes only on A).
// ---------------------------------------------------------------------------
static void run_encoder(const float* Xin0, float* X, int nb,
                        const __half* initHi,
                        const float* biasRows, const __half* PW,
                        const float* bqkv, const float* bo,
                        const float* ln, const float* bff,
                        float* bV, float* bK, __half* Sh,
                        __half* Pq, __half* Pk, __half* Pvt,
                        __half* Pp, __half* Pbq, __half* Ph,
                        __half* Px, long long lo, cudaStream_t st)
{
    const int rows = nb * SS;
    const float sc = 1.0f / sqrtf((float)DD);
    for (int l = 0; l < 2; l++) {
        const __half* AP = (l == 0) ? initHi : Px;
        // QKV (1-term, rope epilogue)
        tg1(AP, 0, PW + (size_t)(l * 3) * 262144, 0,
            bqkv + (size_t)l * 1536, bV, 0, Pq, Pk, 0, 0,
            rows, 1536, 512, 1, 1.0f, 2, st);
        trans_conv<<<dim3(16, 32, nb), dim3(32, 8), 0, st>>>(bV, Pvt, 0, 1024, 512,
                                                             524288, 524288, nullptr);
        // scores = Q @ K^T * sc -> fp16 raw
        tg1(Pq, 524288, Pk, 524288, nullptr, nullptr, 0, Sh, nullptr, 0, 1048576,
            1024, 1024, 512, nb, sc, 0, st);
        softmax1024_planes<<<rows, 256, 0, st>>>(Sh, biasRows, Pp);
        // T = A @ V (1-term) -> hi+lo planes
        tg1(Pp, 1048576, Pvt, 524288, nullptr, nullptr, 0, Pbq, nullptr, lo, 524288,
            1024, 512, 1024, nb, 1.0f, 0, st);
        // O = T @ Wo + bo (3-term)
        tg3(Pbq, lo, 0, PW + (size_t)(6 + l) * 262144, WLO, 0, bo + l * 512,
            bK, 0, nullptr, 0, 0, rows, 512, 512, 1, 1.0f, 0, st);
        ln_kernel<<<rows, 256, 0, st>>>((l == 0) ? Xin0 : X, bK,
                                        ln + l * 2048, ln + l * 2048 + 512, X, Px, lo);
        tg3(Px, lo, 0, PW + (size_t)(8 + 2 * l) * 262144, WLO, 0, bff + l * 1024,
            nullptr, 0, Ph, lo, 0, rows, 512, 512, 1, 1.0f, 1, st);
        tg3(Ph, lo, 0, PW + (size_t)(9 + 2 * l) * 262144, WLO, 0, bff + l * 1024 + 512,
            bK, 0, nullptr, 0, 0, rows, 512, 512, 1, 1.0f, 0, st);
        ln_kernel<<<rows, 256, 0, st>>>(X, bK, ln + l * 2048 + 1024, ln + l * 2048 + 1536,
                                        X, Px, lo);
    }
}

extern "C" void kernel_launch(void* const* d_in, const int* in_sizes, int n_in,
                              void* d_out, int out_size)
{
    const float* raw_emb   = (const float*)d_in[0];
    const float* pos_w     = (const float*)d_in[1];
    const float* post_dec  = (const float*)d_in[2];
    const float* pos_r     = (const float*)d_in[3];
    const float* questions = (const float*)d_in[4];
    const float* W_k       = (const float*)d_in[5];
    const float* W_ig      = (const float*)d_in[6];
    const float* b_ig      = (const float*)d_in[7];
    const float* W_u1      = (const float*)d_in[8];
    const float* b_u1      = (const float*)d_in[9];
    const float* W_u2      = (const float*)d_in[10];
    const float* b_u2      = (const float*)d_in[11];
    const float* b1        = (const float*)d_in[12];
    const float* W_ok      = (const float*)d_in[13];
    const float* b_ok      = (const float*)d_in[14];
    const float* encw_Wqkv = (const float*)d_in[15];
    const float* encw_bqkv = (const float*)d_in[16];
    const float* encw_Wo   = (const float*)d_in[17];
    const float* encw_bo   = (const float*)d_in[18];
    const float* encw_ln   = (const float*)d_in[19];
    const float* encw_Wff  = (const float*)d_in[20];
    const float* encw_bff  = (const float*)d_in[21];
    const float* encr_Wqkv = (const float*)d_in[22];
    const float* encr_bqkv = (const float*)d_in[23];
    const float* encr_Wo   = (const float*)d_in[24];
    const float* encr_bo   = (const float*)d_in[25];
    const float* encr_ln   = (const float*)d_in[26];
    const float* encr_Wff  = (const float*)d_in[27];
    const float* encr_bff  = (const float*)d_in[28];
    const int*   lookup    = (const int*)d_in[29];

    float* out  = (float*)d_out;
    float* gate = out + (size_t)NBB * SS * DD;

    float *pX, *pV, *pK, *pXw, *pVw, *pKw, *pS1, *pKd, *pVd, *pA1, *pA2s, *pA2, *pBW, *pBR;
    __half *pPW, *pPraw, *pPpd, *pPx, *pPq, *pPk, *pPvt, *pPp, *pPbq, *pPh, *pSh;
    __half *pPxw, *pPqw, *pPkw, *pPvtw, *pPpw, *pPbqw, *pPhw, *pShw;
    __half *pPk2, *pPa2, *pPsel, *pPqst;
    cudaGetSymbolAddress((void**)&pX,    g_X);
    cudaGetSymbolAddress((void**)&pV,    g_V);
    cudaGetSymbolAddress((void**)&pK,    g_Kb);
    cudaGetSymbolAddress((void**)&pXw,   g_Xw);
    cudaGetSymbolAddress((void**)&pVw,   g_Vw);
    cudaGetSymbolAddress((void**)&pKw,   g_Kw);
    cudaGetSymbolAddress((void**)&pS1,   g_S1);
    cudaGetSymbolAddress((void**)&pKd,   g_Kdoc);
    cudaGetSymbolAddress((void**)&pVd,   g_Vdoc);
    cudaGetSymbolAddress((void**)&pA1,   g_A1S);
    cudaGetSymbolAddress((void**)&pA2s,  g_A2SC);
    cudaGetSymbolAddress((void**)&pA2,   g_A2);
    cudaGetSymbolAddress((void**)&pBW,   g_BIASW);
    cudaGetSymbolAddress((void**)&pBR,   g_BIASR);
    cudaGetSymbolAddress((void**)&pPW,   g_PW);
    cudaGetSymbolAddress((void**)&pPraw, g_Praw);
    cudaGetSymbolAddress((void**)&pPpd,  g_Ppd);
    cudaGetSymbolAddress((void**)&pPx,   g_Px);
    cudaGetSymbolAddress((void**)&pPq,   g_Pq);
    cudaGetSymbolAddress((void**)&pPk,   g_Pk);
    cudaGetSymbolAddress((void**)&pPvt,  g_Pvt);
    cudaGetSymbolAddress((void**)&pPp,   g_Pp);
    cudaGetSymbolAddress((void**)&pPbq,  g_Pbq);
    cudaGetSymbolAddress((void**)&pPh,   g_Ph);
    cudaGetSymbolAddress((void**)&pSh,   g_Sh);
    cudaGetSymbolAddress((void**)&pPxw,  g_Pxw);
    cudaGetSymbolAddress((void**)&pPqw,  g_Pqw);
    cudaGetSymbolAddress((void**)&pPkw,  g_Pkw);
    cudaGetSymbolAddress((void**)&pPvtw, g_Pvtw);
    cudaGetSymbolAddress((void**)&pPpw,  g_Ppw);
    cudaGetSymbolAddress((void**)&pPbqw, g_Pbqw);
    cudaGetSymbolAddress((void**)&pPhw,  g_Phw);
    cudaGetSymbolAddress((void**)&pShw,  g_Shw);
    cudaGetSymbolAddress((void**)&pPk2,  g_Pk2);
    cudaGetSymbolAddress((void**)&pPa2,  g_Pa2);
    cudaGetSymbolAddress((void**)&pPsel, g_Psel);
    cudaGetSymbolAddress((void**)&pPqst, g_Pqst);

    cudaFuncSetAttribute(tgemm3,    cudaFuncAttributeMaxDynamicSharedMemorySize, TG_SMEM);
    cudaFuncSetAttribute(tgemm1,    cudaFuncAttributeMaxDynamicSharedMemorySize, T1_SMEM);
    cudaFuncSetAttribute(tgemm1n64, cudaFuncAttributeMaxDynamicSharedMemorySize, T1N_SMEM);

    const float scD = 1.0f / sqrtf((float)DD);

    cudaStream_t s2;
    cudaStreamCreateWithFlags(&s2, cudaStreamNonBlocking);
    cudaEvent_t evF, evJ;
    cudaEventCreateWithFlags(&evF, cudaEventDisableTiming);
    cudaEventCreateWithFlags(&evJ, cudaEventDisableTiming);
    cudaStream_t s0 = 0;

    // ---- common prep on s0 ----
    rope_table_kernel<<<1024, 256, 0, s0>>>();
    conv_planes<<<NBB * SS, 256, 0, s0>>>(post_dec, pPpd, 0);

    cudaEventRecord(evF, s0);
    cudaStreamWaitEvent(s2, evF, 0);

    // ================= s2: write side + independent k2/a2 path =============
    trans_conv<<<dim3(16, 16, 6), dim3(32, 8), 0, s2>>>(encw_Wqkv, pPW + 0LL * 262144, WLO, 512, 512, 262144, 262144, nullptr);
    trans_conv<<<dim3(16, 16, 2), dim3(32, 8), 0, s2>>>(encw_Wo,   pPW + 6LL * 262144, WLO, 512, 512, 262144, 262144, nullptr);
    trans_conv<<<dim3(16, 16, 4), dim3(32, 8), 0, s2>>>(encw_Wff,  pPW + 8LL * 262144, WLO, 512, 512, 262144, 262144, nullptr);
    conv_planes<<<NDOC * SS, 256, 0, s2>>>(raw_emb, pPraw, 0);
    bias_prep<<<NDOC, 256, 0, s2>>>(pos_w, pBW, 1);

    run_encoder(raw_emb, pXw, NDOC, pPraw, pBW,
                pPW, encw_bqkv, encw_bo, encw_ln, encw_bff,
                pVw, pKw, pShw, pPqw, pPkw, pPvtw, pPpw, pPbqw, pPhw, pPxw,
                LOW, s2);

    vgate_kernel<<<NDOC * SS, 256, 0, s2>>>(pXw, raw_emb, W_ig, b_ig, pVd);
    trans_conv<<<dim3(16, 16, 1), dim3(32, 8), 0, s2>>>(W_k, pPW + 24LL * 262144, WLO, 512, 512, 262144, 262144, nullptr);
    // k = raw_emb @ W_k (1-term, f32 out)
    tg1(pPraw, 0, pPW + 24LL * 262144, 0, nullptr, pKd, 0, nullptr, nullptr, 0, 0,
        NDOC * SS, 512, 512, 1, 1.0f, 0, s2);
    sgemm_launch(questions, pKd, nullptr, pS1, QQ, SS, DD, NDOC, 0, 524288, 65536, scD, 1, s2);
    softmax_f32<<<NDOC * QQ, 256, 0, s2>>>(pS1, pBW, SS, QQ);
    sgemm_launch(pS1, pVd, nullptr, pA1, QQ, DD, SS, NDOC, 65536, 524288, 32768, 1.0f, 0, s2);
    trans_conv<<<dim3(16, 2, 16), dim3(32, 8), 0, s2>>>(pA1, pPsel, 0, 64, 512, 32768, 32768, lookup);

    // independent k2/a2/A2 chain
    trans_conv<<<dim3(16, 16, 1), dim3(32, 8), 0, s2>>>(W_ok, pPW + 25LL * 262144, WLO, 512, 512, 262144, 262144, nullptr);
    conv_planes<<<QQ, 256, 0, s2>>>(questions, pPqst, 0);
    tg1(pPpd, 0, pPW + 25LL * 262144, 0, b_ok, nullptr, 0, pPk2, nullptr, 0, 0,
        NBB * SS, 512, 512, 1, 1.0f, 0, s2);
    {
        dim3 grid(1, (NBB * SS) / 128, 1);
        tgemm1n64<<<grid, 256, T1N_SMEM, s2>>>(pPk2, pPqst, pA2s, NBB * SS, QQ, DD, 0.125f);
    }
    softmax64_planes<<<NBB * SS / 8, 256, 0, s2>>>(pA2s, pPa2);
    tg1(pPa2, 65536, pPsel, 32768, nullptr, pA2, 524288, nullptr, nullptr, 0, 0,
        1024, 512, 64, NBB, 1.0f, 0, s2);

    cudaEventRecord(evJ, s2);

    // ================= s0: read-side encoder (long pole) ====================
    trans_conv<<<dim3(16, 16, 6), dim3(32, 8), 0, s0>>>(encr_Wqkv, pPW + 12LL * 262144, WLO, 512, 512, 262144, 262144, nullptr);
    trans_conv<<<dim3(16, 16, 2), dim3(32, 8), 0, s0>>>(encr_Wo,   pPW + 18LL * 262144, WLO, 512, 512, 262144, 262144, nullptr);
    trans_conv<<<dim3(16, 16, 4), dim3(32, 8), 0, s0>>>(encr_Wff,  pPW + 20LL * 262144, WLO, 512, 512, 262144, 262144, nullptr);
    bias_prep<<<NBB, 256, 0, s0>>>(pos_r, pBR, 2);

    run_encoder(post_dec, pX, NBB, pPpd, pBR,
                pPW + 12LL * 262144, encr_bqkv, encr_bo, encr_ln, encr_bff,
                pV, pK, pSh, pPq, pPk, pPvt, pPp, pPbq, pPh, pPx,
                LO, s0);

    // join + final
    cudaStreamWaitEvent(s0, evJ, 0);
    out_kernel<<<NBB * SS, 256, 0, s0>>>(pX, pA2, post_dec,
                                         W_u1, b_u1, W_u2, b_u2, b1,
                                         out, gate);

    (void)in_sizes; (void)n_in; (void)out_size;
}